// round 6
// baseline (speedup 1.0000x reference)
#include <cuda_runtime.h>
#include <cstdint>
#include <cstddef>

// Problem dims: B=4, T=2048 -> BT=8192 tokens, D=1024, E=8, I=1024
#define BT_ 8192
#define D_  1024
#define E_  8
#define I_  1024

#define GOLDEN_CENTER 0.36787944117144233f
#define GOLDEN_LOWER  0.21231792754821915f
#define GOLDEN_UPPER  0.5f
#define INV127 (1.0f/127.0f)
#define INV254 (1.0f/254.0f)

// ---------------------------------------------------------------------------
// Device scratch (static; no runtime allocation)
// ---------------------------------------------------------------------------
__device__ char  g_xq1[BT_ * D_], g_xq2[BT_ * D_];           // x 2-level int8 [t][d]
__device__ float g_sx[BT_];                                  // x row scales (amax/127)
__device__ char  g_gq1[E_ * D_ * I_], g_gq2[E_ * D_ * I_];   // Wg^T int8 [e][i][d]
__device__ char  g_uq1[E_ * D_ * I_], g_uq2[E_ * D_ * I_];   // Wu^T int8 [e][i][d]
__device__ char  g_dq1[E_ * D_ * I_], g_dq2[E_ * D_ * I_];   // Wd^T int8 [e][d][i]
__device__ unsigned g_cmG[E_ * I_], g_cmU[E_ * I_], g_cmD[E_ * D_]; // col amax bits
__device__ float g_hf[(size_t)E_ * BT_ * I_];                // h fp32 [e][t][i]
__device__ char  g_hq1[(size_t)E_ * BT_ * I_];               // h 2-level int8
__device__ char  g_hq2[(size_t)E_ * BT_ * I_];
__device__ float g_sh[E_ * BT_];                             // h row scales
__device__ float g_w[BT_ * E_];                              // routing weights

// ---------------------------------------------------------------------------
// helpers
// ---------------------------------------------------------------------------
__device__ __forceinline__ void imma32(int c[4], const uint32_t a[4], const uint32_t b[2]) {
    asm volatile(
        "mma.sync.aligned.m16n8k32.row.col.s32.s8.s8.s32 "
        "{%0,%1,%2,%3},{%4,%5,%6,%7},{%8,%9},{%0,%1,%2,%3};\n"
        : "+r"(c[0]), "+r"(c[1]), "+r"(c[2]), "+r"(c[3])
        : "r"(a[0]), "r"(a[1]), "r"(a[2]), "r"(a[3]), "r"(b[0]), "r"(b[1]));
}
__device__ __forceinline__ void ldsm4(uint32_t r[4], uint32_t addr) {
    asm volatile("ldmatrix.sync.aligned.m8n8.x4.shared.b16 {%0,%1,%2,%3}, [%4];"
        : "=r"(r[0]), "=r"(r[1]), "=r"(r[2]), "=r"(r[3]) : "r"(addr));
}
__device__ __forceinline__ void cp16(uint32_t dst, const void* src) {
    asm volatile("cp.async.cg.shared.global [%0], [%1], 16;\n" :: "r"(dst), "l"(src) : "memory");
}
__device__ __forceinline__ void cpcommit() { asm volatile("cp.async.commit_group;\n" ::: "memory"); }
__device__ __forceinline__ void cpwait0()  { asm volatile("cp.async.wait_group 0;\n" ::: "memory"); }
__device__ __forceinline__ float siluf(float v) { return v / (1.0f + expf(-v)); }

// smem rows: 64 data bytes + 16 pad = 80B (16B-aligned rows; conflict-free ldmatrix)
#define ROWB 80u

// ---------------------------------------------------------------------------
// Routing weights: one warp per token; fp64 accumulation
// ---------------------------------------------------------------------------
__global__ __launch_bounds__(256) void routing_kernel(
    const float* __restrict__ x, const float* __restrict__ Wr,
    const float* __restrict__ temp)
{
    int warp = threadIdx.x >> 5;
    int lane = threadIdx.x & 31;
    int t = blockIdx.x * 8 + warp;

    const float* xr = x + (size_t)t * D_;
    double acc0[E_], acc1[E_];
#pragma unroll
    for (int e = 0; e < E_; e++) { acc0[e] = 0.0; acc1[e] = 0.0; }

#pragma unroll 4
    for (int d0 = lane; d0 < D_; d0 += 64) {
        int d1 = d0 + 32;
        float xv0 = __ldg(xr + d0), xv1 = __ldg(xr + d1);
        float4 wa0 = *(const float4*)(Wr + d0 * E_);
        float4 wb0 = *(const float4*)(Wr + d0 * E_ + 4);
        float4 wa1 = *(const float4*)(Wr + d1 * E_);
        float4 wb1 = *(const float4*)(Wr + d1 * E_ + 4);
        acc0[0] += (double)xv0 * (double)wa0.x;  acc1[0] += (double)xv1 * (double)wa1.x;
        acc0[1] += (double)xv0 * (double)wa0.y;  acc1[1] += (double)xv1 * (double)wa1.y;
        acc0[2] += (double)xv0 * (double)wa0.z;  acc1[2] += (double)xv1 * (double)wa1.z;
        acc0[3] += (double)xv0 * (double)wa0.w;  acc1[3] += (double)xv1 * (double)wa1.w;
        acc0[4] += (double)xv0 * (double)wb0.x;  acc1[4] += (double)xv1 * (double)wb1.x;
        acc0[5] += (double)xv0 * (double)wb0.y;  acc1[5] += (double)xv1 * (double)wb1.y;
        acc0[6] += (double)xv0 * (double)wb0.z;  acc1[6] += (double)xv1 * (double)wb1.z;
        acc0[7] += (double)xv0 * (double)wb0.w;  acc1[7] += (double)xv1 * (double)wb1.w;
    }
    double acc[E_];
#pragma unroll
    for (int e = 0; e < E_; e++) acc[e] = acc0[e] + acc1[e];
#pragma unroll
    for (int off = 16; off > 0; off >>= 1) {
#pragma unroll
        for (int e = 0; e < E_; e++)
            acc[e] += __shfl_down_sync(0xffffffffu, acc[e], off);
    }

    if (lane == 0) {
        float T = temp[0];
        float dist[E_], wv[E_];
        float wsum = 0.0f;
#pragma unroll
        for (int e = 0; e < E_; e++) {
            float z = (float)acc[e] / T;
            float inh = 1.0f / (1.0f + expf(-z));
            dist[e] = fabsf(inh - GOLDEN_CENTER);
            bool zone = (inh >= GOLDEN_LOWER) && (inh <= GOLDEN_UPPER);
            wv[e] = zone ? expf(-dist[e] / 0.1f) : 0.0f;
            wsum += wv[e];
        }
        if (wsum < 1e-8f) {
            float fb[E_];
#pragma unroll
            for (int e = 0; e < E_; e++) fb[e] = expf(-dist[e] / 0.3f);
            int i1 = 0;
#pragma unroll
            for (int e = 1; e < E_; e++) if (fb[e] > fb[i1]) i1 = e;
            int i2 = (i1 == 0) ? 1 : 0;
#pragma unroll
            for (int e = 0; e < E_; e++)
                if (e != i1 && fb[e] > fb[i2]) i2 = e;
            float s = fmaxf(fb[i1] + fb[i2], 1e-8f);
#pragma unroll
            for (int e = 0; e < E_; e++)
                wv[e] = (e == i1 || e == i2) ? fb[e] / s : 0.0f;
        }
        float s2 = 0.0f;
#pragma unroll
        for (int e = 0; e < E_; e++) s2 += wv[e];
        float inv = 1.0f / fmaxf(s2, 1e-8f);
#pragma unroll
        for (int e = 0; e < E_; e++) g_w[t * E_ + e] = wv[e] * inv;
    }
}

// ---------------------------------------------------------------------------
// rowwise 2-level int8 quant: one warp per row of 1024 floats
// ---------------------------------------------------------------------------
__global__ __launch_bounds__(256) void quantrow_kernel(
    const float* __restrict__ in, char* __restrict__ q1, char* __restrict__ q2,
    float* __restrict__ sc)
{
    int row = blockIdx.x * 8 + (threadIdx.x >> 5);
    int lane = threadIdx.x & 31;
    const float4* ip = (const float4*)(in + (size_t)row * 1024);
    float4 v[8];
    float am = 0.0f;
#pragma unroll
    for (int j = 0; j < 8; j++) {
        v[j] = ip[lane + 32 * j];
        am = fmaxf(am, fmaxf(fmaxf(fabsf(v[j].x), fabsf(v[j].y)),
                             fmaxf(fabsf(v[j].z), fabsf(v[j].w))));
    }
#pragma unroll
    for (int o = 16; o; o >>= 1) am = fmaxf(am, __shfl_xor_sync(0xffffffffu, am, o));
    float inv = (am > 0.0f) ? 127.0f / am : 0.0f;
    if (lane == 0) sc[row] = am * INV127;
    char* p1 = q1 + (size_t)row * 1024;
    char* p2 = q2 + (size_t)row * 1024;
#pragma unroll
    for (int j = 0; j < 8; j++) {
        float t0 = v[j].x * inv, t1 = v[j].y * inv, t2 = v[j].z * inv, t3 = v[j].w * inv;
        float r0 = rintf(t0), r1 = rintf(t1), r2 = rintf(t2), r3 = rintf(t3);
        char4 c1 = make_char4((char)(int)r0, (char)(int)r1, (char)(int)r2, (char)(int)r3);
        char4 c2 = make_char4((char)(int)rintf((t0 - r0) * 254.0f),
                              (char)(int)rintf((t1 - r1) * 254.0f),
                              (char)(int)rintf((t2 - r2) * 254.0f),
                              (char)(int)rintf((t3 - r3) * 254.0f));
        *(char4*)(p1 + (lane + 32 * j) * 4) = c1;
        *(char4*)(p2 + (lane + 32 * j) * 4) = c2;
    }
}

// ---------------------------------------------------------------------------
// per-column amax of [e][1024][1024] (atomicMax on float bits; inputs >= 0 safe)
// ---------------------------------------------------------------------------
__global__ void amaxcol_kernel(const float* __restrict__ in, unsigned* __restrict__ cm)
{
    __shared__ float red[8][33];
    int e = blockIdx.z;
    const float* ip = in + ((size_t)e << 20);
    int c0 = blockIdx.x * 32, r0 = blockIdx.y * 32;
    int tx = threadIdx.x, ty = threadIdx.y;
    float m = 0.0f;
#pragma unroll
    for (int j = ty; j < 32; j += 8)
        m = fmaxf(m, fabsf(ip[(size_t)(r0 + j) * 1024 + c0 + tx]));
    red[ty][tx] = m;
    __syncthreads();
    if (ty == 0) {
#pragma unroll
        for (int k = 1; k < 8; k++) m = fmaxf(m, red[k][tx]);
        atomicMax(&cm[e * 1024 + c0 + tx], __float_as_uint(m));
    }
}

// ---------------------------------------------------------------------------
// transpose + 2-level quant: q[e][c][r] = quant(in[e][r][c], cm[e][c])
// ---------------------------------------------------------------------------
__global__ void quantT_kernel(
    const float* __restrict__ in, const unsigned* __restrict__ cm,
    char* __restrict__ q1, char* __restrict__ q2)
{
    __shared__ float t[32][33];
    int e = blockIdx.z;
    const float* ip = in + ((size_t)e << 20);
    int r0 = blockIdx.y * 32, c0 = blockIdx.x * 32;
    int tx = threadIdx.x, ty = threadIdx.y;

#pragma unroll
    for (int j = ty; j < 32; j += 8)
        t[j][tx] = ip[(size_t)(r0 + j) * 1024 + c0 + tx];
    __syncthreads();
#pragma unroll
    for (int j = ty; j < 32; j += 8) {
        float v = t[tx][j];   // in[r0+tx][c0+j]
        float mx = __uint_as_float(cm[e * 1024 + c0 + j]);
        float inv = (mx > 0.0f) ? 127.0f / mx : 0.0f;
        float tt = v * inv;
        float f1 = rintf(tt);
        float f2 = rintf((tt - f1) * 254.0f);
        size_t o = ((size_t)e << 20) + (size_t)(c0 + j) * 1024 + r0 + tx;
        q1[o] = (char)(int)f1;
        q2[o] = (char)(int)f2;
    }
}

// ---------------------------------------------------------------------------
// Pass A (int8 IMMA): h = silu(X@Wg)*(X@Wu), fp32 out to g_hf
// CTA 128m x 64n, 8 warps (4m x 2n), K=1024 in 16 stages of 64 bytes.
// grid (16, 64, 8)
// ---------------------------------------------------------------------------
__global__ __launch_bounds__(256) void passA_kernel()
{
    extern __shared__ char smem[];
    const uint32_t sb = (uint32_t)__cvta_generic_to_shared(smem);

    const int e  = blockIdx.z;
    const int m0 = blockIdx.y * 128;
    const int n0 = blockIdx.x * 64;

    const char* Ax1 = g_xq1 + (size_t)m0 * D_;
    const char* Ax2 = g_xq2 + (size_t)m0 * D_;
    const char* G1  = g_gq1 + ((size_t)e * I_ + n0) * D_;
    const char* G2  = g_gq2 + ((size_t)e * I_ + n0) * D_;
    const char* U1  = g_uq1 + ((size_t)e * I_ + n0) * D_;
    const char* U2  = g_uq2 + ((size_t)e * I_ + n0) * D_;

    const int tid = threadIdx.x, lane = tid & 31, warp = tid >> 5;
    const int wm = warp & 3, wn = warp >> 2;

    const int lr = tid >> 2, lc = tid & 3;
    const uint32_t adst1 = (uint32_t)lr * ROWB + lc * 16;
    const uint32_t adst2 = (uint32_t)(lr + 64) * ROWB + lc * 16;
    const uint32_t bdst  = adst1;
    const size_t asrc1 = (size_t)lr * D_ + lc * 16;
    const size_t asrc2 = (size_t)(lr + 64) * D_ + lc * 16;
    const size_t bsrc  = asrc1;

    const uint32_t aoffL = (uint32_t)((lane & 7) + ((lane >> 3) & 1) * 8) * ROWB + (lane >> 4) * 16;
    const uint32_t boffL = (uint32_t)((lane & 7) + (lane >> 4) * 8) * ROWB + ((lane >> 3) & 1) * 16;

    int cg1[2][4][4], cgx[2][4][4], cu1[2][4][4], cux[2][4][4];
#pragma unroll
    for (int mt = 0; mt < 2; mt++)
#pragma unroll
        for (int nt = 0; nt < 4; nt++)
#pragma unroll
            for (int i = 0; i < 4; i++) {
                cg1[mt][nt][i] = 0; cgx[mt][nt][i] = 0;
                cu1[mt][nt][i] = 0; cux[mt][nt][i] = 0;
            }

#define ISSUE_A(buf, k0) do {                                             \
        uint32_t ao = (uint32_t)(buf) * 10240u, bo = (uint32_t)(buf) * 5120u; \
        cp16(sb + ao + adst1,          Ax1 + asrc1 + (k0));               \
        cp16(sb + ao + adst2,          Ax1 + asrc2 + (k0));               \
        cp16(sb + 20480 + ao + adst1,  Ax2 + asrc1 + (k0));               \
        cp16(sb + 20480 + ao + adst2,  Ax2 + asrc2 + (k0));               \
        cp16(sb + 40960 + bo + bdst,   G1 + bsrc + (k0));                 \
        cp16(sb + 51200 + bo + bdst,   G2 + bsrc + (k0));                 \
        cp16(sb + 61440 + bo + bdst,   U1 + bsrc + (k0));                 \
        cp16(sb + 71680 + bo + bdst,   U2 + bsrc + (k0));                 \
        cpcommit();                                                       \
    } while (0)

    ISSUE_A(0, 0);

#pragma unroll 1
    for (int s = 0; s < 16; s++) {
        cpwait0();
        __syncthreads();
        if (s + 1 < 16) ISSUE_A((s + 1) & 1, (s + 1) * 64);
        const uint32_t ab = (uint32_t)(s & 1) * 10240u;
        const uint32_t bb = (uint32_t)(s & 1) * 5120u;

#pragma unroll
        for (int ks = 0; ks < 2; ks++) {
            const uint32_t kb = (uint32_t)ks * 32u;
            uint32_t a1f[2][4], a2f[2][4];
#pragma unroll
            for (int mt = 0; mt < 2; mt++) {
                uint32_t ro = (uint32_t)(wm * 32 + mt * 16) * ROWB;
                ldsm4(a1f[mt], sb + ab + ro + aoffL + kb);
                ldsm4(a2f[mt], sb + 20480 + ab + ro + aoffL + kb);
            }
            uint32_t g1f[2][4], g2f[2][4], u1f[2][4], u2f[2][4];
#pragma unroll
            for (int p = 0; p < 2; p++) {
                uint32_t ro = (uint32_t)(wn * 32 + p * 16) * ROWB;
                ldsm4(g1f[p], sb + 40960 + bb + ro + boffL + kb);
                ldsm4(g2f[p], sb + 51200 + bb + ro + boffL + kb);
                ldsm4(u1f[p], sb + 61440 + bb + ro + boffL + kb);
                ldsm4(u2f[p], sb + 71680 + bb + ro + boffL + kb);
            }
#pragma unroll
            for (int mt = 0; mt < 2; mt++)
#pragma unroll
                for (int p = 0; p < 2; p++)
#pragma unroll
                    for (int q = 0; q < 2; q++) {
                        const int nt = 2 * p + q;
                        imma32(cg1[mt][nt], a1f[mt], &g1f[p][2 * q]);
                        imma32(cgx[mt][nt], a2f[mt], &g1f[p][2 * q]);
                        imma32(cgx[mt][nt], a1f[mt], &g2f[p][2 * q]);
                        imma32(cu1[mt][nt], a1f[mt], &u1f[p][2 * q]);
                        imma32(cux[mt][nt], a2f[mt], &u1f[p][2 * q]);
                        imma32(cux[mt][nt], a1f[mt], &u2f[p][2 * q]);
                    }
        }
    }
#undef ISSUE_A

    // epilogue: dequant, silu*up, write fp32 h
    const int g = lane >> 2, tg = lane & 3;
    float* H = g_hf + (size_t)e * BT_ * I_;
#pragma unroll
    for (int mt = 0; mt < 2; mt++) {
        int r0 = m0 + wm * 32 + mt * 16 + g;
        float sx0 = g_sx[r0], sx8 = g_sx[r0 + 8];
#pragma unroll
        for (int nt = 0; nt < 4; nt++) {
            int c0 = n0 + wn * 32 + nt * 8 + tg * 2;
            float sg0 = __uint_as_float(g_cmG[e * I_ + c0])     * INV127;
            float sg1 = __uint_as_float(g_cmG[e * I_ + c0 + 1]) * INV127;
            float su0 = __uint_as_float(g_cmU[e * I_ + c0])     * INV127;
            float su1 = __uint_as_float(g_cmU[e * I_ + c0 + 1]) * INV127;
            float gt00 = sx0 * sg0 * ((float)cg1[mt][nt][0] + (float)cgx[mt][nt][0] * INV254);
            float gt01 = sx0 * sg1 * ((float)cg1[mt][nt][1] + (float)cgx[mt][nt][1] * INV254);
            float gt10 = sx8 * sg0 * ((float)cg1[mt][nt][2] + (float)cgx[mt][nt][2] * INV254);
            float gt11 = sx8 * sg1 * ((float)cg1[mt][nt][3] + (float)cgx[mt][nt][3] * INV254);
            float up00 = sx0 * su0 * ((float)cu1[mt][nt][0] + (float)cux[mt][nt][0] * INV254);
            float up01 = sx0 * su1 * ((float)cu1[mt][nt][1] + (float)cux[mt][nt][1] * INV254);
            float up10 = sx8 * su0 * ((float)cu1[mt][nt][2] + (float)cux[mt][nt][2] * INV254);
            float up11 = sx8 * su1 * ((float)cu1[mt][nt][3] + (float)cux[mt][nt][3] * INV254);
            *(float2*)(H + (size_t)r0 * I_ + c0)       = make_float2(siluf(gt00) * up00, siluf(gt01) * up01);
            *(float2*)(H + (size_t)(r0 + 8) * I_ + c0) = make_float2(siluf(gt10) * up10, siluf(gt11) * up11);
        }
    }
}

// ---------------------------------------------------------------------------
// Pass B (int8 IMMA): out = sum_e w[:,e] .* (h[e] @ Wd_e)
// block 128m x 64n; grid (16, 64)
// ---------------------------------------------------------------------------
__global__ __launch_bounds__(256) void passB_kernel(float* __restrict__ out)
{
    extern __shared__ char smem[];
    const uint32_t sb = (uint32_t)__cvta_generic_to_shared(smem);
    __shared__ float ws[128][E_];

    const int m0 = blockIdx.y * 128;
    const int n0 = blockIdx.x * 64;

    const int tid = threadIdx.x, lane = tid & 31, warp = tid >> 5;
    const int wm = warp & 3, wn = warp >> 2;

    for (int idx = tid; idx < 128 * E_; idx += 256)
        ws[idx >> 3][idx & 7] = g_w[(m0 + (idx >> 3)) * E_ + (idx & 7)];

    const int lr = tid >> 2, lc = tid & 3;
    const uint32_t adst1 = (uint32_t)lr * ROWB + lc * 16;
    const uint32_t adst2 = (uint32_t)(lr + 64) * ROWB + lc * 16;
    const uint32_t bdst  = adst1;
    const size_t asrc1 = (size_t)lr * I_ + lc * 16;
    const size_t asrc2 = (size_t)(lr + 64) * I_ + lc * 16;
    const size_t bsrc  = asrc1;

    const uint32_t aoffL = (uint32_t)((lane & 7) + ((lane >> 3) & 1) * 8) * ROWB + (lane >> 4) * 16;
    const uint32_t boffL = (uint32_t)((lane & 7) + (lane >> 4) * 8) * ROWB + ((lane >> 3) & 1) * 16;

    const int g = lane >> 2, tg = lane & 3;

    float acc[2][4][4];
#pragma unroll
    for (int mt = 0; mt < 2; mt++)
#pragma unroll
        for (int nt = 0; nt < 4; nt++)
#pragma unroll
            for (int i = 0; i < 4; i++) acc[mt][nt][i] = 0.0f;

#pragma unroll 1
    for (int e = 0; e < E_; e++) {
        const char* A1 = g_hq1 + ((size_t)e * BT_ + m0) * I_;
        const char* A2 = g_hq2 + ((size_t)e * BT_ + m0) * I_;
        const char* B1 = g_dq1 + ((size_t)e * D_ + n0) * I_;
        const char* B2 = g_dq2 + ((size_t)e * D_ + n0) * I_;

        int p1[2][4][4], px[2][4][4];
#pragma unroll
        for (int mt = 0; mt < 2; mt++)
#pragma unroll
            for (int nt = 0; nt < 4; nt++)
#pragma unroll
                for (int i = 0; i < 4; i++) { p1[mt][nt][i] = 0; px[mt][nt][i] = 0; }

        __syncthreads();   // smem safe to reuse across experts

#define ISSUE_B(buf, k0) do {                                             \
        uint32_t ao = (uint32_t)(buf) * 10240u, bo = (uint32_t)(buf) * 5120u; \
        cp16(sb + ao + adst1,          A1 + asrc1 + (k0));                \
        cp16(sb + ao + adst2,          A1 + asrc2 + (k0));                \
        cp16(sb + 20480 + ao + adst1,  A2 + asrc1 + (k0));                \
        cp16(sb + 20480 + ao + adst2,  A2 + asrc2 + (k0));                \
        cp16(sb + 40960 + bo + bdst,   B1 + bsrc + (k0));                 \
        cp16(sb + 51200 + bo + bdst,   B2 + bsrc + (k0));                 \
        cpcommit();                                                       \
    } while (0)

        ISSUE_B(0, 0);

#pragma unroll 1
        for (int s = 0; s < 16; s++) {
            cpwait0();
            __syncthreads();
            if (s + 1 < 16) ISSUE_B((s + 1) & 1, (s + 1) * 64);
            const uint32_t ab = (uint32_t)(s & 1) * 10240u;
            const uint32_t bb = (uint32_t)(s & 1) * 5120u;

#pragma unroll
            for (int ks = 0; ks < 2; ks++) {
                const uint32_t kb = (uint32_t)ks * 32u;
                uint32_t a1f[2][4], a2f[2][4];
#pragma unroll
                for (int mt = 0; mt < 2; mt++) {
                    uint32_t ro = (uint32_t)(wm * 32 + mt * 16) * ROWB;
                    ldsm4(a1f[mt], sb + ab + ro + aoffL + kb);
                    ldsm4(a2f[mt], sb + 20480 + ab + ro + aoffL + kb);
                }
                uint32_t b1f[2][4], b2f[2][4];
#pragma unroll
                for (int p = 0; p < 2; p++) {
                    uint32_t ro = (uint32_t)(wn * 32 + p * 16) * ROWB;
                    ldsm4(b1f[p], sb + 40960 + bb + ro + boffL + kb);
                    ldsm4(b2f[p], sb + 51200 + bb + ro + boffL + kb);
                }
#pragma unroll
                for (int mt = 0; mt < 2; mt++)
#pragma unroll
                    for (int p = 0; p < 2; p++)
#pragma unroll
                        for (int q = 0; q < 2; q++) {
                            const int nt = 2 * p + q;
                            imma32(p1[mt][nt], a1f[mt], &b1f[p][2 * q]);
                            imma32(px[mt][nt], a2f[mt], &b1f[p][2 * q]);
                            imma32(px[mt][nt], a1f[mt], &b2f[p][2 * q]);
                        }
            }
        }
#undef ISSUE_B

        // dequant + routing weight
#pragma unroll
        for (int mt = 0; mt < 2; mt++) {
            int rr = wm * 32 + mt * 16 + g;
            float sh0 = g_sh[e * BT_ + m0 + rr];
            float sh8 = g_sh[e * BT_ + m0 + rr + 8];
            float w0 = ws[rr][e] * sh0;
            float w1 = ws[rr + 8][e] * sh8;
#pragma unroll
            for (int nt = 0; nt < 4; nt++) {
                int c0 = n0 + wn * 32 + nt * 8 + tg * 2;
                float sd0 = __uint_as_float(g_cmD[e * D_ + c0])     * INV127;
                float sd1 = __uint_as_float(g_cmD[e * D_ + c0 + 1]) * INV127;
                acc[mt][nt][0] += w0 * sd0 * ((float)p1[mt][nt][0] + (float)px[mt][nt][0] * INV254);
                acc[mt][nt][1] += w0 * sd1 * ((float)p1[mt][nt][1] + (float)px[mt][nt][1] * INV254);
                acc[mt][nt][2] += w1 * sd0 * ((float)p1[mt][nt][2] + (float)px[mt][nt][2] * INV254);
                acc[mt][nt][3] += w1 * sd1 * ((float)p1[mt][nt][3] + (float)px[mt][nt][3] * INV254);
            }
        }
    }

#pragma unroll
    for (int mt = 0; mt < 2; mt++) {
        int r0 = m0 + wm * 32 + mt * 16 + g;
#pragma unroll
        for (int nt = 0; nt < 4; nt++) {
            int c0 = n0 + wn * 32 + nt * 8 + tg * 2;
            *(float2*)(out + (size_t)r0 * D_ + c0)       = make_float2(acc[mt][nt][0], acc[mt][nt][1]);
            *(float2*)(out + (size_t)(r0 + 8) * D_ + c0) = make_float2(acc[mt][nt][2], acc[mt][nt][3]);
        }
    }
}

// ---------------------------------------------------------------------------
// launch
// ---------------------------------------------------------------------------
extern "C" void kernel_launch(void* const* d_in, const int* in_sizes, int n_in,
                              void* d_out, int out_size)
{
    const float* x    = (const float*)d_in[0];
    const float* Wg   = (const float*)d_in[1];
    const float* Wu   = (const float*)d_in[2];
    const float* Wd   = (const float*)d_in[3];
    const float* Wr   = (const float*)d_in[4];
    const float* temp = (const float*)d_in[5];
    float* out = (float*)d_out;

    cudaFuncSetAttribute(passA_kernel, cudaFuncAttributeMaxDynamicSharedMemorySize, 81920);
    cudaFuncSetAttribute(passB_kernel, cudaFuncAttributeMaxDynamicSharedMemorySize, 61440);

    char *xq1, *xq2, *hq1, *hq2;
    float *sx, *sh, *hf;
    unsigned *cmG, *cmU, *cmD;
    char *gq1, *gq2, *uq1, *uq2, *dq1, *dq2;
    cudaGetSymbolAddress((void**)&xq1, g_xq1);
    cudaGetSymbolAddress((void**)&xq2, g_xq2);
    cudaGetSymbolAddress((void**)&sx,  g_sx);
    cudaGetSymbolAddress((void**)&hq1, g_hq1);
    cudaGetSymbolAddress((void**)&hq2, g_hq2);
    cudaGetSymbolAddress((void**)&sh,  g_sh);
    cudaGetSymbolAddress((void**)&hf,  g_hf);
    cudaGetSymbolAddress((void**)&cmG, g_cmG);
    cudaGetSymbolAddress((void**)&cmU, g_cmU);
    cudaGetSymbolAddress((void**)&cmD, g_cmD);
    cudaGetSymbolAddress((void**)&gq1, g_gq1);
    cudaGetSymbolAddress((void**)&gq2, g_gq2);
    cudaGetSymbolAddress((void**)&uq1, g_uq1);
    cudaGetSymbolAddress((void**)&uq2, g_uq2);
    cudaGetSymbolAddress((void**)&dq1, g_dq1);
    cudaGetSymbolAddress((void**)&dq2, g_dq2);

    routing_kernel<<<BT_ / 8, 256>>>(x, Wr, temp);
    quantrow_kernel<<<BT_ / 8, 256>>>(x, xq1, xq2, sx);

    dim3 gt(32, 32, E_), bt(32, 8);
    amaxcol_kernel<<<gt, bt>>>(Wg, cmG);
    amaxcol_kernel<<<gt, bt>>>(Wu, cmU);
    amaxcol_kernel<<<gt, bt>>>(Wd, cmD);
    quantT_kernel<<<gt, bt>>>(Wg, cmG, gq1, gq2);
    quantT_kernel<<<gt, bt>>>(Wu, cmU, uq1, uq2);
    quantT_kernel<<<gt, bt>>>(Wd, cmD, dq1, dq2);

    dim3 gA(I_ / 64, BT_ / 128, E_);
    passA_kernel<<<gA, 256, 81920>>>();

    quantrow_kernel<<<E_ * BT_ / 8, 256>>>(hf, hq1, hq2, sh);

    dim3 gB(D_ / 64, BT_ / 128);
    passB_kernel<<<gB, 256, 61440>>>(out);
}

// round 7
// speedup vs baseline: 5.3124x; 5.3124x over previous
#include <cuda_runtime.h>
#include <cuda_fp16.h>
#include <cstdint>
#include <cstddef>

// Problem dims: B=4, T=2048 -> BT=8192 tokens, D=1024, E=8, I=1024
#define BT_ 8192
#define D_  1024
#define E_  8
#define I_  1024

#define GOLDEN_CENTER 0.36787944117144233f
#define GOLDEN_LOWER  0.21231792754821915f
#define GOLDEN_UPPER  0.5f

// ---------------------------------------------------------------------------
// Device scratch (static; no runtime allocation)
// ---------------------------------------------------------------------------
__device__ __half g_xq[BT_ * D_];                 // x fp16 [t][d]
__device__ __half g_gq[E_ * D_ * I_];             // Wg^T fp16 [e][i][d]
__device__ __half g_uq[E_ * D_ * I_];             // Wu^T fp16 [e][i][d]
__device__ __half g_dq[E_ * D_ * I_];             // Wd^T fp16 [e][d][i]
__device__ __half g_hq[(size_t)E_ * BT_ * I_];    // h fp16 [e][t][i]
__device__ float  g_w[BT_ * E_];                  // routing weights

// ---------------------------------------------------------------------------
// helpers
// ---------------------------------------------------------------------------
__device__ __forceinline__ void hmma16(float c[4], const uint32_t a[4], const uint32_t b[2]) {
    asm volatile(
        "mma.sync.aligned.m16n8k16.row.col.f32.f16.f16.f32 "
        "{%0,%1,%2,%3},{%4,%5,%6,%7},{%8,%9},{%0,%1,%2,%3};\n"
        : "+f"(c[0]), "+f"(c[1]), "+f"(c[2]), "+f"(c[3])
        : "r"(a[0]), "r"(a[1]), "r"(a[2]), "r"(a[3]), "r"(b[0]), "r"(b[1]));
}
__device__ __forceinline__ void ldsm4(uint32_t r[4], uint32_t addr) {
    asm volatile("ldmatrix.sync.aligned.m8n8.x4.shared.b16 {%0,%1,%2,%3}, [%4];"
        : "=r"(r[0]), "=r"(r[1]), "=r"(r[2]), "=r"(r[3]) : "r"(addr));
}
__device__ __forceinline__ void cp16(uint32_t dst, const void* src) {
    asm volatile("cp.async.cg.shared.global [%0], [%1], 16;\n" :: "r"(dst), "l"(src) : "memory");
}
__device__ __forceinline__ void cpcommit() { asm volatile("cp.async.commit_group;\n" ::: "memory"); }
__device__ __forceinline__ void cpwait0()  { asm volatile("cp.async.wait_group 0;\n" ::: "memory"); }
__device__ __forceinline__ float siluf(float v) { return v / (1.0f + expf(-v)); }

// smem rows: 64 data bytes + 16 pad = 80B (16B-aligned rows; conflict-free ldmatrix)
#define RSTR 20   // words
#define KT   32   // K elems (fp16) per stage = 64 bytes

// ---------------------------------------------------------------------------
// Routing weights: one warp per token; fp64 accumulation
// ---------------------------------------------------------------------------
__global__ __launch_bounds__(256) void routing_kernel(
    const float* __restrict__ x, const float* __restrict__ Wr,
    const float* __restrict__ temp)
{
    int warp = threadIdx.x >> 5;
    int lane = threadIdx.x & 31;
    int t = blockIdx.x * 8 + warp;

    const float* xr = x + (size_t)t * D_;
    double acc0[E_], acc1[E_];
#pragma unroll
    for (int e = 0; e < E_; e++) { acc0[e] = 0.0; acc1[e] = 0.0; }

#pragma unroll 4
    for (int d0 = lane; d0 < D_; d0 += 64) {
        int d1 = d0 + 32;
        float xv0 = __ldg(xr + d0), xv1 = __ldg(xr + d1);
        float4 wa0 = *(const float4*)(Wr + d0 * E_);
        float4 wb0 = *(const float4*)(Wr + d0 * E_ + 4);
        float4 wa1 = *(const float4*)(Wr + d1 * E_);
        float4 wb1 = *(const float4*)(Wr + d1 * E_ + 4);
        acc0[0] += (double)xv0 * (double)wa0.x;  acc1[0] += (double)xv1 * (double)wa1.x;
        acc0[1] += (double)xv0 * (double)wa0.y;  acc1[1] += (double)xv1 * (double)wa1.y;
        acc0[2] += (double)xv0 * (double)wa0.z;  acc1[2] += (double)xv1 * (double)wa1.z;
        acc0[3] += (double)xv0 * (double)wa0.w;  acc1[3] += (double)xv1 * (double)wa1.w;
        acc0[4] += (double)xv0 * (double)wb0.x;  acc1[4] += (double)xv1 * (double)wb1.x;
        acc0[5] += (double)xv0 * (double)wb0.y;  acc1[5] += (double)xv1 * (double)wb1.y;
        acc0[6] += (double)xv0 * (double)wb0.z;  acc1[6] += (double)xv1 * (double)wb1.z;
        acc0[7] += (double)xv0 * (double)wb0.w;  acc1[7] += (double)xv1 * (double)wb1.w;
    }
    double acc[E_];
#pragma unroll
    for (int e = 0; e < E_; e++) acc[e] = acc0[e] + acc1[e];
#pragma unroll
    for (int off = 16; off > 0; off >>= 1) {
#pragma unroll
        for (int e = 0; e < E_; e++)
            acc[e] += __shfl_down_sync(0xffffffffu, acc[e], off);
    }

    if (lane == 0) {
        float T = temp[0];
        float dist[E_], wv[E_];
        float wsum = 0.0f;
#pragma unroll
        for (int e = 0; e < E_; e++) {
            float z = (float)acc[e] / T;
            float inh = 1.0f / (1.0f + expf(-z));
            dist[e] = fabsf(inh - GOLDEN_CENTER);
            bool zone = (inh >= GOLDEN_LOWER) && (inh <= GOLDEN_UPPER);
            wv[e] = zone ? expf(-dist[e] / 0.1f) : 0.0f;
            wsum += wv[e];
        }
        if (wsum < 1e-8f) {
            float fb[E_];
#pragma unroll
            for (int e = 0; e < E_; e++) fb[e] = expf(-dist[e] / 0.3f);
            int i1 = 0;
#pragma unroll
            for (int e = 1; e < E_; e++) if (fb[e] > fb[i1]) i1 = e;
            int i2 = (i1 == 0) ? 1 : 0;
#pragma unroll
            for (int e = 0; e < E_; e++)
                if (e != i1 && fb[e] > fb[i2]) i2 = e;
            float s = fmaxf(fb[i1] + fb[i2], 1e-8f);
#pragma unroll
            for (int e = 0; e < E_; e++)
                wv[e] = (e == i1 || e == i2) ? fb[e] / s : 0.0f;
        }
        float s2 = 0.0f;
#pragma unroll
        for (int e = 0; e < E_; e++) s2 += wv[e];
        float inv = 1.0f / fmaxf(s2, 1e-8f);
#pragma unroll
        for (int e = 0; e < E_; e++) g_w[t * E_ + e] = wv[e] * inv;
    }
}

// ---------------------------------------------------------------------------
// convert x -> fp16
// ---------------------------------------------------------------------------
__global__ __launch_bounds__(256) void convx_kernel(const float* __restrict__ x)
{
    int i = (blockIdx.x * 256 + threadIdx.x) * 4;
    float4 v = *(const float4*)(x + i);
    __half2 p01 = __floats2half2_rn(v.x, v.y);
    __half2 p23 = __floats2half2_rn(v.z, v.w);
    *(__half2*)(g_xq + i)     = p01;
    *(__half2*)(g_xq + i + 2) = p23;
}

// ---------------------------------------------------------------------------
// transpose + fp16: out[e][c][r] = half(in[e][r][c]),  1024x1024 per expert
// ---------------------------------------------------------------------------
__global__ void convT_kernel(const float* __restrict__ in, __half* __restrict__ oq)
{
    __shared__ float t[32][33];
    int e = blockIdx.z;
    const float* ip = in + ((size_t)e << 20);
    __half* op = oq + ((size_t)e << 20);
    int r0 = blockIdx.y * 32, c0 = blockIdx.x * 32;
    int tx = threadIdx.x, ty = threadIdx.y;

#pragma unroll
    for (int j = ty; j < 32; j += 8)
        t[j][tx] = ip[(size_t)(r0 + j) * 1024 + c0 + tx];
    __syncthreads();
#pragma unroll
    for (int j = ty; j < 32; j += 8)
        op[(size_t)(c0 + j) * 1024 + r0 + tx] = __float2half_rn(t[tx][j]);
}

// ---------------------------------------------------------------------------
// Pass A (fp16 HMMA, 1-term): h[e] = silu(X @ Wg_e) * (X @ Wu_e) -> fp16 g_hq
// CTA 128m x 64n, 8 warps (4m x 2n), warp 32x32, K=1024 in 32 stages of 32.
// smem/stage: A 10240 + G 5120 + U 5120 = 20480; x2 stages = 40960 bytes.
// grid (16, 64, 8)
// ---------------------------------------------------------------------------
__global__ __launch_bounds__(256) void passA_kernel()
{
    extern __shared__ char smem[];
    const uint32_t sb = (uint32_t)__cvta_generic_to_shared(smem);

    const int e  = blockIdx.z;
    const int m0 = blockIdx.y * 128;
    const int n0 = blockIdx.x * 64;

    const __half* Ax = g_xq + (size_t)m0 * D_;
    const __half* Gq = g_gq + ((size_t)e * I_ + n0) * D_;
    const __half* Uq = g_uq + ((size_t)e * I_ + n0) * D_;

    const int tid = threadIdx.x, lane = tid & 31, warp = tid >> 5;
    const int wm = warp & 3, wn = warp >> 2;

    const int lr = tid >> 2, lc = tid & 3;
    const uint32_t adst1 = (uint32_t)((lr)      * RSTR + lc * 4) * 4;
    const uint32_t adst2 = (uint32_t)((lr + 64) * RSTR + lc * 4) * 4;
    const uint32_t bdst  = adst1;
    const size_t asrc1 = (size_t)lr * D_ + lc * 8;
    const size_t asrc2 = (size_t)(lr + 64) * D_ + lc * 8;
    const size_t bsrc  = asrc1;

    const uint32_t aoffL = (uint32_t)((((lane & 7) + ((lane >> 3) & 1) * 8) * RSTR + (lane >> 4) * 4)) * 4;
    const uint32_t boffL = (uint32_t)((((lane & 7) + (lane >> 4) * 8) * RSTR + ((lane >> 3) & 1) * 4)) * 4;

    float cg[2][4][4], cu[2][4][4];
#pragma unroll
    for (int mt = 0; mt < 2; mt++)
#pragma unroll
        for (int nt = 0; nt < 4; nt++)
#pragma unroll
            for (int i = 0; i < 4; i++) { cg[mt][nt][i] = 0.0f; cu[mt][nt][i] = 0.0f; }

#define ISSUE_A(buf, k0) do {                                            \
        uint32_t ao = (uint32_t)(buf) * 10240u, bo = (uint32_t)(buf) * 5120u; \
        cp16(sb + ao + adst1,          Ax + asrc1 + (k0));               \
        cp16(sb + ao + adst2,          Ax + asrc2 + (k0));               \
        cp16(sb + 20480u + bo + bdst,  Gq + bsrc + (k0));                \
        cp16(sb + 30720u + bo + bdst,  Uq + bsrc + (k0));                \
        cpcommit();                                                      \
    } while (0)

    ISSUE_A(0, 0);

#pragma unroll 1
    for (int s = 0; s < D_ / KT; s++) {
        cpwait0();
        __syncthreads();
        if (s + 1 < D_ / KT) ISSUE_A((s + 1) & 1, (s + 1) * KT);
        const uint32_t ab = (uint32_t)(s & 1) * 10240u;
        const uint32_t bb = (uint32_t)(s & 1) * 5120u;

#pragma unroll
        for (int ks = 0; ks < 2; ks++) {
            const uint32_t kkb = (uint32_t)ks * 32u;   // 16 halfs
            uint32_t ah[2][4];
#pragma unroll
            for (int mt = 0; mt < 2; mt++) {
                uint32_t ro = (uint32_t)((wm * 32 + mt * 16) * RSTR * 4);
                ldsm4(ah[mt], sb + ab + ro + aoffL + kkb);
            }
            uint32_t gf[2][4], uf[2][4];
#pragma unroll
            for (int p = 0; p < 2; p++) {
                uint32_t ro = (uint32_t)((wn * 32 + p * 16) * RSTR * 4);
                ldsm4(gf[p], sb + 20480u + bb + ro + boffL + kkb);
                ldsm4(uf[p], sb + 30720u + bb + ro + boffL + kkb);
            }
#pragma unroll
            for (int mt = 0; mt < 2; mt++)
#pragma unroll
                for (int p = 0; p < 2; p++)
#pragma unroll
                    for (int q = 0; q < 2; q++) {
                        const int nt = 2 * p + q;
                        hmma16(cg[mt][nt], ah[mt], &gf[p][2 * q]);
                        hmma16(cu[mt][nt], ah[mt], &uf[p][2 * q]);
                    }
        }
    }
#undef ISSUE_A

    // epilogue: h = silu(gate)*up -> fp16
    const int g = lane >> 2, tg = lane & 3;
    __half* H = g_hq + (size_t)e * BT_ * I_;
#pragma unroll
    for (int mt = 0; mt < 2; mt++) {
        int r0 = m0 + wm * 32 + mt * 16 + g;
#pragma unroll
        for (int nt = 0; nt < 4; nt++) {
            int c0 = n0 + wn * 32 + nt * 8 + tg * 2;
            float h0 = siluf(cg[mt][nt][0]) * cu[mt][nt][0];
            float h1 = siluf(cg[mt][nt][1]) * cu[mt][nt][1];
            float h2 = siluf(cg[mt][nt][2]) * cu[mt][nt][2];
            float h3 = siluf(cg[mt][nt][3]) * cu[mt][nt][3];
            *(__half2*)(H + (size_t)r0 * I_ + c0)       = __floats2half2_rn(h0, h1);
            *(__half2*)(H + (size_t)(r0 + 8) * I_ + c0) = __floats2half2_rn(h2, h3);
        }
    }
}

// ---------------------------------------------------------------------------
// Pass B (fp16 HMMA, 1-term): out = sum_e w[:,e] .* (h[e] @ Wd_e)
// block 128m x 64n; grid (16, 64). smem: A 2x10240 + B 2x5120 = 30720.
// ---------------------------------------------------------------------------
__global__ __launch_bounds__(256) void passB_kernel(float* __restrict__ out)
{
    extern __shared__ char smem[];
    const uint32_t sb = (uint32_t)__cvta_generic_to_shared(smem);
    __shared__ float ws[128][E_];

    const int m0 = blockIdx.y * 128;
    const int n0 = blockIdx.x * 64;

    const int tid = threadIdx.x, lane = tid & 31, warp = tid >> 5;
    const int wm = warp & 3, wn = warp >> 2;

    for (int idx = tid; idx < 128 * E_; idx += 256)
        ws[idx >> 3][idx & 7] = g_w[(m0 + (idx >> 3)) * E_ + (idx & 7)];

    const int lr = tid >> 2, lc = tid & 3;
    const uint32_t adst1 = (uint32_t)((lr)      * RSTR + lc * 4) * 4;
    const uint32_t adst2 = (uint32_t)((lr + 64) * RSTR + lc * 4) * 4;
    const uint32_t bdst  = adst1;
    const size_t asrc1 = (size_t)lr * I_ + lc * 8;
    const size_t asrc2 = (size_t)(lr + 64) * I_ + lc * 8;
    const size_t bsrc  = asrc1;

    const uint32_t aoffL = (uint32_t)((((lane & 7) + ((lane >> 3) & 1) * 8) * RSTR + (lane >> 4) * 4)) * 4;
    const uint32_t boffL = (uint32_t)((((lane & 7) + (lane >> 4) * 8) * RSTR + ((lane >> 3) & 1) * 4)) * 4;

    const int g = lane >> 2, tg = lane & 3;

    float acc[2][4][4];
#pragma unroll
    for (int mt = 0; mt < 2; mt++)
#pragma unroll
        for (int nt = 0; nt < 4; nt++)
#pragma unroll
            for (int i = 0; i < 4; i++) acc[mt][nt][i] = 0.0f;

#pragma unroll 1
    for (int e = 0; e < E_; e++) {
        const __half* Ap = g_hq + ((size_t)e * BT_ + m0) * I_;
        const __half* Bp = g_dq + ((size_t)e * D_ + n0) * I_;

        float part[2][4][4];
#pragma unroll
        for (int mt = 0; mt < 2; mt++)
#pragma unroll
            for (int nt = 0; nt < 4; nt++)
#pragma unroll
                for (int i = 0; i < 4; i++) part[mt][nt][i] = 0.0f;

        __syncthreads();   // smem reuse across experts (and ws staging at e=0)

#define ISSUE_B(buf, k0) do {                                            \
        uint32_t ao = (uint32_t)(buf) * 10240u, bo = (uint32_t)(buf) * 5120u; \
        cp16(sb + ao + adst1,          Ap + asrc1 + (k0));               \
        cp16(sb + ao + adst2,          Ap + asrc2 + (k0));               \
        cp16(sb + 20480u + bo + bdst,  Bp + bsrc + (k0));                \
        cpcommit();                                                      \
    } while (0)

        ISSUE_B(0, 0);

#pragma unroll 1
        for (int s = 0; s < I_ / KT; s++) {
            cpwait0();
            __syncthreads();
            if (s + 1 < I_ / KT) ISSUE_B((s + 1) & 1, (s + 1) * KT);
            const uint32_t ab = (uint32_t)(s & 1) * 10240u;
            const uint32_t bb = (uint32_t)(s & 1) * 5120u;

#pragma unroll
            for (int ks = 0; ks < 2; ks++) {
                const uint32_t kkb = (uint32_t)ks * 32u;
                uint32_t af[2][4];
#pragma unroll
                for (int mt = 0; mt < 2; mt++) {
                    uint32_t ro = (uint32_t)((wm * 32 + mt * 16) * RSTR * 4);
                    ldsm4(af[mt], sb + ab + ro + aoffL + kkb);
                }
                uint32_t bf[2][4];
#pragma unroll
                for (int p = 0; p < 2; p++) {
                    uint32_t ro = (uint32_t)((wn * 32 + p * 16) * RSTR * 4);
                    ldsm4(bf[p], sb + 20480u + bb + ro + boffL + kkb);
                }
#pragma unroll
                for (int mt = 0; mt < 2; mt++)
#pragma unroll
                    for (int p = 0; p < 2; p++)
#pragma unroll
                        for (int q = 0; q < 2; q++)
                            hmma16(part[mt][2 * p + q], af[mt], &bf[p][2 * q]);
            }
        }
#undef ISSUE_B

        // apply per-token routing weight for this expert
#pragma unroll
        for (int mt = 0; mt < 2; mt++) {
            int rr = wm * 32 + mt * 16 + g;
            float w0 = ws[rr][e];
            float w1 = ws[rr + 8][e];
#pragma unroll
            for (int nt = 0; nt < 4; nt++) {
                acc[mt][nt][0] += w0 * part[mt][nt][0];
                acc[mt][nt][1] += w0 * part[mt][nt][1];
                acc[mt][nt][2] += w1 * part[mt][nt][2];
                acc[mt][nt][3] += w1 * part[mt][nt][3];
            }
        }
    }

#pragma unroll
    for (int mt = 0; mt < 2; mt++) {
        int r0 = m0 + wm * 32 + mt * 16 + g;
#pragma unroll
        for (int nt = 0; nt < 4; nt++) {
            int c0 = n0 + wn * 32 + nt * 8 + tg * 2;
            *(float2*)(out + (size_t)r0 * D_ + c0)       = make_float2(acc[mt][nt][0], acc[mt][nt][1]);
            *(float2*)(out + (size_t)(r0 + 8) * D_ + c0) = make_float2(acc[mt][nt][2], acc[mt][nt][3]);
        }
    }
}

// ---------------------------------------------------------------------------
// launch  (ordered so ncu -s 5 -c 1 profiles passA)
// ---------------------------------------------------------------------------
extern "C" void kernel_launch(void* const* d_in, const int* in_sizes, int n_in,
                              void* d_out, int out_size)
{
    const float* x    = (const float*)d_in[0];
    const float* Wg   = (const float*)d_in[1];
    const float* Wu   = (const float*)d_in[2];
    const float* Wd   = (const float*)d_in[3];
    const float* Wr   = (const float*)d_in[4];
    const float* temp = (const float*)d_in[5];
    float* out = (float*)d_out;

    cudaFuncSetAttribute(passA_kernel, cudaFuncAttributeMaxDynamicSharedMemorySize, 40960);
    cudaFuncSetAttribute(passB_kernel, cudaFuncAttributeMaxDynamicSharedMemorySize, 30720);

    __half *gq, *uq, *dq;
    cudaGetSymbolAddress((void**)&gq, g_gq);
    cudaGetSymbolAddress((void**)&uq, g_uq);
    cudaGetSymbolAddress((void**)&dq, g_dq);

    routing_kernel<<<BT_ / 8, 256>>>(x, Wr, temp);          // 1
    convx_kernel<<<BT_ * D_ / 1024, 256>>>(x);              // 2

    dim3 gt(32, 32, E_), bt(32, 8);
    convT_kernel<<<gt, bt>>>(Wg, gq);                       // 3
    convT_kernel<<<gt, bt>>>(Wu, uq);                       // 4
    convT_kernel<<<gt, bt>>>(Wd, dq);                       // 5

    dim3 gA(I_ / 64, BT_ / 128, E_);
    passA_kernel<<<gA, 256, 40960>>>();                     // 6  <- ncu target

    dim3 gB(D_ / 64, BT_ / 128);
    passB_kernel<<<gB, 256, 30720>>>(out);                  // 7
}

// round 8
// speedup vs baseline: 9.4531x; 1.7794x over previous
#include <cuda_runtime.h>
#include <cuda_fp16.h>
#include <cstdint>
#include <cstddef>

// Problem dims: B=4, T=2048 -> BT=8192 tokens, D=1024, E=8, I=1024
#define BT_ 8192
#define D_  1024
#define E_  8
#define I_  1024

#define GOLDEN_CENTER 0.36787944117144233f
#define GOLDEN_LOWER  0.21231792754821915f
#define GOLDEN_UPPER  0.5f

// ---------------------------------------------------------------------------
// Device scratch (static; no runtime allocation)
// ---------------------------------------------------------------------------
__device__ __half g_xq[BT_ * D_];                      // x fp16 [t][d]
__device__ __half g_gq[E_ * D_ * I_];                  // Wg^T fp16 [e][i][d]
__device__ __half g_uq[E_ * D_ * I_];                  // Wu^T fp16 [e][i][d]
__device__ __half g_dq[E_ * D_ * I_];                  // Wd^T fp16 [e][d][i]
__device__ __half g_guq[(size_t)2 * E_ * BT_ * I_];    // gate|up fp16 [s][t][i], s<8 gate
__device__ __half g_hq[(size_t)E_ * BT_ * I_];         // h' = w*silu(g)*u fp16 [e][t][i]
__device__ float  g_w[BT_ * E_];                       // routing weights

// ---------------------------------------------------------------------------
// helpers
// ---------------------------------------------------------------------------
__device__ __forceinline__ void hmma16(float c[4], const uint32_t a[4], const uint32_t b[2]) {
    asm volatile(
        "mma.sync.aligned.m16n8k16.row.col.f32.f16.f16.f32 "
        "{%0,%1,%2,%3},{%4,%5,%6,%7},{%8,%9},{%0,%1,%2,%3};\n"
        : "+f"(c[0]), "+f"(c[1]), "+f"(c[2]), "+f"(c[3])
        : "r"(a[0]), "r"(a[1]), "r"(a[2]), "r"(a[3]), "r"(b[0]), "r"(b[1]));
}
__device__ __forceinline__ void ldsm4(uint32_t r[4], uint32_t addr) {
    asm volatile("ldmatrix.sync.aligned.m8n8.x4.shared.b16 {%0,%1,%2,%3}, [%4];"
        : "=r"(r[0]), "=r"(r[1]), "=r"(r[2]), "=r"(r[3]) : "r"(addr));
}
__device__ __forceinline__ void cp16(uint32_t dst, const void* src) {
    asm volatile("cp.async.cg.shared.global [%0], [%1], 16;\n" :: "r"(dst), "l"(src) : "memory");
}
__device__ __forceinline__ void cpcommit() { asm volatile("cp.async.commit_group;\n" ::: "memory"); }
__device__ __forceinline__ void cpwait0()  { asm volatile("cp.async.wait_group 0;\n" ::: "memory"); }
__device__ __forceinline__ float siluf(float v) { return v / (1.0f + expf(-v)); }

// smem rows: 128 data bytes + 16 pad = 144B; (4r+c) mod 32 distinct -> conflict-free
#define ROWB   144u
#define KT     64        // K halfs per stage (128 bytes)
#define TILEB  18432u    // 128 rows * 144B
#define STGB   36864u    // A tile + B tile per stage

// ---------------------------------------------------------------------------
// Routing weights: one warp per token; fp64 accumulation (unchanged)
// ---------------------------------------------------------------------------
__global__ __launch_bounds__(256) void routing_kernel(
    const float* __restrict__ x, const float* __restrict__ Wr,
    const float* __restrict__ temp)
{
    int warp = threadIdx.x >> 5;
    int lane = threadIdx.x & 31;
    int t = blockIdx.x * 8 + warp;

    const float* xr = x + (size_t)t * D_;
    double acc0[E_], acc1[E_];
#pragma unroll
    for (int e = 0; e < E_; e++) { acc0[e] = 0.0; acc1[e] = 0.0; }

#pragma unroll 4
    for (int d0 = lane; d0 < D_; d0 += 64) {
        int d1 = d0 + 32;
        float xv0 = __ldg(xr + d0), xv1 = __ldg(xr + d1);
        float4 wa0 = *(const float4*)(Wr + d0 * E_);
        float4 wb0 = *(const float4*)(Wr + d0 * E_ + 4);
        float4 wa1 = *(const float4*)(Wr + d1 * E_);
        float4 wb1 = *(const float4*)(Wr + d1 * E_ + 4);
        acc0[0] += (double)xv0 * (double)wa0.x;  acc1[0] += (double)xv1 * (double)wa1.x;
        acc0[1] += (double)xv0 * (double)wa0.y;  acc1[1] += (double)xv1 * (double)wa1.y;
        acc0[2] += (double)xv0 * (double)wa0.z;  acc1[2] += (double)xv1 * (double)wa1.z;
        acc0[3] += (double)xv0 * (double)wa0.w;  acc1[3] += (double)xv1 * (double)wa1.w;
        acc0[4] += (double)xv0 * (double)wb0.x;  acc1[4] += (double)xv1 * (double)wb1.x;
        acc0[5] += (double)xv0 * (double)wb0.y;  acc1[5] += (double)xv1 * (double)wb1.y;
        acc0[6] += (double)xv0 * (double)wb0.z;  acc1[6] += (double)xv1 * (double)wb1.z;
        acc0[7] += (double)xv0 * (double)wb0.w;  acc1[7] += (double)xv1 * (double)wb1.w;
    }
    double acc[E_];
#pragma unroll
    for (int e = 0; e < E_; e++) acc[e] = acc0[e] + acc1[e];
#pragma unroll
    for (int off = 16; off > 0; off >>= 1) {
#pragma unroll
        for (int e = 0; e < E_; e++)
            acc[e] += __shfl_down_sync(0xffffffffu, acc[e], off);
    }

    if (lane == 0) {
        float T = temp[0];
        float dist[E_], wv[E_];
        float wsum = 0.0f;
#pragma unroll
        for (int e = 0; e < E_; e++) {
            float z = (float)acc[e] / T;
            float inh = 1.0f / (1.0f + expf(-z));
            dist[e] = fabsf(inh - GOLDEN_CENTER);
            bool zone = (inh >= GOLDEN_LOWER) && (inh <= GOLDEN_UPPER);
            wv[e] = zone ? expf(-dist[e] / 0.1f) : 0.0f;
            wsum += wv[e];
        }
        if (wsum < 1e-8f) {
            float fb[E_];
#pragma unroll
            for (int e = 0; e < E_; e++) fb[e] = expf(-dist[e] / 0.3f);
            int i1 = 0;
#pragma unroll
            for (int e = 1; e < E_; e++) if (fb[e] > fb[i1]) i1 = e;
            int i2 = (i1 == 0) ? 1 : 0;
#pragma unroll
            for (int e = 0; e < E_; e++)
                if (e != i1 && fb[e] > fb[i2]) i2 = e;
            float s = fmaxf(fb[i1] + fb[i2], 1e-8f);
#pragma unroll
            for (int e = 0; e < E_; e++)
                wv[e] = (e == i1 || e == i2) ? fb[e] / s : 0.0f;
        }
        float s2 = 0.0f;
#pragma unroll
        for (int e = 0; e < E_; e++) s2 += wv[e];
        float inv = 1.0f / fmaxf(s2, 1e-8f);
#pragma unroll
        for (int e = 0; e < E_; e++) g_w[t * E_ + e] = wv[e] * inv;
    }
}

// ---------------------------------------------------------------------------
// convert x -> fp16
// ---------------------------------------------------------------------------
__global__ __launch_bounds__(256) void convx_kernel(const float* __restrict__ x)
{
    int i = (blockIdx.x * 256 + threadIdx.x) * 4;
    float4 v = *(const float4*)(x + i);
    *(__half2*)(g_xq + i)     = __floats2half2_rn(v.x, v.y);
    *(__half2*)(g_xq + i + 2) = __floats2half2_rn(v.z, v.w);
}

// ---------------------------------------------------------------------------
// transpose + fp16: out[e][c][r] = half(in[e][r][c])
// ---------------------------------------------------------------------------
__global__ void convT_kernel(const float* __restrict__ in, __half* __restrict__ oq)
{
    __shared__ float t[32][33];
    int e = blockIdx.z;
    const float* ip = in + ((size_t)e << 20);
    __half* op = oq + ((size_t)e << 20);
    int r0 = blockIdx.y * 32, c0 = blockIdx.x * 32;
    int tx = threadIdx.x, ty = threadIdx.y;

#pragma unroll
    for (int j = ty; j < 32; j += 8)
        t[j][tx] = ip[(size_t)(r0 + j) * 1024 + c0 + tx];
    __syncthreads();
#pragma unroll
    for (int j = ty; j < 32; j += 8)
        op[(size_t)(c0 + j) * 1024 + r0 + tx] = __float2half_rn(t[tx][j]);
}

// ---------------------------------------------------------------------------
// shared GEMM-core fragment math. CTA 128x128, 8 warps (2m x 4n), warp 64x32.
// ---------------------------------------------------------------------------
struct Frag { uint32_t aoffL, boffL, aro, bro; int wm, wn, g, tg; };

__device__ __forceinline__ Frag mk_frag(int tid) {
    Frag f;
    int lane = tid & 31, warp = tid >> 5;
    f.wm = warp & 1; f.wn = warp >> 1;
    f.g = lane >> 2; f.tg = lane & 3;
    f.aoffL = (uint32_t)((lane & 7) + ((lane >> 3) & 1) * 8) * ROWB + (lane >> 4) * 16;
    f.boffL = (uint32_t)((lane & 7) + (lane >> 4) * 8) * ROWB + ((lane >> 3) & 1) * 16;
    f.aro = (uint32_t)(f.wm * 64) * ROWB;
    f.bro = TILEB + (uint32_t)(f.wn * 32) * ROWB;
    return f;
}

// compute one K=64 stage from smem buffer at byte base st
__device__ __forceinline__ void stage_mma(uint32_t st, const Frag& f, float acc[4][4][4]) {
#pragma unroll
    for (int ks = 0; ks < 4; ks++) {
        const uint32_t kb = (uint32_t)ks * 32u;
        uint32_t af[4][4];
#pragma unroll
        for (int mt = 0; mt < 4; mt++)
            ldsm4(af[mt], st + f.aro + (uint32_t)(mt * 16) * ROWB + f.aoffL + kb);
        uint32_t bf[2][4];
#pragma unroll
        for (int p = 0; p < 2; p++)
            ldsm4(bf[p], st + f.bro + (uint32_t)(p * 16) * ROWB + f.boffL + kb);
#pragma unroll
        for (int mt = 0; mt < 4; mt++)
#pragma unroll
            for (int p = 0; p < 2; p++)
#pragma unroll
                for (int q = 0; q < 2; q++)
                    hmma16(acc[mt][2 * p + q], af[mt], &bf[p][2 * q]);
    }
}

// issue cp.async for one stage: A rows m-tile, B rows n-tile, both 128x64 halfs
#define ISSUE_STAGE(buf, Ap, Bp, k0) do {                                     \
        uint32_t st_ = sb + (uint32_t)(buf) * STGB;                           \
        _Pragma("unroll")                                                     \
        for (int j = 0; j < 4; j++) {                                         \
            int r_ = rbase + 32 * j;                                          \
            uint32_t off_ = (uint32_t)r_ * ROWB + (uint32_t)qq * 16;          \
            cp16(st_ + off_,         (Ap) + (size_t)r_ * 1024 + (k0) + qq * 8); \
            cp16(st_ + TILEB + off_, (Bp) + (size_t)r_ * 1024 + (k0) + qq * 8); \
        }                                                                     \
        cpcommit();                                                           \
    } while (0)

// ---------------------------------------------------------------------------
// gemm_gu: out[s] = X @ W[s]^T, s in [0,16): s<8 -> Wg[e], s>=8 -> Wu[e-8]
// grid (I/128=8, BT/128=64, 16); out fp16 [s][t][i]
// ---------------------------------------------------------------------------
__global__ __launch_bounds__(256) void gemm_gu_kernel()
{
    extern __shared__ char smem[];
    const uint32_t sb = (uint32_t)__cvta_generic_to_shared(smem);

    const int s4 = blockIdx.z;
    const int m0 = blockIdx.y * 128;
    const int n0 = blockIdx.x * 128;

    const __half* Ap = g_xq + (size_t)m0 * D_;
    const __half* Bp = (s4 < 8 ? g_gq + ((size_t)s4 * I_ + n0) * D_
                               : g_uq + ((size_t)(s4 - 8) * I_ + n0) * D_);
    __half* Op = g_guq + (size_t)s4 * BT_ * I_;

    const int tid = threadIdx.x;
    const int rbase = tid >> 3, qq = tid & 7;
    const Frag f = mk_frag(tid);

    float acc[4][4][4];
#pragma unroll
    for (int mt = 0; mt < 4; mt++)
#pragma unroll
        for (int nt = 0; nt < 4; nt++)
#pragma unroll
            for (int i = 0; i < 4; i++) acc[mt][nt][i] = 0.0f;

    ISSUE_STAGE(0, Ap, Bp, 0);
#pragma unroll 1
    for (int st = 0; st < D_ / KT; st++) {
        cpwait0();
        __syncthreads();
        if (st + 1 < D_ / KT) ISSUE_STAGE((st + 1) & 1, Ap, Bp, (st + 1) * KT);
        stage_mma(sb + (uint32_t)(st & 1) * STGB, f, acc);
        __syncthreads();
    }

    // epilogue fp16
#pragma unroll
    for (int mt = 0; mt < 4; mt++) {
        int r0 = m0 + f.wm * 64 + mt * 16 + f.g;
#pragma unroll
        for (int nt = 0; nt < 4; nt++) {
            int c0 = n0 + f.wn * 32 + nt * 8 + f.tg * 2;
            *(__half2*)(Op + (size_t)r0 * I_ + c0)       = __floats2half2_rn(acc[mt][nt][0], acc[mt][nt][1]);
            *(__half2*)(Op + (size_t)(r0 + 8) * I_ + c0) = __floats2half2_rn(acc[mt][nt][2], acc[mt][nt][3]);
        }
    }
}

// ---------------------------------------------------------------------------
// silumul: h'[e][t][i] = w[t][e] * silu(gate) * up   (one row per block)
// ---------------------------------------------------------------------------
__global__ __launch_bounds__(256) void silumul_kernel()
{
    int row = blockIdx.x;            // row = e*BT + t
    int e = row >> 13, t = row & (BT_ - 1);
    float w = g_w[t * E_ + e];
    const __half* gp = g_guq + (size_t)row * I_;
    const __half* up = g_guq + ((size_t)(e + 8) * BT_ + t) * I_;
    __half* hp = g_hq + (size_t)row * I_;

    int i = threadIdx.x * 4;
    __half2 gv0 = *(const __half2*)(gp + i),     gv1 = *(const __half2*)(gp + i + 2);
    __half2 uv0 = *(const __half2*)(up + i),     uv1 = *(const __half2*)(up + i + 2);
    float g0 = __half2float(gv0.x), g1 = __half2float(gv0.y);
    float g2 = __half2float(gv1.x), g3 = __half2float(gv1.y);
    float u0 = __half2float(uv0.x), u1 = __half2float(uv0.y);
    float u2 = __half2float(uv1.x), u3 = __half2float(uv1.y);
    *(__half2*)(hp + i)     = __floats2half2_rn(w * siluf(g0) * u0, w * siluf(g1) * u1);
    *(__half2*)(hp + i + 2) = __floats2half2_rn(w * siluf(g2) * u2, w * siluf(g3) * u3);
}

// ---------------------------------------------------------------------------
// gemm_d: out[t][d] = sum_e h'[e] @ Wd[e]^T   — 128 continuous stages
// grid (D/128=8, BT/128=64); out fp32
// ---------------------------------------------------------------------------
__global__ __launch_bounds__(256) void gemm_d_kernel(float* __restrict__ out)
{
    extern __shared__ char smem[];
    const uint32_t sb = (uint32_t)__cvta_generic_to_shared(smem);

    const int m0 = blockIdx.y * 128;
    const int n0 = blockIdx.x * 128;

    const int tid = threadIdx.x;
    const int rbase = tid >> 3, qq = tid & 7;
    const Frag f = mk_frag(tid);

    float acc[4][4][4];
#pragma unroll
    for (int mt = 0; mt < 4; mt++)
#pragma unroll
        for (int nt = 0; nt < 4; nt++)
#pragma unroll
            for (int i = 0; i < 4; i++) acc[mt][nt][i] = 0.0f;

    const int NS = E_ * (I_ / KT);   // 128 stages
    {
        const __half* Ap = g_hq + (size_t)m0 * I_;
        const __half* Bp = g_dq + (size_t)n0 * I_;
        ISSUE_STAGE(0, Ap, Bp, 0);
    }
#pragma unroll 1
    for (int st = 0; st < NS; st++) {
        cpwait0();
        __syncthreads();
        if (st + 1 < NS) {
            int e1 = (st + 1) >> 4, k1 = ((st + 1) & 15) * KT;
            const __half* Ap = g_hq + ((size_t)e1 * BT_ + m0) * I_;
            const __half* Bp = g_dq + ((size_t)e1 * D_ + n0) * I_;
            ISSUE_STAGE((st + 1) & 1, Ap, Bp, k1);
        }
        stage_mma(sb + (uint32_t)(st & 1) * STGB, f, acc);
        __syncthreads();
    }

    // epilogue fp32
#pragma unroll
    for (int mt = 0; mt < 4; mt++) {
        int r0 = m0 + f.wm * 64 + mt * 16 + f.g;
#pragma unroll
        for (int nt = 0; nt < 4; nt++) {
            int c0 = n0 + f.wn * 32 + nt * 8 + f.tg * 2;
            *(float2*)(out + (size_t)r0 * D_ + c0)       = make_float2(acc[mt][nt][0], acc[mt][nt][1]);
            *(float2*)(out + (size_t)(r0 + 8) * D_ + c0) = make_float2(acc[mt][nt][2], acc[mt][nt][3]);
        }
    }
}

// ---------------------------------------------------------------------------
// launch
// ---------------------------------------------------------------------------
extern "C" void kernel_launch(void* const* d_in, const int* in_sizes, int n_in,
                              void* d_out, int out_size)
{
    const float* x    = (const float*)d_in[0];
    const float* Wg   = (const float*)d_in[1];
    const float* Wu   = (const float*)d_in[2];
    const float* Wd   = (const float*)d_in[3];
    const float* Wr   = (const float*)d_in[4];
    const float* temp = (const float*)d_in[5];
    float* out = (float*)d_out;

    cudaFuncSetAttribute(gemm_gu_kernel, cudaFuncAttributeMaxDynamicSharedMemorySize, 2 * STGB);
    cudaFuncSetAttribute(gemm_d_kernel,  cudaFuncAttributeMaxDynamicSharedMemorySize, 2 * STGB);

    __half *gq, *uq, *dq;
    cudaGetSymbolAddress((void**)&gq, g_gq);
    cudaGetSymbolAddress((void**)&uq, g_uq);
    cudaGetSymbolAddress((void**)&dq, g_dq);

    routing_kernel<<<BT_ / 8, 256>>>(x, Wr, temp);
    convx_kernel<<<BT_ * D_ / 1024, 256>>>(x);

    dim3 gt(32, 32, E_), bt(32, 8);
    convT_kernel<<<gt, bt>>>(Wg, gq);
    convT_kernel<<<gt, bt>>>(Wu, uq);
    convT_kernel<<<gt, bt>>>(Wd, dq);

    dim3 gGU(I_ / 128, BT_ / 128, 2 * E_);
    gemm_gu_kernel<<<gGU, 256, 2 * STGB>>>();

    silumul_kernel<<<E_ * BT_, 256>>>();

    dim3 gD(D_ / 128, BT_ / 128);
    gemm_d_kernel<<<gD, 256, 2 * STGB>>>(out);
}

// round 10
// speedup vs baseline: 9.4723x; 1.0020x over previous
#include <cuda_runtime.h>
#include <cuda_fp16.h>
#include <cstdint>
#include <cstddef>

// Problem dims: B=4, T=2048 -> BT=8192 tokens, D=1024, E=8, I=1024
#define BT_ 8192
#define D_  1024
#define E_  8
#define I_  1024

#define GOLDEN_CENTER 0.36787944117144233f
#define GOLDEN_LOWER  0.21231792754821915f
#define GOLDEN_UPPER  0.5f

// ---------------------------------------------------------------------------
// Device scratch (static; no runtime allocation)
// ---------------------------------------------------------------------------
__device__ __half g_xq[BT_ * D_];                      // x fp16 [t][d]
__device__ __half g_gq[E_ * D_ * I_];                  // Wg^T fp16 [e][i][d]
__device__ __half g_uq[E_ * D_ * I_];                  // Wu^T fp16 [e][i][d]
__device__ __half g_dq[E_ * D_ * I_];                  // Wd^T fp16 [e][d][i]
__device__ __half g_guq[(size_t)2 * E_ * BT_ * I_];    // gate|up fp16 [s][t][i]
__device__ __half g_hq[(size_t)E_ * BT_ * I_];         // h' = w*silu(g)*u fp16
__device__ float  g_w[BT_ * E_];                       // routing weights

// ---------------------------------------------------------------------------
// helpers
// ---------------------------------------------------------------------------
__device__ __forceinline__ void hmma16(float c[4], const uint32_t a[4], const uint32_t b[2]) {
    asm volatile(
        "mma.sync.aligned.m16n8k16.row.col.f32.f16.f16.f32 "
        "{%0,%1,%2,%3},{%4,%5,%6,%7},{%8,%9},{%0,%1,%2,%3};\n"
        : "+f"(c[0]), "+f"(c[1]), "+f"(c[2]), "+f"(c[3])
        : "r"(a[0]), "r"(a[1]), "r"(a[2]), "r"(a[3]), "r"(b[0]), "r"(b[1]));
}
__device__ __forceinline__ void ldsm4(uint32_t r[4], uint32_t addr) {
    asm volatile("ldmatrix.sync.aligned.m8n8.x4.shared.b16 {%0,%1,%2,%3}, [%4];"
        : "=r"(r[0]), "=r"(r[1]), "=r"(r[2]), "=r"(r[3]) : "r"(addr));
}
__device__ __forceinline__ void cp16(uint32_t dst, const void* src) {
    asm volatile("cp.async.cg.shared.global [%0], [%1], 16;\n" :: "r"(dst), "l"(src) : "memory");
}
__device__ __forceinline__ void cpcommit() { asm volatile("cp.async.commit_group;\n" ::: "memory"); }
__device__ __forceinline__ void cpwait1()  { asm volatile("cp.async.wait_group 1;\n" ::: "memory"); }
__device__ __forceinline__ float siluf(float v) { return v / (1.0f + expf(-v)); }

// smem rows: 128 data bytes + 16 pad = 144B; conflict-free for ldmatrix
#define ROWB   144u
#define KT     64        // K halfs per stage (128 bytes)
#define ATB    36864u    // A tile: 256 rows * 144B
#define BTB    18432u    // B tile: 128 rows * 144B
#define STGB   55296u    // stage bytes
#define NSTG   3u        // ring depth

// ---------------------------------------------------------------------------
// Routing weights: one warp per token; fp64 accumulation (unchanged)
// ---------------------------------------------------------------------------
__global__ __launch_bounds__(256) void routing_kernel(
    const float* __restrict__ x, const float* __restrict__ Wr,
    const float* __restrict__ temp)
{
    int warp = threadIdx.x >> 5;
    int lane = threadIdx.x & 31;
    int t = blockIdx.x * 8 + warp;

    const float* xr = x + (size_t)t * D_;
    double acc0[E_], acc1[E_];
#pragma unroll
    for (int e = 0; e < E_; e++) { acc0[e] = 0.0; acc1[e] = 0.0; }

#pragma unroll 4
    for (int d0 = lane; d0 < D_; d0 += 64) {
        int d1 = d0 + 32;
        float xv0 = __ldg(xr + d0), xv1 = __ldg(xr + d1);
        float4 wa0 = *(const float4*)(Wr + d0 * E_);
        float4 wb0 = *(const float4*)(Wr + d0 * E_ + 4);
        float4 wa1 = *(const float4*)(Wr + d1 * E_);
        float4 wb1 = *(const float4*)(Wr + d1 * E_ + 4);
        acc0[0] += (double)xv0 * (double)wa0.x;  acc1[0] += (double)xv1 * (double)wa1.x;
        acc0[1] += (double)xv0 * (double)wa0.y;  acc1[1] += (double)xv1 * (double)wa1.y;
        acc0[2] += (double)xv0 * (double)wa0.z;  acc1[2] += (double)xv1 * (double)wa1.z;
        acc0[3] += (double)xv0 * (double)wa0.w;  acc1[3] += (double)xv1 * (double)wa1.w;
        acc0[4] += (double)xv0 * (double)wb0.x;  acc1[4] += (double)xv1 * (double)wb1.x;
        acc0[5] += (double)xv0 * (double)wb0.y;  acc1[5] += (double)xv1 * (double)wb1.y;
        acc0[6] += (double)xv0 * (double)wb0.z;  acc1[6] += (double)xv1 * (double)wb1.z;
        acc0[7] += (double)xv0 * (double)wb0.w;  acc1[7] += (double)xv1 * (double)wb1.w;
    }
    double acc[E_];
#pragma unroll
    for (int e = 0; e < E_; e++) acc[e] = acc0[e] + acc1[e];
#pragma unroll
    for (int off = 16; off > 0; off >>= 1) {
#pragma unroll
        for (int e = 0; e < E_; e++)
            acc[e] += __shfl_down_sync(0xffffffffu, acc[e], off);
    }

    if (lane == 0) {
        float T = temp[0];
        float dist[E_], wv[E_];
        float wsum = 0.0f;
#pragma unroll
        for (int e = 0; e < E_; e++) {
            float z = (float)acc[e] / T;
            float inh = 1.0f / (1.0f + expf(-z));
            dist[e] = fabsf(inh - GOLDEN_CENTER);
            bool zone = (inh >= GOLDEN_LOWER) && (inh <= GOLDEN_UPPER);
            wv[e] = zone ? expf(-dist[e] / 0.1f) : 0.0f;
            wsum += wv[e];
        }
        if (wsum < 1e-8f) {
            float fb[E_];
#pragma unroll
            for (int e = 0; e < E_; e++) fb[e] = expf(-dist[e] / 0.3f);
            int i1 = 0;
#pragma unroll
            for (int e = 1; e < E_; e++) if (fb[e] > fb[i1]) i1 = e;
            int i2 = (i1 == 0) ? 1 : 0;
#pragma unroll
            for (int e = 0; e < E_; e++)
                if (e != i1 && fb[e] > fb[i2]) i2 = e;
            float s = fmaxf(fb[i1] + fb[i2], 1e-8f);
#pragma unroll
            for (int e = 0; e < E_; e++)
                wv[e] = (e == i1 || e == i2) ? fb[e] / s : 0.0f;
        }
        float s2 = 0.0f;
#pragma unroll
        for (int e = 0; e < E_; e++) s2 += wv[e];
        float inv = 1.0f / fmaxf(s2, 1e-8f);
#pragma unroll
        for (int e = 0; e < E_; e++) g_w[t * E_ + e] = wv[e] * inv;
    }
}

// ---------------------------------------------------------------------------
// convert x -> fp16
// ---------------------------------------------------------------------------
__global__ __launch_bounds__(256) void convx_kernel(const float* __restrict__ x)
{
    int i = (blockIdx.x * 256 + threadIdx.x) * 4;
    float4 v = *(const float4*)(x + i);
    *(__half2*)(g_xq + i)     = __floats2half2_rn(v.x, v.y);
    *(__half2*)(g_xq + i + 2) = __floats2half2_rn(v.z, v.w);
}

// ---------------------------------------------------------------------------
// transpose + fp16: out[e][c][r] = half(in[e][r][c])
// ---------------------------------------------------------------------------
__global__ void convT_kernel(const float* __restrict__ in, __half* __restrict__ oq)
{
    __shared__ float t[32][33];
    int e = blockIdx.z;
    const float* ip = in + ((size_t)e << 20);
    __half* op = oq + ((size_t)e << 20);
    int r0 = blockIdx.y * 32, c0 = blockIdx.x * 32;
    int tx = threadIdx.x, ty = threadIdx.y;

#pragma unroll
    for (int j = ty; j < 32; j += 8)
        t[j][tx] = ip[(size_t)(r0 + j) * 1024 + c0 + tx];
    __syncthreads();
#pragma unroll
    for (int j = ty; j < 32; j += 8)
        op[(size_t)(c0 + j) * 1024 + r0 + tx] = __float2half_rn(t[tx][j]);
}

// ---------------------------------------------------------------------------
// GEMM core: CTA 256m x 128n, 8 warps (4m x 2n), warp 64x64, K=64/stage,
// 3-stage cp.async ring, one __syncthreads per stage.
// ---------------------------------------------------------------------------
struct Frag { uint32_t aoffL, boffL, aro, bro; int wm, wn, g, tg; };

__device__ __forceinline__ Frag mk_frag(int tid) {
    Frag f;
    int lane = tid & 31, warp = tid >> 5;
    f.wm = warp & 3; f.wn = warp >> 2;
    f.g = lane >> 2; f.tg = lane & 3;
    f.aoffL = (uint32_t)((lane & 7) + ((lane >> 3) & 1) * 8) * ROWB + (lane >> 4) * 16;
    f.boffL = (uint32_t)((lane & 7) + (lane >> 4) * 8) * ROWB + ((lane >> 3) & 1) * 16;
    f.aro = (uint32_t)(f.wm * 64) * ROWB;
    f.bro = ATB + (uint32_t)(f.wn * 64) * ROWB;
    return f;
}

// one K=64 stage: 32 LDSM.x4 -> 128 HMMA per warp
__device__ __forceinline__ void stage_mma(uint32_t st, const Frag& f, float acc[4][8][4]) {
#pragma unroll
    for (int ks = 0; ks < 4; ks++) {
        const uint32_t kb = (uint32_t)ks * 32u;
        uint32_t af[4][4];
#pragma unroll
        for (int mt = 0; mt < 4; mt++)
            ldsm4(af[mt], st + f.aro + (uint32_t)(mt * 16) * ROWB + f.aoffL + kb);
        uint32_t bf[4][4];
#pragma unroll
        for (int p = 0; p < 4; p++)
            ldsm4(bf[p], st + f.bro + (uint32_t)(p * 16) * ROWB + f.boffL + kb);
#pragma unroll
        for (int mt = 0; mt < 4; mt++)
#pragma unroll
            for (int p = 0; p < 4; p++)
#pragma unroll
                for (int q = 0; q < 2; q++)
                    hmma16(acc[mt][2 * p + q], af[mt], &bf[p][2 * q]);
    }
}

// issue one stage: A 256x64 halfs (8 chunks/thread), B 128x64 (4 chunks/thread)
#define ISSUE_STAGE(buf, Ap, Bp, k0) do {                                       \
        uint32_t st_ = sb + (uint32_t)(buf) * STGB;                             \
        _Pragma("unroll")                                                       \
        for (int j = 0; j < 8; j++) {                                           \
            int r_ = rbase + 32 * j;                                            \
            cp16(st_ + (uint32_t)r_ * ROWB + qo, (Ap) + (size_t)r_ * 1024 + (k0) + qh); \
        }                                                                       \
        _Pragma("unroll")                                                       \
        for (int j = 0; j < 4; j++) {                                           \
            int r_ = rbase + 32 * j;                                            \
            cp16(st_ + ATB + (uint32_t)r_ * ROWB + qo, (Bp) + (size_t)r_ * 1024 + (k0) + qh); \
        }                                                                       \
        cpcommit();                                                             \
    } while (0)

// ---------------------------------------------------------------------------
// gemm_gu: out[s] = X @ W[s]^T, s<8 -> Wg[e], s>=8 -> Wu[e-8]
// grid (I/128=8, BT/256=32, 16)
// ---------------------------------------------------------------------------
__global__ __launch_bounds__(256) void gemm_gu_kernel()
{
    extern __shared__ char smem[];
    const uint32_t sb = (uint32_t)__cvta_generic_to_shared(smem);

    const int s4 = blockIdx.z;
    const int m0 = blockIdx.y * 256;
    const int n0 = blockIdx.x * 128;

    const __half* Ap = g_xq + (size_t)m0 * D_;
    const __half* Bp = (s4 < 8 ? g_gq + ((size_t)s4 * I_ + n0) * D_
                               : g_uq + ((size_t)(s4 - 8) * I_ + n0) * D_);
    __half* Op = g_guq + (size_t)s4 * BT_ * I_;

    const int tid = threadIdx.x;
    const int rbase = tid >> 3;
    const uint32_t qo = (uint32_t)(tid & 7) * 16;
    const int qh = (tid & 7) * 8;
    const Frag f = mk_frag(tid);

    float acc[4][8][4];
#pragma unroll
    for (int mt = 0; mt < 4; mt++)
#pragma unroll
        for (int nt = 0; nt < 8; nt++)
#pragma unroll
            for (int i = 0; i < 4; i++) acc[mt][nt][i] = 0.0f;

    const int NS = D_ / KT;   // 16
    ISSUE_STAGE(0, Ap, Bp, 0);
    ISSUE_STAGE(1, Ap, Bp, KT);

#pragma unroll 1
    for (int st = 0; st < NS; st++) {
        cpwait1();
        __syncthreads();
        if (st + 2 < NS) ISSUE_STAGE((st + 2) % 3, Ap, Bp, (st + 2) * KT);
        else cpcommit();
        stage_mma(sb + (uint32_t)(st % 3) * STGB, f, acc);
    }

#pragma unroll
    for (int mt = 0; mt < 4; mt++) {
        int r0 = m0 + f.wm * 64 + mt * 16 + f.g;
#pragma unroll
        for (int nt = 0; nt < 8; nt++) {
            int c0 = n0 + f.wn * 64 + nt * 8 + f.tg * 2;
            *(__half2*)(Op + (size_t)r0 * I_ + c0)       = __floats2half2_rn(acc[mt][nt][0], acc[mt][nt][1]);
            *(__half2*)(Op + (size_t)(r0 + 8) * I_ + c0) = __floats2half2_rn(acc[mt][nt][2], acc[mt][nt][3]);
        }
    }
}

// ---------------------------------------------------------------------------
// silumul: h'[e][t][i] = w[t][e] * silu(gate) * up
// ---------------------------------------------------------------------------
__global__ __launch_bounds__(256) void silumul_kernel()
{
    int row = blockIdx.x;            // row = e*BT + t
    int e = row >> 13, t = row & (BT_ - 1);
    float w = g_w[t * E_ + e];
    const __half* gp = g_guq + (size_t)row * I_;
    const __half* up = g_guq + ((size_t)(e + 8) * BT_ + t) * I_;
    __half* hp = g_hq + (size_t)row * I_;

    int i = threadIdx.x * 4;
    __half2 gv0 = *(const __half2*)(gp + i), gv1 = *(const __half2*)(gp + i + 2);
    __half2 uv0 = *(const __half2*)(up + i), uv1 = *(const __half2*)(up + i + 2);
    float g0 = __half2float(gv0.x), g1 = __half2float(gv0.y);
    float g2 = __half2float(gv1.x), g3 = __half2float(gv1.y);
    float u0 = __half2float(uv0.x), u1 = __half2float(uv0.y);
    float u2 = __half2float(uv1.x), u3 = __half2float(uv1.y);
    *(__half2*)(hp + i)     = __floats2half2_rn(w * siluf(g0) * u0, w * siluf(g1) * u1);
    *(__half2*)(hp + i + 2) = __floats2half2_rn(w * siluf(g2) * u2, w * siluf(g3) * u3);
}

// ---------------------------------------------------------------------------
// gemm_d: out = sum_e h'[e] @ Wd[e]^T — 128 continuous stages
// grid (D/128=8, BT/256=32)
// ---------------------------------------------------------------------------
__global__ __launch_bounds__(256) void gemm_d_kernel(float* __restrict__ out)
{
    extern __shared__ char smem[];
    const uint32_t sb = (uint32_t)__cvta_generic_to_shared(smem);

    const int m0 = blockIdx.y * 256;
    const int n0 = blockIdx.x * 128;

    const int tid = threadIdx.x;
    const int rbase = tid >> 3;
    const uint32_t qo = (uint32_t)(tid & 7) * 16;
    const int qh = (tid & 7) * 8;
    const Frag f = mk_frag(tid);

    float acc[4][8][4];
#pragma unroll
    for (int mt = 0; mt < 4; mt++)
#pragma unroll
        for (int nt = 0; nt < 8; nt++)
#pragma unroll
            for (int i = 0; i < 4; i++) acc[mt][nt][i] = 0.0f;

    const int NS = E_ * (I_ / KT);   // 128
    {
        const __half* Ap = g_hq + (size_t)m0 * I_;
        const __half* Bp = g_dq + (size_t)n0 * I_;
        ISSUE_STAGE(0, Ap, Bp, 0);
        ISSUE_STAGE(1, Ap, Bp, KT);
    }

#pragma unroll 1
    for (int st = 0; st < NS; st++) {
        cpwait1();
        __syncthreads();
        if (st + 2 < NS) {
            int e2 = (st + 2) >> 4, k2 = ((st + 2) & 15) * KT;
            const __half* Ap = g_hq + ((size_t)e2 * BT_ + m0) * I_;
            const __half* Bp = g_dq + ((size_t)e2 * D_ + n0) * I_;
            ISSUE_STAGE((st + 2) % 3, Ap, Bp, k2);
        } else cpcommit();
        stage_mma(sb + (uint32_t)(st % 3) * STGB, f, acc);
    }

#pragma unroll
    for (int mt = 0; mt < 4; mt++) {
        int r0 = m0 + f.wm * 64 + mt * 16 + f.g;
#pragma unroll
        for (int nt = 0; nt < 8; nt++) {
            int c0 = n0 + f.wn * 64 + nt * 8 + f.tg * 2;
            *(float2*)(out + (size_t)r0 * D_ + c0)       = make_float2(acc[mt][nt][0], acc[mt][nt][1]);
            *(float2*)(out + (size_t)(r0 + 8) * D_ + c0) = make_float2(acc[mt][nt][2], acc[mt][nt][3]);
        }
    }
}

// ---------------------------------------------------------------------------
// launch
// ---------------------------------------------------------------------------
extern "C" void kernel_launch(void* const* d_in, const int* in_sizes, int n_in,
                              void* d_out, int out_size)
{
    const float* x    = (const float*)d_in[0];
    const float* Wg   = (const float*)d_in[1];
    const float* Wu   = (const float*)d_in[2];
    const float* Wd   = (const float*)d_in[3];
    const float* Wr   = (const float*)d_in[4];
    const float* temp = (const float*)d_in[5];
    float* out = (float*)d_out;

    cudaFuncSetAttribute(gemm_gu_kernel, cudaFuncAttributeMaxDynamicSharedMemorySize, NSTG * STGB);
    cudaFuncSetAttribute(gemm_d_kernel,  cudaFuncAttributeMaxDynamicSharedMemorySize, NSTG * STGB);

    __half *gq, *uq, *dq;
    cudaGetSymbolAddress((void**)&gq, g_gq);
    cudaGetSymbolAddress((void**)&uq, g_uq);
    cudaGetSymbolAddress((void**)&dq, g_dq);

    routing_kernel<<<BT_ / 8, 256>>>(x, Wr, temp);
    convx_kernel<<<BT_ * D_ / 1024, 256>>>(x);

    dim3 gt(32, 32, E_), bt(32, 8);
    convT_kernel<<<gt, bt>>>(Wg, gq);
    convT_kernel<<<gt, bt>>>(Wu, uq);
    convT_kernel<<<gt, bt>>>(Wd, dq);

    dim3 gGU(I_ / 128, BT_ / 256, 2 * E_);
    gemm_gu_kernel<<<gGU, 256, NSTG * STGB>>>();

    silumul_kernel<<<E_ * BT_, 256>>>();

    dim3 gD(D_ / 128, BT_ / 256);
    gemm_d_kernel<<<gD, 256, NSTG * STGB>>>(out);
}

// round 11
// speedup vs baseline: 10.7583x; 1.1358x over previous
#include <cuda_runtime.h>
#include <cuda_fp16.h>
#include <cstdint>
#include <cstddef>

// Problem dims: B=4, T=2048 -> BT=8192 tokens, D=1024, E=8, I=1024
#define BT_ 8192
#define D_  1024
#define E_  8
#define I_  1024

#define GOLDEN_CENTER 0.36787944117144233f
#define GOLDEN_LOWER  0.21231792754821915f
#define GOLDEN_UPPER  0.5f

// ---------------------------------------------------------------------------
// Device scratch (static; no runtime allocation)
// ---------------------------------------------------------------------------
__device__ __half g_xq[BT_ * D_];                      // x fp16 [t][d]
__device__ __half g_gq[E_ * D_ * I_];                  // Wg^T fp16 [e][i][d]
__device__ __half g_uq[E_ * D_ * I_];                  // Wu^T fp16 [e][i][d]
__device__ __half g_dq[E_ * D_ * I_];                  // Wd^T fp16 [e][d][i]
__device__ __half g_guq[(size_t)2 * E_ * BT_ * I_];    // gate|up fp16 [s][t][i]
__device__ __half g_hq[(size_t)E_ * BT_ * I_];         // h' = w*silu(g)*u fp16
__device__ float  g_w[BT_ * E_];                       // routing weights

// ---------------------------------------------------------------------------
// helpers
// ---------------------------------------------------------------------------
__device__ __forceinline__ void hmma16(float c[4], const uint32_t a[4], const uint32_t b[2]) {
    asm volatile(
        "mma.sync.aligned.m16n8k16.row.col.f32.f16.f16.f32 "
        "{%0,%1,%2,%3},{%4,%5,%6,%7},{%8,%9},{%0,%1,%2,%3};\n"
        : "+f"(c[0]), "+f"(c[1]), "+f"(c[2]), "+f"(c[3])
        : "r"(a[0]), "r"(a[1]), "r"(a[2]), "r"(a[3]), "r"(b[0]), "r"(b[1]));
}
__device__ __forceinline__ void ldsm4(uint32_t r[4], uint32_t addr) {
    asm volatile("ldmatrix.sync.aligned.m8n8.x4.shared.b16 {%0,%1,%2,%3}, [%4];"
        : "=r"(r[0]), "=r"(r[1]), "=r"(r[2]), "=r"(r[3]) : "r"(addr));
}
__device__ __forceinline__ void cp16(uint32_t dst, const void* src) {
    asm volatile("cp.async.cg.shared.global [%0], [%1], 16;\n" :: "r"(dst), "l"(src) : "memory");
}
__device__ __forceinline__ void cpcommit() { asm volatile("cp.async.commit_group;\n" ::: "memory"); }
__device__ __forceinline__ void cpwait1()  { asm volatile("cp.async.wait_group 1;\n" ::: "memory"); }
__device__ __forceinline__ float siluf(float v) { return v / (1.0f + expf(-v)); }

// smem rows: 128 data bytes + 16 pad = 144B; conflict-free for ldmatrix
#define ROWB   144u
#define KT     64        // K halfs per stage (128 bytes)
// gemm_gu: CTA 256x128
#define ATB    36864u    // A tile: 256 rows * 144B
#define STGB   55296u
#define NSTG   3u
// gemm_d: CTA 64x128
#define ATB64  9216u     // A tile: 64 rows * 144B
#define STGB64 27648u

// ---------------------------------------------------------------------------
// Routing weights: fp32 twoProd-FMA + Neumaier compensated accumulation.
// One warp per token. Numerically ~1e-7 from the fp64 version.
// ---------------------------------------------------------------------------
__global__ __launch_bounds__(256) void routing_kernel(
    const float* __restrict__ x, const float* __restrict__ Wr,
    const float* __restrict__ temp)
{
    int warp = threadIdx.x >> 5;
    int lane = threadIdx.x & 31;
    int t = blockIdx.x * 8 + warp;

    const float* xr = x + (size_t)t * D_;
    float s[E_], c[E_];
#pragma unroll
    for (int e = 0; e < E_; e++) { s[e] = 0.0f; c[e] = 0.0f; }

#pragma unroll 4
    for (int d0 = lane; d0 < D_; d0 += 32) {
        float xv = __ldg(xr + d0);
        float4 wa = *(const float4*)(Wr + d0 * E_);
        float4 wb = *(const float4*)(Wr + d0 * E_ + 4);
        float wv[E_] = {wa.x, wa.y, wa.z, wa.w, wb.x, wb.y, wb.z, wb.w};
#pragma unroll
        for (int e = 0; e < E_; e++) {
            float p   = xv * wv[e];
            float err = fmaf(xv, wv[e], -p);          // exact product residual
            float tt  = s[e] + p;                      // Neumaier add
            float e1  = (fabsf(s[e]) >= fabsf(p)) ? ((s[e] - tt) + p)
                                                  : ((p - tt) + s[e]);
            s[e] = tt;
            c[e] += e1 + err;
        }
    }
    // compensated warp reduction
#pragma unroll
    for (int off = 16; off > 0; off >>= 1) {
#pragma unroll
        for (int e = 0; e < E_; e++) {
            float s2 = __shfl_down_sync(0xffffffffu, s[e], off);
            float c2 = __shfl_down_sync(0xffffffffu, c[e], off);
            float tt = s[e] + s2;
            float e1 = (fabsf(s[e]) >= fabsf(s2)) ? ((s[e] - tt) + s2)
                                                  : ((s2 - tt) + s[e]);
            s[e] = tt;
            c[e] += c2 + e1;
        }
    }

    if (lane == 0) {
        float T = temp[0];
        float dist[E_], wv[E_];
        float wsum = 0.0f;
#pragma unroll
        for (int e = 0; e < E_; e++) {
            float z = (s[e] + c[e]) / T;
            float inh = 1.0f / (1.0f + expf(-z));
            dist[e] = fabsf(inh - GOLDEN_CENTER);
            bool zone = (inh >= GOLDEN_LOWER) && (inh <= GOLDEN_UPPER);
            wv[e] = zone ? expf(-dist[e] / 0.1f) : 0.0f;
            wsum += wv[e];
        }
        if (wsum < 1e-8f) {
            float fb[E_];
#pragma unroll
            for (int e = 0; e < E_; e++) fb[e] = expf(-dist[e] / 0.3f);
            int i1 = 0;
#pragma unroll
            for (int e = 1; e < E_; e++) if (fb[e] > fb[i1]) i1 = e;
            int i2 = (i1 == 0) ? 1 : 0;
#pragma unroll
            for (int e = 0; e < E_; e++)
                if (e != i1 && fb[e] > fb[i2]) i2 = e;
            float sc = fmaxf(fb[i1] + fb[i2], 1e-8f);
#pragma unroll
            for (int e = 0; e < E_; e++)
                wv[e] = (e == i1 || e == i2) ? fb[e] / sc : 0.0f;
        }
        float s2 = 0.0f;
#pragma unroll
        for (int e = 0; e < E_; e++) s2 += wv[e];
        float inv = 1.0f / fmaxf(s2, 1e-8f);
#pragma unroll
        for (int e = 0; e < E_; e++) g_w[t * E_ + e] = wv[e] * inv;
    }
}

// ---------------------------------------------------------------------------
// convert x -> fp16
// ---------------------------------------------------------------------------
__global__ __launch_bounds__(256) void convx_kernel(const float* __restrict__ x)
{
    int i = (blockIdx.x * 256 + threadIdx.x) * 4;
    float4 v = *(const float4*)(x + i);
    *(__half2*)(g_xq + i)     = __floats2half2_rn(v.x, v.y);
    *(__half2*)(g_xq + i + 2) = __floats2half2_rn(v.z, v.w);
}

// ---------------------------------------------------------------------------
// transpose + fp16: out[e][c][r] = half(in[e][r][c])
// ---------------------------------------------------------------------------
__global__ void convT_kernel(const float* __restrict__ in, __half* __restrict__ oq)
{
    __shared__ float t[32][33];
    int e = blockIdx.z;
    const float* ip = in + ((size_t)e << 20);
    __half* op = oq + ((size_t)e << 20);
    int r0 = blockIdx.y * 32, c0 = blockIdx.x * 32;
    int tx = threadIdx.x, ty = threadIdx.y;

#pragma unroll
    for (int j = ty; j < 32; j += 8)
        t[j][tx] = ip[(size_t)(r0 + j) * 1024 + c0 + tx];
    __syncthreads();
#pragma unroll
    for (int j = ty; j < 32; j += 8)
        op[(size_t)(c0 + j) * 1024 + r0 + tx] = __float2half_rn(t[tx][j]);
}

// ---------------------------------------------------------------------------
// gemm_gu geometry: CTA 256m x 128n, 8 warps (4m x 2n), warp 64x64
// ---------------------------------------------------------------------------
struct Frag { uint32_t aoffL, boffL, aro, bro; int wm, wn, g, tg; };

__device__ __forceinline__ Frag mk_frag(int tid) {
    Frag f;
    int lane = tid & 31, warp = tid >> 5;
    f.wm = warp & 3; f.wn = warp >> 2;
    f.g = lane >> 2; f.tg = lane & 3;
    f.aoffL = (uint32_t)((lane & 7) + ((lane >> 3) & 1) * 8) * ROWB + (lane >> 4) * 16;
    f.boffL = (uint32_t)((lane & 7) + (lane >> 4) * 8) * ROWB + ((lane >> 3) & 1) * 16;
    f.aro = (uint32_t)(f.wm * 64) * ROWB;
    f.bro = ATB + (uint32_t)(f.wn * 64) * ROWB;
    return f;
}

__device__ __forceinline__ void stage_mma(uint32_t st, const Frag& f, float acc[4][8][4]) {
#pragma unroll
    for (int ks = 0; ks < 4; ks++) {
        const uint32_t kb = (uint32_t)ks * 32u;
        uint32_t af[4][4];
#pragma unroll
        for (int mt = 0; mt < 4; mt++)
            ldsm4(af[mt], st + f.aro + (uint32_t)(mt * 16) * ROWB + f.aoffL + kb);
        uint32_t bf[4][4];
#pragma unroll
        for (int p = 0; p < 4; p++)
            ldsm4(bf[p], st + f.bro + (uint32_t)(p * 16) * ROWB + f.boffL + kb);
#pragma unroll
        for (int mt = 0; mt < 4; mt++)
#pragma unroll
            for (int p = 0; p < 4; p++)
#pragma unroll
                for (int q = 0; q < 2; q++)
                    hmma16(acc[mt][2 * p + q], af[mt], &bf[p][2 * q]);
    }
}

#define ISSUE_STAGE(buf, Ap, Bp, k0) do {                                       \
        uint32_t st_ = sb + (uint32_t)(buf) * STGB;                             \
        _Pragma("unroll")                                                       \
        for (int j = 0; j < 8; j++) {                                           \
            int r_ = rbase + 32 * j;                                            \
            cp16(st_ + (uint32_t)r_ * ROWB + qo, (Ap) + (size_t)r_ * 1024 + (k0) + qh); \
        }                                                                       \
        _Pragma("unroll")                                                       \
        for (int j = 0; j < 4; j++) {                                           \
            int r_ = rbase + 32 * j;                                            \
            cp16(st_ + ATB + (uint32_t)r_ * ROWB + qo, (Bp) + (size_t)r_ * 1024 + (k0) + qh); \
        }                                                                       \
        cpcommit();                                                             \
    } while (0)

// ---------------------------------------------------------------------------
// gemm_gu: out[s] = X @ W[s]^T, s<8 -> Wg[e], s>=8 -> Wu[e-8]
// grid (I/128=8, BT/256=32, 16)
// ---------------------------------------------------------------------------
__global__ __launch_bounds__(256) void gemm_gu_kernel()
{
    extern __shared__ char smem[];
    const uint32_t sb = (uint32_t)__cvta_generic_to_shared(smem);

    const int s4 = blockIdx.z;
    const int m0 = blockIdx.y * 256;
    const int n0 = blockIdx.x * 128;

    const __half* Ap = g_xq + (size_t)m0 * D_;
    const __half* Bp = (s4 < 8 ? g_gq + ((size_t)s4 * I_ + n0) * D_
                               : g_uq + ((size_t)(s4 - 8) * I_ + n0) * D_);
    __half* Op = g_guq + (size_t)s4 * BT_ * I_;

    const int tid = threadIdx.x;
    const int rbase = tid >> 3;
    const uint32_t qo = (uint32_t)(tid & 7) * 16;
    const int qh = (tid & 7) * 8;
    const Frag f = mk_frag(tid);

    float acc[4][8][4];
#pragma unroll
    for (int mt = 0; mt < 4; mt++)
#pragma unroll
        for (int nt = 0; nt < 8; nt++)
#pragma unroll
            for (int i = 0; i < 4; i++) acc[mt][nt][i] = 0.0f;

    const int NS = D_ / KT;   // 16
    ISSUE_STAGE(0, Ap, Bp, 0);
    ISSUE_STAGE(1, Ap, Bp, KT);

#pragma unroll 1
    for (int st = 0; st < NS; st++) {
        cpwait1();
        __syncthreads();
        if (st + 2 < NS) ISSUE_STAGE((st + 2) % 3, Ap, Bp, (st + 2) * KT);
        else cpcommit();
        stage_mma(sb + (uint32_t)(st % 3) * STGB, f, acc);
    }

#pragma unroll
    for (int mt = 0; mt < 4; mt++) {
        int r0 = m0 + f.wm * 64 + mt * 16 + f.g;
#pragma unroll
        for (int nt = 0; nt < 8; nt++) {
            int c0 = n0 + f.wn * 64 + nt * 8 + f.tg * 2;
            *(__half2*)(Op + (size_t)r0 * I_ + c0)       = __floats2half2_rn(acc[mt][nt][0], acc[mt][nt][1]);
            *(__half2*)(Op + (size_t)(r0 + 8) * I_ + c0) = __floats2half2_rn(acc[mt][nt][2], acc[mt][nt][3]);
        }
    }
}

// ---------------------------------------------------------------------------
// silumul: h'[e][t][i] = w[t][e] * silu(gate) * up
// ---------------------------------------------------------------------------
__global__ __launch_bounds__(256) void silumul_kernel()
{
    int row = blockIdx.x;            // row = e*BT + t
    int e = row >> 13, t = row & (BT_ - 1);
    float w = g_w[t * E_ + e];
    const __half* gp = g_guq + (size_t)row * I_;
    const __half* up = g_guq + ((size_t)(e + 8) * BT_ + t) * I_;
    __half* hp = g_hq + (size_t)row * I_;

    int i = threadIdx.x * 4;
    __half2 gv0 = *(const __half2*)(gp + i), gv1 = *(const __half2*)(gp + i + 2);
    __half2 uv0 = *(const __half2*)(up + i), uv1 = *(const __half2*)(up + i + 2);
    float g0 = __half2float(gv0.x), g1 = __half2float(gv0.y);
    float g2 = __half2float(gv1.x), g3 = __half2float(gv1.y);
    float u0 = __half2float(uv0.x), u1 = __half2float(uv0.y);
    float u2 = __half2float(uv1.x), u3 = __half2float(uv1.y);
    *(__half2*)(hp + i)     = __floats2half2_rn(w * siluf(g0) * u0, w * siluf(g1) * u1);
    *(__half2*)(hp + i + 2) = __floats2half2_rn(w * siluf(g2) * u2, w * siluf(g3) * u3);
}

// ---------------------------------------------------------------------------
// gemm_d: out = sum_e h'[e] @ Wd[e]^T — CTA 64m x 128n, 8 warps (2m x 4n),
// warp 32x32, 3-stage ring, 128 continuous K-stages. grid (8, 128).
// 1024 CTAs -> ~7 full waves (vs 1.73 before): kills the tail waste.
// ---------------------------------------------------------------------------
__global__ __launch_bounds__(256) void gemm_d_kernel(float* __restrict__ out)
{
    extern __shared__ char smem[];
    const uint32_t sb = (uint32_t)__cvta_generic_to_shared(smem);

    const int m0 = blockIdx.y * 64;
    const int n0 = blockIdx.x * 128;

    const int tid = threadIdx.x, lane = tid & 31, warp = tid >> 5;
    const int wm = warp & 1, wn = warp >> 1;
    const int g = lane >> 2, tg = lane & 3;
    const int rbase = tid >> 3;
    const uint32_t qo = (uint32_t)(tid & 7) * 16;
    const int qh = (tid & 7) * 8;

    const uint32_t aoffL = (uint32_t)((lane & 7) + ((lane >> 3) & 1) * 8) * ROWB + (lane >> 4) * 16;
    const uint32_t boffL = (uint32_t)((lane & 7) + (lane >> 4) * 8) * ROWB + ((lane >> 3) & 1) * 16;
    const uint32_t aro = (uint32_t)(wm * 32) * ROWB;
    const uint32_t bro = ATB64 + (uint32_t)(wn * 32) * ROWB;

    float acc[2][4][4];
#pragma unroll
    for (int mt = 0; mt < 2; mt++)
#pragma unroll
        for (int nt = 0; nt < 4; nt++)
#pragma unroll
            for (int i = 0; i < 4; i++) acc[mt][nt][i] = 0.0f;

#define ISSUE_D(buf, Ap, Bp, k0) do {                                           \
        uint32_t st_ = sb + (uint32_t)(buf) * STGB64;                           \
        _Pragma("unroll")                                                       \
        for (int j = 0; j < 2; j++) {                                           \
            int r_ = rbase + 32 * j;                                            \
            cp16(st_ + (uint32_t)r_ * ROWB + qo, (Ap) + (size_t)r_ * 1024 + (k0) + qh); \
        }                                                                       \
        _Pragma("unroll")                                                       \
        for (int j = 0; j < 4; j++) {                                           \
            int r_ = rbase + 32 * j;                                            \
            cp16(st_ + ATB64 + (uint32_t)r_ * ROWB + qo, (Bp) + (size_t)r_ * 1024 + (k0) + qh); \
        }                                                                       \
        cpcommit();                                                             \
    } while (0)

    const int NS = E_ * (I_ / KT);   // 128
    {
        const __half* Ap = g_hq + (size_t)m0 * I_;
        const __half* Bp = g_dq + (size_t)n0 * I_;
        ISSUE_D(0, Ap, Bp, 0);
        ISSUE_D(1, Ap, Bp, KT);
    }

#pragma unroll 1
    for (int st = 0; st < NS; st++) {
        cpwait1();
        __syncthreads();
        if (st + 2 < NS) {
            int e2 = (st + 2) >> 4, k2 = ((st + 2) & 15) * KT;
            const __half* Ap = g_hq + ((size_t)e2 * BT_ + m0) * I_;
            const __half* Bp = g_dq + ((size_t)e2 * D_ + n0) * I_;
            ISSUE_D((st + 2) % 3, Ap, Bp, k2);
        } else cpcommit();

        const uint32_t stb = sb + (uint32_t)(st % 3) * STGB64;
#pragma unroll
        for (int ks = 0; ks < 4; ks++) {
            const uint32_t kb = (uint32_t)ks * 32u;
            uint32_t af[2][4];
#pragma unroll
            for (int mt = 0; mt < 2; mt++)
                ldsm4(af[mt], stb + aro + (uint32_t)(mt * 16) * ROWB + aoffL + kb);
            uint32_t bf[2][4];
#pragma unroll
            for (int p = 0; p < 2; p++)
                ldsm4(bf[p], stb + bro + (uint32_t)(p * 16) * ROWB + boffL + kb);
#pragma unroll
            for (int mt = 0; mt < 2; mt++)
#pragma unroll
                for (int p = 0; p < 2; p++)
#pragma unroll
                    for (int q = 0; q < 2; q++)
                        hmma16(acc[mt][2 * p + q], af[mt], &bf[p][2 * q]);
        }
    }
#undef ISSUE_D

#pragma unroll
    for (int mt = 0; mt < 2; mt++) {
        int r0 = m0 + wm * 32 + mt * 16 + g;
#pragma unroll
        for (int nt = 0; nt < 4; nt++) {
            int c0 = n0 + wn * 32 + nt * 8 + tg * 2;
            *(float2*)(out + (size_t)r0 * D_ + c0)       = make_float2(acc[mt][nt][0], acc[mt][nt][1]);
            *(float2*)(out + (size_t)(r0 + 8) * D_ + c0) = make_float2(acc[mt][nt][2], acc[mt][nt][3]);
        }
    }
}

// ---------------------------------------------------------------------------
// launch — ordered so the profiler's skip-5 window lands on gemm_gu
// ---------------------------------------------------------------------------
extern "C" void kernel_launch(void* const* d_in, const int* in_sizes, int n_in,
                              void* d_out, int out_size)
{
    const float* x    = (const float*)d_in[0];
    const float* Wg   = (const float*)d_in[1];
    const float* Wu   = (const float*)d_in[2];
    const float* Wd   = (const float*)d_in[3];
    const float* Wr   = (const float*)d_in[4];
    const float* temp = (const float*)d_in[5];
    float* out = (float*)d_out;

    cudaFuncSetAttribute(gemm_gu_kernel, cudaFuncAttributeMaxDynamicSharedMemorySize, NSTG * STGB);
    cudaFuncSetAttribute(gemm_d_kernel,  cudaFuncAttributeMaxDynamicSharedMemorySize, NSTG * STGB64);

    __half *gq, *uq, *dq;
    cudaGetSymbolAddress((void**)&gq, g_gq);
    cudaGetSymbolAddress((void**)&uq, g_uq);
    cudaGetSymbolAddress((void**)&dq, g_dq);

    dim3 gt(32, 32, E_), bt(32, 8);

    convx_kernel<<<BT_ * D_ / 1024, 256>>>(x);          // 1
    convT_kernel<<<gt, bt>>>(Wg, gq);                   // 2
    convT_kernel<<<gt, bt>>>(Wu, uq);                   // 3
    routing_kernel<<<BT_ / 8, 256>>>(x, Wr, temp);      // 4

    dim3 gGU(I_ / 128, BT_ / 256, 2 * E_);
    gemm_gu_kernel<<<gGU, 256, NSTG * STGB>>>();        // 5 <- ncu target

    convT_kernel<<<gt, bt>>>(Wd, dq);                   // 6
    silumul_kernel<<<E_ * BT_, 256>>>();                // 7

    dim3 gD(D_ / 128, BT_ / 64);
    gemm_d_kernel<<<gD, 256, NSTG * STGB64>>>(out);     // 8
}

// round 12
// speedup vs baseline: 10.8708x; 1.0105x over previous
#include <cuda_runtime.h>
#include <cuda_fp16.h>
#include <cstdint>
#include <cstddef>

// Problem dims: B=4, T=2048 -> BT=8192 tokens, D=1024, E=8, I=1024
#define BT_ 8192
#define D_  1024
#define E_  8
#define I_  1024

#define GOLDEN_CENTER 0.36787944117144233f
#define GOLDEN_LOWER  0.21231792754821915f
#define GOLDEN_UPPER  0.5f

// ---------------------------------------------------------------------------
// Device scratch (static; no runtime allocation)
// ---------------------------------------------------------------------------
__device__ __half g_xq[BT_ * D_];                      // x fp16 [t][d]
__device__ __half g_gq[E_ * D_ * I_];                  // Wg^T fp16 [e][i][d]
__device__ __half g_uq[E_ * D_ * I_];                  // Wu^T fp16 [e][i][d]
__device__ __half g_dq[E_ * D_ * I_];                  // Wd^T fp16 [e][d][i]
__device__ __half g_hq[(size_t)E_ * BT_ * I_];         // h' = w*silu(g)*u fp16
__device__ float  g_w[BT_ * E_];                       // routing weights

// ---------------------------------------------------------------------------
// helpers
// ---------------------------------------------------------------------------
__device__ __forceinline__ void hmma16(float c[4], const uint32_t a[4], const uint32_t b[2]) {
    asm volatile(
        "mma.sync.aligned.m16n8k16.row.col.f32.f16.f16.f32 "
        "{%0,%1,%2,%3},{%4,%5,%6,%7},{%8,%9},{%0,%1,%2,%3};\n"
        : "+f"(c[0]), "+f"(c[1]), "+f"(c[2]), "+f"(c[3])
        : "r"(a[0]), "r"(a[1]), "r"(a[2]), "r"(a[3]), "r"(b[0]), "r"(b[1]));
}
__device__ __forceinline__ void ldsm4(uint32_t r[4], uint32_t addr) {
    asm volatile("ldmatrix.sync.aligned.m8n8.x4.shared.b16 {%0,%1,%2,%3}, [%4];"
        : "=r"(r[0]), "=r"(r[1]), "=r"(r[2]), "=r"(r[3]) : "r"(addr));
}
__device__ __forceinline__ void cp16(uint32_t dst, const void* src) {
    asm volatile("cp.async.cg.shared.global [%0], [%1], 16;\n" :: "r"(dst), "l"(src) : "memory");
}
__device__ __forceinline__ void cpcommit() { asm volatile("cp.async.commit_group;\n" ::: "memory"); }
__device__ __forceinline__ void cpwait1()  { asm volatile("cp.async.wait_group 1;\n" ::: "memory"); }
__device__ __forceinline__ float siluf(float v) { return v / (1.0f + expf(-v)); }

// smem rows: 128 data bytes + 16 pad = 144B; conflict-free for ldmatrix
#define ROWB   144u
#define KT     64        // K halfs per stage (128 bytes)
// fused gemm_gu: CTA 128m x 128n, tiles A/G/U each 128 rows
#define TLB    18432u    // 128 rows * 144B
#define STGB   55296u    // 3 tiles per stage
#define NSTG   3u
// gemm_d: CTA 64m x 128n
#define ATB64  9216u     // A tile: 64 rows * 144B
#define STGB64 27648u

// ---------------------------------------------------------------------------
// Routing weights: fp32 twoProd-FMA + Neumaier compensated accumulation.
// ---------------------------------------------------------------------------
__global__ __launch_bounds__(256) void routing_kernel(
    const float* __restrict__ x, const float* __restrict__ Wr,
    const float* __restrict__ temp)
{
    int warp = threadIdx.x >> 5;
    int lane = threadIdx.x & 31;
    int t = blockIdx.x * 8 + warp;

    const float* xr = x + (size_t)t * D_;
    float s[E_], c[E_];
#pragma unroll
    for (int e = 0; e < E_; e++) { s[e] = 0.0f; c[e] = 0.0f; }

#pragma unroll 4
    for (int d0 = lane; d0 < D_; d0 += 32) {
        float xv = __ldg(xr + d0);
        float4 wa = *(const float4*)(Wr + d0 * E_);
        float4 wb = *(const float4*)(Wr + d0 * E_ + 4);
        float wv[E_] = {wa.x, wa.y, wa.z, wa.w, wb.x, wb.y, wb.z, wb.w};
#pragma unroll
        for (int e = 0; e < E_; e++) {
            float p   = xv * wv[e];
            float err = fmaf(xv, wv[e], -p);
            float tt  = s[e] + p;
            float e1  = (fabsf(s[e]) >= fabsf(p)) ? ((s[e] - tt) + p)
                                                  : ((p - tt) + s[e]);
            s[e] = tt;
            c[e] += e1 + err;
        }
    }
#pragma unroll
    for (int off = 16; off > 0; off >>= 1) {
#pragma unroll
        for (int e = 0; e < E_; e++) {
            float s2 = __shfl_down_sync(0xffffffffu, s[e], off);
            float c2 = __shfl_down_sync(0xffffffffu, c[e], off);
            float tt = s[e] + s2;
            float e1 = (fabsf(s[e]) >= fabsf(s2)) ? ((s[e] - tt) + s2)
                                                  : ((s2 - tt) + s[e]);
            s[e] = tt;
            c[e] += c2 + e1;
        }
    }

    if (lane == 0) {
        float T = temp[0];
        float dist[E_], wv[E_];
        float wsum = 0.0f;
#pragma unroll
        for (int e = 0; e < E_; e++) {
            float z = (s[e] + c[e]) / T;
            float inh = 1.0f / (1.0f + expf(-z));
            dist[e] = fabsf(inh - GOLDEN_CENTER);
            bool zone = (inh >= GOLDEN_LOWER) && (inh <= GOLDEN_UPPER);
            wv[e] = zone ? expf(-dist[e] / 0.1f) : 0.0f;
            wsum += wv[e];
        }
        if (wsum < 1e-8f) {
            float fb[E_];
#pragma unroll
            for (int e = 0; e < E_; e++) fb[e] = expf(-dist[e] / 0.3f);
            int i1 = 0;
#pragma unroll
            for (int e = 1; e < E_; e++) if (fb[e] > fb[i1]) i1 = e;
            int i2 = (i1 == 0) ? 1 : 0;
#pragma unroll
            for (int e = 0; e < E_; e++)
                if (e != i1 && fb[e] > fb[i2]) i2 = e;
            float sc = fmaxf(fb[i1] + fb[i2], 1e-8f);
#pragma unroll
            for (int e = 0; e < E_; e++)
                wv[e] = (e == i1 || e == i2) ? fb[e] / sc : 0.0f;
        }
        float s2 = 0.0f;
#pragma unroll
        for (int e = 0; e < E_; e++) s2 += wv[e];
        float inv = 1.0f / fmaxf(s2, 1e-8f);
#pragma unroll
        for (int e = 0; e < E_; e++) g_w[t * E_ + e] = wv[e] * inv;
    }
}

// ---------------------------------------------------------------------------
// convert x -> fp16
// ---------------------------------------------------------------------------
__global__ __launch_bounds__(256) void convx_kernel(const float* __restrict__ x)
{
    int i = (blockIdx.x * 256 + threadIdx.x) * 4;
    float4 v = *(const float4*)(x + i);
    *(__half2*)(g_xq + i)     = __floats2half2_rn(v.x, v.y);
    *(__half2*)(g_xq + i + 2) = __floats2half2_rn(v.z, v.w);
}

// ---------------------------------------------------------------------------
// transpose + fp16: out[e][c][r] = half(in[e][r][c])
// ---------------------------------------------------------------------------
__global__ void convT_kernel(const float* __restrict__ in, __half* __restrict__ oq)
{
    __shared__ float t[32][33];
    int e = blockIdx.z;
    const float* ip = in + ((size_t)e << 20);
    __half* op = oq + ((size_t)e << 20);
    int r0 = blockIdx.y * 32, c0 = blockIdx.x * 32;
    int tx = threadIdx.x, ty = threadIdx.y;

#pragma unroll
    for (int j = ty; j < 32; j += 8)
        t[j][tx] = ip[(size_t)(r0 + j) * 1024 + c0 + tx];
    __syncthreads();
#pragma unroll
    for (int j = ty; j < 32; j += 8)
        op[(size_t)(c0 + j) * 1024 + r0 + tx] = __float2half_rn(t[tx][j]);
}

// ---------------------------------------------------------------------------
// gemm_gu FUSED: h'[e] = w[:,e] * silu(X@Wg_e^T) * (X@Wu_e^T), fp16 out.
// CTA 128m x 128n, 8 warps (2m x 4n), warp 64m x 32n, dual accumulators.
// Per k16 per warp: 8 LDSM -> 32 HMMA. 3-stage cp.async ring.
// grid (I/128=8, BT/128=64, E=8)
// ---------------------------------------------------------------------------
__global__ __launch_bounds__(256) void gemm_gu_kernel()
{
    extern __shared__ char smem[];
    const uint32_t sb = (uint32_t)__cvta_generic_to_shared(smem);

    const int e  = blockIdx.z;
    const int m0 = blockIdx.y * 128;
    const int n0 = blockIdx.x * 128;

    const __half* Ap = g_xq + (size_t)m0 * D_;
    const __half* Gp = g_gq + ((size_t)e * I_ + n0) * D_;
    const __half* Up = g_uq + ((size_t)e * I_ + n0) * D_;

    const int tid = threadIdx.x, lane = tid & 31, warp = tid >> 5;
    const int wm = warp & 1, wn = warp >> 1;
    const int g = lane >> 2, tg = lane & 3;
    const int rbase = tid >> 3;
    const uint32_t qo = (uint32_t)(tid & 7) * 16;
    const int qh = (tid & 7) * 8;

    const uint32_t aoffL = (uint32_t)((lane & 7) + ((lane >> 3) & 1) * 8) * ROWB + (lane >> 4) * 16;
    const uint32_t boffL = (uint32_t)((lane & 7) + (lane >> 4) * 8) * ROWB + ((lane >> 3) & 1) * 16;
    const uint32_t aro  = (uint32_t)(wm * 64) * ROWB;
    const uint32_t broG = TLB  + (uint32_t)(wn * 32) * ROWB;
    const uint32_t broU = 2u * TLB + (uint32_t)(wn * 32) * ROWB;

    float accg[4][4][4], accu[4][4][4];
#pragma unroll
    for (int mt = 0; mt < 4; mt++)
#pragma unroll
        for (int nt = 0; nt < 4; nt++)
#pragma unroll
            for (int i = 0; i < 4; i++) { accg[mt][nt][i] = 0.0f; accu[mt][nt][i] = 0.0f; }

#define ISSUE_GU(buf, k0) do {                                                  \
        uint32_t st_ = sb + (uint32_t)(buf) * STGB;                             \
        _Pragma("unroll")                                                       \
        for (int j = 0; j < 4; j++) {                                           \
            int r_ = rbase + 32 * j;                                            \
            uint32_t o_ = (uint32_t)r_ * ROWB + qo;                             \
            size_t  s_ = (size_t)r_ * 1024 + (k0) + qh;                         \
            cp16(st_ + o_,            Ap + s_);                                 \
            cp16(st_ + TLB + o_,      Gp + s_);                                 \
            cp16(st_ + 2u * TLB + o_, Up + s_);                                 \
        }                                                                       \
        cpcommit();                                                             \
    } while (0)

    const int NS = D_ / KT;   // 16
    ISSUE_GU(0, 0);
    ISSUE_GU(1, KT);

#pragma unroll 1
    for (int st = 0; st < NS; st++) {
        cpwait1();
        __syncthreads();
        if (st + 2 < NS) ISSUE_GU((st + 2) % 3, (st + 2) * KT);
        else cpcommit();

        const uint32_t stb = sb + (uint32_t)(st % 3) * STGB;
#pragma unroll
        for (int ks = 0; ks < 4; ks++) {
            const uint32_t kb = (uint32_t)ks * 32u;
            uint32_t af[4][4];
#pragma unroll
            for (int mt = 0; mt < 4; mt++)
                ldsm4(af[mt], stb + aro + (uint32_t)(mt * 16) * ROWB + aoffL + kb);
            uint32_t gf[2][4], uf[2][4];
#pragma unroll
            for (int p = 0; p < 2; p++) {
                ldsm4(gf[p], stb + broG + (uint32_t)(p * 16) * ROWB + boffL + kb);
                ldsm4(uf[p], stb + broU + (uint32_t)(p * 16) * ROWB + boffL + kb);
            }
#pragma unroll
            for (int mt = 0; mt < 4; mt++)
#pragma unroll
                for (int p = 0; p < 2; p++)
#pragma unroll
                    for (int q = 0; q < 2; q++) {
                        hmma16(accg[mt][2 * p + q], af[mt], &gf[p][2 * q]);
                        hmma16(accu[mt][2 * p + q], af[mt], &uf[p][2 * q]);
                    }
        }
    }
#undef ISSUE_GU

    // epilogue: h' = w * silu(gate) * up  (fp32 accs -> single fp16 rounding)
    __half* H = g_hq + (size_t)e * BT_ * I_;
#pragma unroll
    for (int mt = 0; mt < 4; mt++) {
        int r0 = m0 + wm * 64 + mt * 16 + g;
        float w0 = g_w[r0 * E_ + e];
        float w1 = g_w[(r0 + 8) * E_ + e];
#pragma unroll
        for (int nt = 0; nt < 4; nt++) {
            int c0 = n0 + wn * 32 + nt * 8 + tg * 2;
            float h0 = w0 * siluf(accg[mt][nt][0]) * accu[mt][nt][0];
            float h1 = w0 * siluf(accg[mt][nt][1]) * accu[mt][nt][1];
            float h2 = w1 * siluf(accg[mt][nt][2]) * accu[mt][nt][2];
            float h3 = w1 * siluf(accg[mt][nt][3]) * accu[mt][nt][3];
            *(__half2*)(H + (size_t)r0 * I_ + c0)       = __floats2half2_rn(h0, h1);
            *(__half2*)(H + (size_t)(r0 + 8) * I_ + c0) = __floats2half2_rn(h2, h3);
        }
    }
}

// ---------------------------------------------------------------------------
// gemm_d: out = sum_e h'[e] @ Wd[e]^T — CTA 64m x 128n, 8 warps (2m x 4n),
// warp 32x32, 3-stage ring, 128 continuous K-stages. grid (8, 128).
// ---------------------------------------------------------------------------
__global__ __launch_bounds__(256) void gemm_d_kernel(float* __restrict__ out)
{
    extern __shared__ char smem[];
    const uint32_t sb = (uint32_t)__cvta_generic_to_shared(smem);

    const int m0 = blockIdx.y * 64;
    const int n0 = blockIdx.x * 128;

    const int tid = threadIdx.x, lane = tid & 31, warp = tid >> 5;
    const int wm = warp & 1, wn = warp >> 1;
    const int g = lane >> 2, tg = lane & 3;
    const int rbase = tid >> 3;
    const uint32_t qo = (uint32_t)(tid & 7) * 16;
    const int qh = (tid & 7) * 8;

    const uint32_t aoffL = (uint32_t)((lane & 7) + ((lane >> 3) & 1) * 8) * ROWB + (lane >> 4) * 16;
    const uint32_t boffL = (uint32_t)((lane & 7) + (lane >> 4) * 8) * ROWB + ((lane >> 3) & 1) * 16;
    const uint32_t aro = (uint32_t)(wm * 32) * ROWB;
    const uint32_t bro = ATB64 + (uint32_t)(wn * 32) * ROWB;

    float acc[2][4][4];
#pragma unroll
    for (int mt = 0; mt < 2; mt++)
#pragma unroll
        for (int nt = 0; nt < 4; nt++)
#pragma unroll
            for (int i = 0; i < 4; i++) acc[mt][nt][i] = 0.0f;

#define ISSUE_D(buf, Ap, Bp, k0) do {                                           \
        uint32_t st_ = sb + (uint32_t)(buf) * STGB64;                           \
        _Pragma("unroll")                                                       \
        for (int j = 0; j < 2; j++) {                                           \
            int r_ = rbase + 32 * j;                                            \
            cp16(st_ + (uint32_t)r_ * ROWB + qo, (Ap) + (size_t)r_ * 1024 + (k0) + qh); \
        }                                                                       \
        _Pragma("unroll")                                                       \
        for (int j = 0; j < 4; j++) {                                           \
            int r_ = rbase + 32 * j;                                            \
            cp16(st_ + ATB64 + (uint32_t)r_ * ROWB + qo, (Bp) + (size_t)r_ * 1024 + (k0) + qh); \
        }                                                                       \
        cpcommit();                                                             \
    } while (0)

    const int NS = E_ * (I_ / KT);   // 128
    {
        const __half* Ap = g_hq + (size_t)m0 * I_;
        const __half* Bp = g_dq + (size_t)n0 * I_;
        ISSUE_D(0, Ap, Bp, 0);
        ISSUE_D(1, Ap, Bp, KT);
    }

#pragma unroll 1
    for (int st = 0; st < NS; st++) {
        cpwait1();
        __syncthreads();
        if (st + 2 < NS) {
            int e2 = (st + 2) >> 4, k2 = ((st + 2) & 15) * KT;
            const __half* Ap = g_hq + ((size_t)e2 * BT_ + m0) * I_;
            const __half* Bp = g_dq + ((size_t)e2 * D_ + n0) * I_;
            ISSUE_D((st + 2) % 3, Ap, Bp, k2);
        } else cpcommit();

        const uint32_t stb = sb + (uint32_t)(st % 3) * STGB64;
#pragma unroll
        for (int ks = 0; ks < 4; ks++) {
            const uint32_t kb = (uint32_t)ks * 32u;
            uint32_t af[2][4];
#pragma unroll
            for (int mt = 0; mt < 2; mt++)
                ldsm4(af[mt], stb + aro + (uint32_t)(mt * 16) * ROWB + aoffL + kb);
            uint32_t bf[2][4];
#pragma unroll
            for (int p = 0; p < 2; p++)
                ldsm4(bf[p], stb + bro + (uint32_t)(p * 16) * ROWB + boffL + kb);
#pragma unroll
            for (int mt = 0; mt < 2; mt++)
#pragma unroll
                for (int p = 0; p < 2; p++)
#pragma unroll
                    for (int q = 0; q < 2; q++)
                        hmma16(acc[mt][2 * p + q], af[mt], &bf[p][2 * q]);
        }
    }
#undef ISSUE_D

#pragma unroll
    for (int mt = 0; mt < 2; mt++) {
        int r0 = m0 + wm * 32 + mt * 16 + g;
#pragma unroll
        for (int nt = 0; nt < 4; nt++) {
            int c0 = n0 + wn * 32 + nt * 8 + tg * 2;
            *(float2*)(out + (size_t)r0 * D_ + c0)       = make_float2(acc[mt][nt][0], acc[mt][nt][1]);
            *(float2*)(out + (size_t)(r0 + 8) * D_ + c0) = make_float2(acc[mt][nt][2], acc[mt][nt][3]);
        }
    }
}

// ---------------------------------------------------------------------------
// launch
// ---------------------------------------------------------------------------
extern "C" void kernel_launch(void* const* d_in, const int* in_sizes, int n_in,
                              void* d_out, int out_size)
{
    const float* x    = (const float*)d_in[0];
    const float* Wg   = (const float*)d_in[1];
    const float* Wu   = (const float*)d_in[2];
    const float* Wd   = (const float*)d_in[3];
    const float* Wr   = (const float*)d_in[4];
    const float* temp = (const float*)d_in[5];
    float* out = (float*)d_out;

    cudaFuncSetAttribute(gemm_gu_kernel, cudaFuncAttributeMaxDynamicSharedMemorySize, NSTG * STGB);
    cudaFuncSetAttribute(gemm_d_kernel,  cudaFuncAttributeMaxDynamicSharedMemorySize, NSTG * STGB64);

    __half *gq, *uq, *dq;
    cudaGetSymbolAddress((void**)&gq, g_gq);
    cudaGetSymbolAddress((void**)&uq, g_uq);
    cudaGetSymbolAddress((void**)&dq, g_dq);

    dim3 gt(32, 32, E_), bt(32, 8);

    convx_kernel<<<BT_ * D_ / 1024, 256>>>(x);          // 1
    convT_kernel<<<gt, bt>>>(Wg, gq);                   // 2
    convT_kernel<<<gt, bt>>>(Wu, uq);                   // 3
    routing_kernel<<<BT_ / 8, 256>>>(x, Wr, temp);      // 4

    dim3 gGU(I_ / 128, BT_ / 128, E_);
    gemm_gu_kernel<<<gGU, 256, NSTG * STGB>>>();        // 5 (fused silu*up*w)

    convT_kernel<<<gt, bt>>>(Wd, dq);                   // 6

    dim3 gD(D_ / 128, BT_ / 64);
    gemm_d_kernel<<<gD, 256, NSTG * STGB64>>>(out);     // 7
}

// round 13
// speedup vs baseline: 13.9690x; 1.2850x over previous
#include <cuda_runtime.h>
#include <cuda_fp16.h>
#include <cstdint>
#include <cstddef>

// Problem dims: B=4, T=2048 -> BT=8192 tokens, D=1024, E=8, I=1024
#define BT_ 8192
#define D_  1024
#define E_  8
#define I_  1024

#define GOLDEN_CENTER 0.36787944117144233f
#define GOLDEN_LOWER  0.21231792754821915f
#define GOLDEN_UPPER  0.5f

// ---------------------------------------------------------------------------
// Device scratch (static; no runtime allocation)
// ---------------------------------------------------------------------------
__device__ __half g_xq[BT_ * D_];                      // x fp16 [t][d]
__device__ __half g_gq[E_ * D_ * I_];                  // Wg^T fp16 [e][i][d]
__device__ __half g_uq[E_ * D_ * I_];                  // Wu^T fp16 [e][i][d]
__device__ __half g_dq[E_ * D_ * I_];                  // Wd^T fp16 [e][d][i]
__device__ __half g_hq[(size_t)E_ * BT_ * I_];         // h' compacted fp16 [e][slot][i]
__device__ float  g_w[BT_ * E_];                       // routing weights [t][e]
__device__ float  g_wT[E_ * BT_];                      // routing weights [e][t]
__device__ int    g_tok[E_ * BT_];                     // compacted token ids per expert
__device__ int    g_cnt[E_];                           // active token count per expert
__device__ float  g_part[(size_t)E_ * BT_ * D_];       // per-expert partial out fp32 [e][t][d]

// ---------------------------------------------------------------------------
// helpers
// ---------------------------------------------------------------------------
__device__ __forceinline__ void hmma16(float c[4], const uint32_t a[4], const uint32_t b[2]) {
    asm volatile(
        "mma.sync.aligned.m16n8k16.row.col.f32.f16.f16.f32 "
        "{%0,%1,%2,%3},{%4,%5,%6,%7},{%8,%9},{%0,%1,%2,%3};\n"
        : "+f"(c[0]), "+f"(c[1]), "+f"(c[2]), "+f"(c[3])
        : "r"(a[0]), "r"(a[1]), "r"(a[2]), "r"(a[3]), "r"(b[0]), "r"(b[1]));
}
__device__ __forceinline__ void ldsm4(uint32_t r[4], uint32_t addr) {
    asm volatile("ldmatrix.sync.aligned.m8n8.x4.shared.b16 {%0,%1,%2,%3}, [%4];"
        : "=r"(r[0]), "=r"(r[1]), "=r"(r[2]), "=r"(r[3]) : "r"(addr));
}
__device__ __forceinline__ void cp16(uint32_t dst, const void* src) {
    asm volatile("cp.async.cg.shared.global [%0], [%1], 16;\n" :: "r"(dst), "l"(src) : "memory");
}
__device__ __forceinline__ void cpcommit() { asm volatile("cp.async.commit_group;\n" ::: "memory"); }
__device__ __forceinline__ void cpwait1()  { asm volatile("cp.async.wait_group 1;\n" ::: "memory"); }
__device__ __forceinline__ float siluf(float v) { return v / (1.0f + expf(-v)); }

// smem rows: 128 data bytes + 16 pad = 144B; conflict-free for ldmatrix
#define ROWB   144u
#define KT     64        // K halfs per stage (128 bytes)
// fused gemm_gu: CTA 128m x 128n, tiles A/G/U each 128 rows
#define TLB    18432u    // 128 rows * 144B
#define STGB   55296u    // 3 tiles per stage
#define NSTG   3u
// gemm_d: CTA 64m x 128n
#define ATB64  9216u     // A tile: 64 rows * 144B
#define STGB64 27648u

// ---------------------------------------------------------------------------
// Routing weights: fp32 twoProd-FMA + Neumaier compensated accumulation.
// Writes both [t][e] and [e][t] layouts.
// ---------------------------------------------------------------------------
__global__ __launch_bounds__(256) void routing_kernel(
    const float* __restrict__ x, const float* __restrict__ Wr,
    const float* __restrict__ temp)
{
    int warp = threadIdx.x >> 5;
    int lane = threadIdx.x & 31;
    int t = blockIdx.x * 8 + warp;

    const float* xr = x + (size_t)t * D_;
    float s[E_], c[E_];
#pragma unroll
    for (int e = 0; e < E_; e++) { s[e] = 0.0f; c[e] = 0.0f; }

#pragma unroll 4
    for (int d0 = lane; d0 < D_; d0 += 32) {
        float xv = __ldg(xr + d0);
        float4 wa = *(const float4*)(Wr + d0 * E_);
        float4 wb = *(const float4*)(Wr + d0 * E_ + 4);
        float wv[E_] = {wa.x, wa.y, wa.z, wa.w, wb.x, wb.y, wb.z, wb.w};
#pragma unroll
        for (int e = 0; e < E_; e++) {
            float p   = xv * wv[e];
            float err = fmaf(xv, wv[e], -p);
            float tt  = s[e] + p;
            float e1  = (fabsf(s[e]) >= fabsf(p)) ? ((s[e] - tt) + p)
                                                  : ((p - tt) + s[e]);
            s[e] = tt;
            c[e] += e1 + err;
        }
    }
#pragma unroll
    for (int off = 16; off > 0; off >>= 1) {
#pragma unroll
        for (int e = 0; e < E_; e++) {
            float s2 = __shfl_down_sync(0xffffffffu, s[e], off);
            float c2 = __shfl_down_sync(0xffffffffu, c[e], off);
            float tt = s[e] + s2;
            float e1 = (fabsf(s[e]) >= fabsf(s2)) ? ((s[e] - tt) + s2)
                                                  : ((s2 - tt) + s[e]);
            s[e] = tt;
            c[e] += c2 + e1;
        }
    }

    if (lane == 0) {
        float T = temp[0];
        float dist[E_], wv[E_];
        float wsum = 0.0f;
#pragma unroll
        for (int e = 0; e < E_; e++) {
            float z = (s[e] + c[e]) / T;
            float inh = 1.0f / (1.0f + expf(-z));
            dist[e] = fabsf(inh - GOLDEN_CENTER);
            bool zone = (inh >= GOLDEN_LOWER) && (inh <= GOLDEN_UPPER);
            wv[e] = zone ? expf(-dist[e] / 0.1f) : 0.0f;
            wsum += wv[e];
        }
        if (wsum < 1e-8f) {
            float fb[E_];
#pragma unroll
            for (int e = 0; e < E_; e++) fb[e] = expf(-dist[e] / 0.3f);
            int i1 = 0;
#pragma unroll
            for (int e = 1; e < E_; e++) if (fb[e] > fb[i1]) i1 = e;
            int i2 = (i1 == 0) ? 1 : 0;
#pragma unroll
            for (int e = 0; e < E_; e++)
                if (e != i1 && fb[e] > fb[i2]) i2 = e;
            float sc = fmaxf(fb[i1] + fb[i2], 1e-8f);
#pragma unroll
            for (int e = 0; e < E_; e++)
                wv[e] = (e == i1 || e == i2) ? fb[e] / sc : 0.0f;
        }
        float s2 = 0.0f;
#pragma unroll
        for (int e = 0; e < E_; e++) s2 += wv[e];
        float inv = 1.0f / fmaxf(s2, 1e-8f);
#pragma unroll
        for (int e = 0; e < E_; e++) {
            float w = wv[e] * inv;
            g_w[t * E_ + e]  = w;
            g_wT[e * BT_ + t] = w;
        }
    }
}

// ---------------------------------------------------------------------------
// Deterministic per-expert compaction (ordered by token id; no atomics).
// 8 blocks (one per expert) x 256 threads.
// ---------------------------------------------------------------------------
__global__ __launch_bounds__(256) void compact_kernel()
{
    __shared__ int wsum[8];
    __shared__ int sbase;
    int e = blockIdx.x, tid = threadIdx.x, lane = tid & 31, wid = tid >> 5;
    if (tid == 0) sbase = 0;
    __syncthreads();

#pragma unroll 1
    for (int cch = 0; cch < BT_ / 256; cch++) {
        int t = cch * 256 + tid;
        int a = (g_wT[e * BT_ + t] != 0.0f) ? 1 : 0;
        unsigned m = __ballot_sync(0xffffffffu, a);
        int pos = __popc(m & ((1u << lane) - 1u));
        if (lane == 0) wsum[wid] = __popc(m);
        __syncthreads();
        int wbase = 0;
#pragma unroll
        for (int k = 0; k < 8; k++) if (k < wid) wbase += wsum[k];
        int tot = 0;
#pragma unroll
        for (int k = 0; k < 8; k++) tot += wsum[k];
        int base = sbase;
        __syncthreads();
        if (a) g_tok[e * BT_ + base + wbase + pos] = t;
        if (tid == 0) sbase = base + tot;
        __syncthreads();
    }

    int cnt = sbase;
    int pad = (cnt + 127) & ~127;
    for (int sidx = cnt + tid; sidx < pad; sidx += 256) g_tok[e * BT_ + sidx] = 0;
    if (tid == 0) g_cnt[e] = cnt;
}

// ---------------------------------------------------------------------------
// convert x -> fp16
// ---------------------------------------------------------------------------
__global__ __launch_bounds__(256) void convx_kernel(const float* __restrict__ x)
{
    int i = (blockIdx.x * 256 + threadIdx.x) * 4;
    float4 v = *(const float4*)(x + i);
    *(__half2*)(g_xq + i)     = __floats2half2_rn(v.x, v.y);
    *(__half2*)(g_xq + i + 2) = __floats2half2_rn(v.z, v.w);
}

// ---------------------------------------------------------------------------
// transpose + fp16: out[e][c][r] = half(in[e][r][c])
// ---------------------------------------------------------------------------
__global__ void convT_kernel(const float* __restrict__ in, __half* __restrict__ oq)
{
    __shared__ float t[32][33];
    int e = blockIdx.z;
    const float* ip = in + ((size_t)e << 20);
    __half* op = oq + ((size_t)e << 20);
    int r0 = blockIdx.y * 32, c0 = blockIdx.x * 32;
    int tx = threadIdx.x, ty = threadIdx.y;

#pragma unroll
    for (int j = ty; j < 32; j += 8)
        t[j][tx] = ip[(size_t)(r0 + j) * 1024 + c0 + tx];
    __syncthreads();
#pragma unroll
    for (int j = ty; j < 32; j += 8)
        op[(size_t)(c0 + j) * 1024 + r0 + tx] = __float2half_rn(t[tx][j]);
}

// ---------------------------------------------------------------------------
// gemm_gu FUSED + COMPACT: for expert e, over compacted token slots:
// h'[e][slot] = w[t][e] * silu(x[t]@Wg_e^T) * (x[t]@Wu_e^T), fp16, compacted.
// CTA 128slots x 128n, 8 warps (2m x 4n), dual accumulators. Early-exit if
// m0 >= cnt[e]. grid (I/128=8, BT/128=64, E=8)
// ---------------------------------------------------------------------------
__global__ __launch_bounds__(256) void gemm_gu_kernel()
{
    const int e  = blockIdx.z;
    const int m0 = blockIdx.y * 128;
    const int cnt = __ldg(&g_cnt[e]);
    if (m0 >= cnt) return;

    extern __shared__ char smem[];
    const uint32_t sb = (uint32_t)__cvta_generic_to_shared(smem);
    const int n0 = blockIdx.x * 128;

    const __half* Gp = g_gq + ((size_t)e * I_ + n0) * D_;
    const __half* Up = g_uq + ((size_t)e * I_ + n0) * D_;

    const int tid = threadIdx.x, lane = tid & 31, warp = tid >> 5;
    const int wm = warp & 1, wn = warp >> 1;
    const int g = lane >> 2, tg = lane & 3;
    const int rbase = tid >> 3;
    const uint32_t qo = (uint32_t)(tid & 7) * 16;
    const int qh = (tid & 7) * 8;

    // token-row pointers for the 4 A rows this thread stages
    const __half* arow[4];
#pragma unroll
    for (int j = 0; j < 4; j++) {
        int tk = __ldg(&g_tok[e * BT_ + m0 + rbase + 32 * j]);
        arow[j] = g_xq + (size_t)tk * D_;
    }

    const uint32_t aoffL = (uint32_t)((lane & 7) + ((lane >> 3) & 1) * 8) * ROWB + (lane >> 4) * 16;
    const uint32_t boffL = (uint32_t)((lane & 7) + (lane >> 4) * 8) * ROWB + ((lane >> 3) & 1) * 16;
    const uint32_t aro  = (uint32_t)(wm * 64) * ROWB;
    const uint32_t broG = TLB  + (uint32_t)(wn * 32) * ROWB;
    const uint32_t broU = 2u * TLB + (uint32_t)(wn * 32) * ROWB;

    float accg[4][4][4], accu[4][4][4];
#pragma unroll
    for (int mt = 0; mt < 4; mt++)
#pragma unroll
        for (int nt = 0; nt < 4; nt++)
#pragma unroll
            for (int i = 0; i < 4; i++) { accg[mt][nt][i] = 0.0f; accu[mt][nt][i] = 0.0f; }

#define ISSUE_GU(buf, k0) do {                                                  \
        uint32_t st_ = sb + (uint32_t)(buf) * STGB;                             \
        _Pragma("unroll")                                                       \
        for (int j = 0; j < 4; j++) {                                           \
            int r_ = rbase + 32 * j;                                            \
            uint32_t o_ = (uint32_t)r_ * ROWB + qo;                             \
            size_t  ws_ = (size_t)r_ * 1024 + (k0) + qh;                        \
            cp16(st_ + o_,            arow[j] + (k0) + qh);                     \
            cp16(st_ + TLB + o_,      Gp + ws_);                                \
            cp16(st_ + 2u * TLB + o_, Up + ws_);                                \
        }                                                                       \
        cpcommit();                                                             \
    } while (0)

    const int NS = D_ / KT;   // 16
    ISSUE_GU(0, 0);
    ISSUE_GU(1, KT);

#pragma unroll 1
    for (int st = 0; st < NS; st++) {
        cpwait1();
        __syncthreads();
        if (st + 2 < NS) ISSUE_GU((st + 2) % 3, (st + 2) * KT);
        else cpcommit();

        const uint32_t stb = sb + (uint32_t)(st % 3) * STGB;
#pragma unroll
        for (int ks = 0; ks < 4; ks++) {
            const uint32_t kb = (uint32_t)ks * 32u;
            uint32_t af[4][4];
#pragma unroll
            for (int mt = 0; mt < 4; mt++)
                ldsm4(af[mt], stb + aro + (uint32_t)(mt * 16) * ROWB + aoffL + kb);
            uint32_t gf[2][4], uf[2][4];
#pragma unroll
            for (int p = 0; p < 2; p++) {
                ldsm4(gf[p], stb + broG + (uint32_t)(p * 16) * ROWB + boffL + kb);
                ldsm4(uf[p], stb + broU + (uint32_t)(p * 16) * ROWB + boffL + kb);
            }
#pragma unroll
            for (int mt = 0; mt < 4; mt++)
#pragma unroll
                for (int p = 0; p < 2; p++)
#pragma unroll
                    for (int q = 0; q < 2; q++) {
                        hmma16(accg[mt][2 * p + q], af[mt], &gf[p][2 * q]);
                        hmma16(accu[mt][2 * p + q], af[mt], &uf[p][2 * q]);
                    }
        }
    }
#undef ISSUE_GU

    // epilogue: h'(compact slot) = w * silu(gate) * up
    __half* H = g_hq + (size_t)e * BT_ * I_;
#pragma unroll
    for (int mt = 0; mt < 4; mt++) {
        int r0 = m0 + wm * 64 + mt * 16 + g;
        int t0 = __ldg(&g_tok[e * BT_ + r0]);
        int t1 = __ldg(&g_tok[e * BT_ + r0 + 8]);
        float w0 = g_w[t0 * E_ + e];
        float w1 = g_w[t1 * E_ + e];
#pragma unroll
        for (int nt = 0; nt < 4; nt++) {
            int c0 = n0 + wn * 32 + nt * 8 + tg * 2;
            float h0 = w0 * siluf(accg[mt][nt][0]) * accu[mt][nt][0];
            float h1 = w0 * siluf(accg[mt][nt][1]) * accu[mt][nt][1];
            float h2 = w1 * siluf(accg[mt][nt][2]) * accu[mt][nt][2];
            float h3 = w1 * siluf(accg[mt][nt][3]) * accu[mt][nt][3];
            *(__half2*)(H + (size_t)r0 * I_ + c0)       = __floats2half2_rn(h0, h1);
            *(__half2*)(H + (size_t)(r0 + 8) * I_ + c0) = __floats2half2_rn(h2, h3);
        }
    }
}

// ---------------------------------------------------------------------------
// gemm_d COMPACT: per expert, part[e][t] = h'[e][slot] @ Wd[e]^T, fp32,
// scattered to token rows, masked by slot < cnt. CTA 64slots x 128n,
// 8 warps (2m x 4n), 3-stage ring, K=1024. grid (8, 128, 8), early-exit.
// ---------------------------------------------------------------------------
__global__ __launch_bounds__(256) void gemm_d_kernel()
{
    const int e  = blockIdx.z;
    const int m0 = blockIdx.y * 64;
    const int cnt = __ldg(&g_cnt[e]);
    if (m0 >= cnt) return;

    extern __shared__ char smem[];
    const uint32_t sb = (uint32_t)__cvta_generic_to_shared(smem);
    const int n0 = blockIdx.x * 128;

    const __half* Ap = g_hq + ((size_t)e * BT_ + m0) * I_;
    const __half* Bp = g_dq + ((size_t)e * D_ + n0) * I_;

    const int tid = threadIdx.x, lane = tid & 31, warp = tid >> 5;
    const int wm = warp & 1, wn = warp >> 1;
    const int g = lane >> 2, tg = lane & 3;
    const int rbase = tid >> 3;
    const uint32_t qo = (uint32_t)(tid & 7) * 16;
    const int qh = (tid & 7) * 8;

    const uint32_t aoffL = (uint32_t)((lane & 7) + ((lane >> 3) & 1) * 8) * ROWB + (lane >> 4) * 16;
    const uint32_t boffL = (uint32_t)((lane & 7) + (lane >> 4) * 8) * ROWB + ((lane >> 3) & 1) * 16;
    const uint32_t aro = (uint32_t)(wm * 32) * ROWB;
    const uint32_t bro = ATB64 + (uint32_t)(wn * 32) * ROWB;

    float acc[2][4][4];
#pragma unroll
    for (int mt = 0; mt < 2; mt++)
#pragma unroll
        for (int nt = 0; nt < 4; nt++)
#pragma unroll
            for (int i = 0; i < 4; i++) acc[mt][nt][i] = 0.0f;

#define ISSUE_D(buf, k0) do {                                                   \
        uint32_t st_ = sb + (uint32_t)(buf) * STGB64;                           \
        _Pragma("unroll")                                                       \
        for (int j = 0; j < 2; j++) {                                           \
            int r_ = rbase + 32 * j;                                            \
            cp16(st_ + (uint32_t)r_ * ROWB + qo, Ap + (size_t)r_ * 1024 + (k0) + qh); \
        }                                                                       \
        _Pragma("unroll")                                                       \
        for (int j = 0; j < 4; j++) {                                           \
            int r_ = rbase + 32 * j;                                            \
            cp16(st_ + ATB64 + (uint32_t)r_ * ROWB + qo, Bp + (size_t)r_ * 1024 + (k0) + qh); \
        }                                                                       \
        cpcommit();                                                             \
    } while (0)

    const int NS = I_ / KT;   // 16
    ISSUE_D(0, 0);
    ISSUE_D(1, KT);

#pragma unroll 1
    for (int st = 0; st < NS; st++) {
        cpwait1();
        __syncthreads();
        if (st + 2 < NS) ISSUE_D((st + 2) % 3, (st + 2) * KT);
        else cpcommit();

        const uint32_t stb = sb + (uint32_t)(st % 3) * STGB64;
#pragma unroll
        for (int ks = 0; ks < 4; ks++) {
            const uint32_t kb = (uint32_t)ks * 32u;
            uint32_t af[2][4];
#pragma unroll
            for (int mt = 0; mt < 2; mt++)
                ldsm4(af[mt], stb + aro + (uint32_t)(mt * 16) * ROWB + aoffL + kb);
            uint32_t bf[2][4];
#pragma unroll
            for (int p = 0; p < 2; p++)
                ldsm4(bf[p], stb + bro + (uint32_t)(p * 16) * ROWB + boffL + kb);
#pragma unroll
            for (int mt = 0; mt < 2; mt++)
#pragma unroll
                for (int p = 0; p < 2; p++)
#pragma unroll
                    for (int q = 0; q < 2; q++)
                        hmma16(acc[mt][2 * p + q], af[mt], &bf[p][2 * q]);
        }
    }
#undef ISSUE_D

    // scatter partials to token rows (masked by slot < cnt)
#pragma unroll
    for (int mt = 0; mt < 2; mt++) {
        int s0 = m0 + wm * 32 + mt * 16 + g;
        int s1 = s0 + 8;
        if (s0 < cnt) {
            int t0 = __ldg(&g_tok[e * BT_ + s0]);
            float* P = g_part + ((size_t)e * BT_ + t0) * D_;
#pragma unroll
            for (int nt = 0; nt < 4; nt++) {
                int c0 = n0 + wn * 32 + nt * 8 + tg * 2;
                *(float2*)(P + c0) = make_float2(acc[mt][nt][0], acc[mt][nt][1]);
            }
        }
        if (s1 < cnt) {
            int t1 = __ldg(&g_tok[e * BT_ + s1]);
            float* P = g_part + ((size_t)e * BT_ + t1) * D_;
#pragma unroll
            for (int nt = 0; nt < 4; nt++) {
                int c0 = n0 + wn * 32 + nt * 8 + tg * 2;
                *(float2*)(P + c0) = make_float2(acc[mt][nt][2], acc[mt][nt][3]);
            }
        }
    }
}

// ---------------------------------------------------------------------------
// reduce: out[t] = sum over active experts (fixed order) of part[e][t]
// grid 8192 blocks (one per token) x 256 threads (4 floats each)
// ---------------------------------------------------------------------------
__global__ __launch_bounds__(256) void reduce_kernel(float* __restrict__ out)
{
    __shared__ float ws[E_];
    int t = blockIdx.x, tid = threadIdx.x;
    if (tid < E_) ws[tid] = g_w[t * E_ + tid];
    __syncthreads();

    int d = tid * 4;
    float4 acc = make_float4(0.0f, 0.0f, 0.0f, 0.0f);
#pragma unroll
    for (int e = 0; e < E_; e++) {
        if (ws[e] != 0.0f) {
            float4 v = *(const float4*)(g_part + ((size_t)e * BT_ + t) * D_ + d);
            acc.x += v.x; acc.y += v.y; acc.z += v.z; acc.w += v.w;
        }
    }
    *(float4*)(out + (size_t)t * D_ + d) = acc;
}

// ---------------------------------------------------------------------------
// launch — gemm_gu is the 6th launch so ncu (-s 5 -c 1) profiles it
// ---------------------------------------------------------------------------
extern "C" void kernel_launch(void* const* d_in, const int* in_sizes, int n_in,
                              void* d_out, int out_size)
{
    const float* x    = (const float*)d_in[0];
    const float* Wg   = (const float*)d_in[1];
    const float* Wu   = (const float*)d_in[2];
    const float* Wd   = (const float*)d_in[3];
    const float* Wr   = (const float*)d_in[4];
    const float* temp = (const float*)d_in[5];
    float* out = (float*)d_out;

    cudaFuncSetAttribute(gemm_gu_kernel, cudaFuncAttributeMaxDynamicSharedMemorySize, NSTG * STGB);
    cudaFuncSetAttribute(gemm_d_kernel,  cudaFuncAttributeMaxDynamicSharedMemorySize, NSTG * STGB64);

    __half *gq, *uq, *dq;
    cudaGetSymbolAddress((void**)&gq, g_gq);
    cudaGetSymbolAddress((void**)&uq, g_uq);
    cudaGetSymbolAddress((void**)&dq, g_dq);

    dim3 gt(32, 32, E_), bt(32, 8);

    convx_kernel<<<BT_ * D_ / 1024, 256>>>(x);          // 1
    convT_kernel<<<gt, bt>>>(Wg, gq);                   // 2
    convT_kernel<<<gt, bt>>>(Wu, uq);                   // 3
    routing_kernel<<<BT_ / 8, 256>>>(x, Wr, temp);      // 4
    compact_kernel<<<E_, 256>>>();                      // 5

    dim3 gGU(I_ / 128, BT_ / 128, E_);
    gemm_gu_kernel<<<gGU, 256, NSTG * STGB>>>();        // 6 <- ncu target

    convT_kernel<<<gt, bt>>>(Wd, dq);                   // 7

    dim3 gD(D_ / 128, BT_ / 64, E_);
    gemm_d_kernel<<<gD, 256, NSTG * STGB64>>>();        // 8

    reduce_kernel<<<BT_, 256>>>(out);                   // 9
}

// round 14
// speedup vs baseline: 21.0352x; 1.5058x over previous
#include <cuda_runtime.h>
#include <cuda_fp16.h>
#include <cstdint>
#include <cstddef>

// Problem dims: B=4, T=2048 -> BT=8192 tokens, D=1024, E=8, I=1024
#define BT_ 8192
#define D_  1024
#define E_  8
#define I_  1024

#define GOLDEN_CENTER 0.36787944117144233f
#define GOLDEN_LOWER  0.21231792754821915f
#define GOLDEN_UPPER  0.5f

// ---------------------------------------------------------------------------
// Device scratch (static; no runtime allocation)
// ---------------------------------------------------------------------------
__device__ __half g_xq[BT_ * D_];                      // x fp16 [t][d]
__device__ __half g_gq[E_ * D_ * I_];                  // Wg^T fp16 [e][i][d]
__device__ __half g_uq[E_ * D_ * I_];                  // Wu^T fp16 [e][i][d]
__device__ __half g_dq[E_ * D_ * I_];                  // Wd^T fp16 [e][d][i]
__device__ __half g_hq[(size_t)E_ * BT_ * I_];         // h' compacted fp16 [e][slot][i]
__device__ float  g_w[BT_ * E_];                       // routing weights [t][e]
__device__ int    g_tok[E_ * BT_];                     // compacted token ids per expert
__device__ int    g_cnt[E_];                           // active token count per expert
__device__ __half g_part[(size_t)E_ * BT_ * D_];       // per-expert partial out fp16 [e][t][d]

// ---------------------------------------------------------------------------
// helpers
// ---------------------------------------------------------------------------
__device__ __forceinline__ void hmma16(float c[4], const uint32_t a[4], const uint32_t b[2]) {
    asm volatile(
        "mma.sync.aligned.m16n8k16.row.col.f32.f16.f16.f32 "
        "{%0,%1,%2,%3},{%4,%5,%6,%7},{%8,%9},{%0,%1,%2,%3};\n"
        : "+f"(c[0]), "+f"(c[1]), "+f"(c[2]), "+f"(c[3])
        : "r"(a[0]), "r"(a[1]), "r"(a[2]), "r"(a[3]), "r"(b[0]), "r"(b[1]));
}
__device__ __forceinline__ void ldsm4(uint32_t r[4], uint32_t addr) {
    asm volatile("ldmatrix.sync.aligned.m8n8.x4.shared.b16 {%0,%1,%2,%3}, [%4];"
        : "=r"(r[0]), "=r"(r[1]), "=r"(r[2]), "=r"(r[3]) : "r"(addr));
}
__device__ __forceinline__ void cp16(uint32_t dst, const void* src) {
    asm volatile("cp.async.cg.shared.global [%0], [%1], 16;\n" :: "r"(dst), "l"(src) : "memory");
}
__device__ __forceinline__ void cpcommit() { asm volatile("cp.async.commit_group;\n" ::: "memory"); }
__device__ __forceinline__ void cpwait1()  { asm volatile("cp.async.wait_group 1;\n" ::: "memory"); }
__device__ __forceinline__ float siluf(float v) { return v / (1.0f + expf(-v)); }

// smem rows: 128 data bytes + 16 pad = 144B; conflict-free for ldmatrix
#define ROWB   144u
#define KT     64        // K halfs per stage (128 bytes)
// fused gemm_gu: CTA 128m x 128n, tiles A/G/U each 128 rows
#define TLB    18432u    // 128 rows * 144B
#define STGB   55296u    // 3 tiles per stage
#define NSTG   3u
// gemm_d: CTA 64m x 128n
#define ATB64  9216u     // A tile: 64 rows * 144B
#define STGB64 27648u

// ---------------------------------------------------------------------------
// Routing weights + x->fp16 conversion fused.
// One warp per token; fp32 twoProd-FMA + Neumaier compensated accumulation.
// ---------------------------------------------------------------------------
__global__ __launch_bounds__(256) void routing_kernel(
    const float* __restrict__ x, const float* __restrict__ Wr,
    const float* __restrict__ temp)
{
    int warp = threadIdx.x >> 5;
    int lane = threadIdx.x & 31;
    int t = blockIdx.x * 8 + warp;

    const float* xr = x + (size_t)t * D_;
    float s[E_], c[E_];
#pragma unroll
    for (int e = 0; e < E_; e++) { s[e] = 0.0f; c[e] = 0.0f; }

#pragma unroll 4
    for (int d0 = lane; d0 < D_; d0 += 32) {
        float xv = __ldg(xr + d0);
        float4 wa = *(const float4*)(Wr + d0 * E_);
        float4 wb = *(const float4*)(Wr + d0 * E_ + 4);
        float wv[E_] = {wa.x, wa.y, wa.z, wa.w, wb.x, wb.y, wb.z, wb.w};
#pragma unroll
        for (int e = 0; e < E_; e++) {
            float p   = xv * wv[e];
            float err = fmaf(xv, wv[e], -p);
            float tt  = s[e] + p;
            float e1  = (fabsf(s[e]) >= fabsf(p)) ? ((s[e] - tt) + p)
                                                  : ((p - tt) + s[e]);
            s[e] = tt;
            c[e] += e1 + err;
        }
    }
#pragma unroll
    for (int off = 16; off > 0; off >>= 1) {
#pragma unroll
        for (int e = 0; e < E_; e++) {
            float s2 = __shfl_down_sync(0xffffffffu, s[e], off);
            float c2 = __shfl_down_sync(0xffffffffu, c[e], off);
            float tt = s[e] + s2;
            float e1 = (fabsf(s[e]) >= fabsf(s2)) ? ((s[e] - tt) + s2)
                                                  : ((s2 - tt) + s[e]);
            s[e] = tt;
            c[e] += c2 + e1;
        }
    }

    if (lane == 0) {
        float T = temp[0];
        float dist[E_], wv[E_];
        float wsum = 0.0f;
#pragma unroll
        for (int e = 0; e < E_; e++) {
            float z = (s[e] + c[e]) / T;
            float inh = 1.0f / (1.0f + expf(-z));
            dist[e] = fabsf(inh - GOLDEN_CENTER);
            bool zone = (inh >= GOLDEN_LOWER) && (inh <= GOLDEN_UPPER);
            wv[e] = zone ? expf(-dist[e] / 0.1f) : 0.0f;
            wsum += wv[e];
        }
        if (wsum < 1e-8f) {
            float fb[E_];
#pragma unroll
            for (int e = 0; e < E_; e++) fb[e] = expf(-dist[e] / 0.3f);
            int i1 = 0;
#pragma unroll
            for (int e = 1; e < E_; e++) if (fb[e] > fb[i1]) i1 = e;
            int i2 = (i1 == 0) ? 1 : 0;
#pragma unroll
            for (int e = 0; e < E_; e++)
                if (e != i1 && fb[e] > fb[i2]) i2 = e;
            float sc = fmaxf(fb[i1] + fb[i2], 1e-8f);
#pragma unroll
            for (int e = 0; e < E_; e++)
                wv[e] = (e == i1 || e == i2) ? fb[e] / sc : 0.0f;
        }
        float s2 = 0.0f;
#pragma unroll
        for (int e = 0; e < E_; e++) s2 += wv[e];
        float inv = 1.0f / fmaxf(s2, 1e-8f);
#pragma unroll
        for (int e = 0; e < E_; e++) g_w[t * E_ + e] = wv[e] * inv;
    }

    // fused x -> fp16 conversion for this token's row (L1-hot re-read, coalesced)
    __half* xo = g_xq + (size_t)t * D_;
#pragma unroll
    for (int j = 0; j < 8; j++) {
        int d = (lane + 32 * j) * 4;
        float4 v = *(const float4*)(xr + d);
        *(__half2*)(xo + d)     = __floats2half2_rn(v.x, v.y);
        *(__half2*)(xo + d + 2) = __floats2half2_rn(v.z, v.w);
    }
}

// ---------------------------------------------------------------------------
// Deterministic per-expert compaction (ordered by token id; no atomics).
// 8 blocks (one per expert) x 256 threads.
// ---------------------------------------------------------------------------
__global__ __launch_bounds__(256) void compact_kernel()
{
    __shared__ int wsum[8];
    __shared__ int sbase;
    int e = blockIdx.x, tid = threadIdx.x, lane = tid & 31, wid = tid >> 5;
    if (tid == 0) sbase = 0;
    __syncthreads();

#pragma unroll 1
    for (int cch = 0; cch < BT_ / 256; cch++) {
        int t = cch * 256 + tid;
        int a = (g_w[t * E_ + e] != 0.0f) ? 1 : 0;
        unsigned m = __ballot_sync(0xffffffffu, a);
        int pos = __popc(m & ((1u << lane) - 1u));
        if (lane == 0) wsum[wid] = __popc(m);
        __syncthreads();
        int wbase = 0;
#pragma unroll
        for (int k = 0; k < 8; k++) if (k < wid) wbase += wsum[k];
        int tot = 0;
#pragma unroll
        for (int k = 0; k < 8; k++) tot += wsum[k];
        int base = sbase;
        __syncthreads();
        if (a) g_tok[e * BT_ + base + wbase + pos] = t;
        if (tid == 0) sbase = base + tot;
        __syncthreads();
    }

    int cnt = sbase;
    int pad = (cnt + 127) & ~127;
    for (int sidx = cnt + tid; sidx < pad; sidx += 256) g_tok[e * BT_ + sidx] = 0;
    if (tid == 0) g_cnt[e] = cnt;
}

// ---------------------------------------------------------------------------
// transpose + fp16: out[e][c][r] = half(in[e][r][c])
// ---------------------------------------------------------------------------
__global__ void convT_kernel(const float* __restrict__ in, __half* __restrict__ oq)
{
    __shared__ float t[32][33];
    int e = blockIdx.z;
    const float* ip = in + ((size_t)e << 20);
    __half* op = oq + ((size_t)e << 20);
    int r0 = blockIdx.y * 32, c0 = blockIdx.x * 32;
    int tx = threadIdx.x, ty = threadIdx.y;

#pragma unroll
    for (int j = ty; j < 32; j += 8)
        t[j][tx] = ip[(size_t)(r0 + j) * 1024 + c0 + tx];
    __syncthreads();
#pragma unroll
    for (int j = ty; j < 32; j += 8)
        op[(size_t)(c0 + j) * 1024 + r0 + tx] = __float2half_rn(t[tx][j]);
}

// ---------------------------------------------------------------------------
// gemm_gu FUSED + COMPACT: for expert e, over compacted token slots:
// h'[e][slot] = w[t][e] * silu(x[t]@Wg_e^T) * (x[t]@Wu_e^T), fp16, compacted.
// CTA 128slots x 128n, 8 warps (2m x 4n), dual accumulators. Early-exit if
// m0 >= cnt[e]. grid (I/128=8, BT/128=64, E=8)
// ---------------------------------------------------------------------------
__global__ __launch_bounds__(256) void gemm_gu_kernel()
{
    const int e  = blockIdx.z;
    const int m0 = blockIdx.y * 128;
    const int cnt = __ldg(&g_cnt[e]);
    if (m0 >= cnt) return;

    extern __shared__ char smem[];
    const uint32_t sb = (uint32_t)__cvta_generic_to_shared(smem);
    const int n0 = blockIdx.x * 128;

    const __half* Gp = g_gq + ((size_t)e * I_ + n0) * D_;
    const __half* Up = g_uq + ((size_t)e * I_ + n0) * D_;

    const int tid = threadIdx.x, lane = tid & 31, warp = tid >> 5;
    const int wm = warp & 1, wn = warp >> 1;
    const int g = lane >> 2, tg = lane & 3;
    const int rbase = tid >> 3;
    const uint32_t qo = (uint32_t)(tid & 7) * 16;
    const int qh = (tid & 7) * 8;

    const __half* arow[4];
#pragma unroll
    for (int j = 0; j < 4; j++) {
        int tk = __ldg(&g_tok[e * BT_ + m0 + rbase + 32 * j]);
        arow[j] = g_xq + (size_t)tk * D_;
    }

    const uint32_t aoffL = (uint32_t)((lane & 7) + ((lane >> 3) & 1) * 8) * ROWB + (lane >> 4) * 16;
    const uint32_t boffL = (uint32_t)((lane & 7) + (lane >> 4) * 8) * ROWB + ((lane >> 3) & 1) * 16;
    const uint32_t aro  = (uint32_t)(wm * 64) * ROWB;
    const uint32_t broG = TLB  + (uint32_t)(wn * 32) * ROWB;
    const uint32_t broU = 2u * TLB + (uint32_t)(wn * 32) * ROWB;

    float accg[4][4][4], accu[4][4][4];
#pragma unroll
    for (int mt = 0; mt < 4; mt++)
#pragma unroll
        for (int nt = 0; nt < 4; nt++)
#pragma unroll
            for (int i = 0; i < 4; i++) { accg[mt][nt][i] = 0.0f; accu[mt][nt][i] = 0.0f; }

#define ISSUE_GU(buf, k0) do {                                                  \
        uint32_t st_ = sb + (uint32_t)(buf) * STGB;                             \
        _Pragma("unroll")                                                       \
        for (int j = 0; j < 4; j++) {                                           \
            int r_ = rbase + 32 * j;                                            \
            uint32_t o_ = (uint32_t)r_ * ROWB + qo;                             \
            size_t  ws_ = (size_t)r_ * 1024 + (k0) + qh;                        \
            cp16(st_ + o_,            arow[j] + (k0) + qh);                     \
            cp16(st_ + TLB + o_,      Gp + ws_);                                \
            cp16(st_ + 2u * TLB + o_, Up + ws_);                                \
        }                                                                       \
        cpcommit();                                                             \
    } while (0)

    const int NS = D_ / KT;   // 16
    ISSUE_GU(0, 0);
    ISSUE_GU(1, KT);

#pragma unroll 1
    for (int st = 0; st < NS; st++) {
        cpwait1();
        __syncthreads();
        if (st + 2 < NS) ISSUE_GU((st + 2) % 3, (st + 2) * KT);
        else cpcommit();

        const uint32_t stb = sb + (uint32_t)(st % 3) * STGB;
#pragma unroll
        for (int ks = 0; ks < 4; ks++) {
            const uint32_t kb = (uint32_t)ks * 32u;
            uint32_t af[4][4];
#pragma unroll
            for (int mt = 0; mt < 4; mt++)
                ldsm4(af[mt], stb + aro + (uint32_t)(mt * 16) * ROWB + aoffL + kb);
            uint32_t gf[2][4], uf[2][4];
#pragma unroll
            for (int p = 0; p < 2; p++) {
                ldsm4(gf[p], stb + broG + (uint32_t)(p * 16) * ROWB + boffL + kb);
                ldsm4(uf[p], stb + broU + (uint32_t)(p * 16) * ROWB + boffL + kb);
            }
#pragma unroll
            for (int mt = 0; mt < 4; mt++)
#pragma unroll
                for (int p = 0; p < 2; p++)
#pragma unroll
                    for (int q = 0; q < 2; q++) {
                        hmma16(accg[mt][2 * p + q], af[mt], &gf[p][2 * q]);
                        hmma16(accu[mt][2 * p + q], af[mt], &uf[p][2 * q]);
                    }
        }
    }
#undef ISSUE_GU

    // epilogue: h'(compact slot) = w * silu(gate) * up
    __half* H = g_hq + (size_t)e * BT_ * I_;
#pragma unroll
    for (int mt = 0; mt < 4; mt++) {
        int r0 = m0 + wm * 64 + mt * 16 + g;
        int t0 = __ldg(&g_tok[e * BT_ + r0]);
        int t1 = __ldg(&g_tok[e * BT_ + r0 + 8]);
        float w0 = g_w[t0 * E_ + e];
        float w1 = g_w[t1 * E_ + e];
#pragma unroll
        for (int nt = 0; nt < 4; nt++) {
            int c0 = n0 + wn * 32 + nt * 8 + tg * 2;
            float h0 = w0 * siluf(accg[mt][nt][0]) * accu[mt][nt][0];
            float h1 = w0 * siluf(accg[mt][nt][1]) * accu[mt][nt][1];
            float h2 = w1 * siluf(accg[mt][nt][2]) * accu[mt][nt][2];
            float h3 = w1 * siluf(accg[mt][nt][3]) * accu[mt][nt][3];
            *(__half2*)(H + (size_t)r0 * I_ + c0)       = __floats2half2_rn(h0, h1);
            *(__half2*)(H + (size_t)(r0 + 8) * I_ + c0) = __floats2half2_rn(h2, h3);
        }
    }
}

// ---------------------------------------------------------------------------
// gemm_d COMPACT: per expert, part[e][t] = h'[e][slot] @ Wd[e]^T, fp16,
// scattered to token rows, masked by slot < cnt. CTA 64slots x 128n,
// 8 warps (2m x 4n), 3-stage ring, K=1024. grid (8, 128, 8), early-exit.
// ---------------------------------------------------------------------------
__global__ __launch_bounds__(256) void gemm_d_kernel()
{
    const int e  = blockIdx.z;
    const int m0 = blockIdx.y * 64;
    const int cnt = __ldg(&g_cnt[e]);
    if (m0 >= cnt) return;

    extern __shared__ char smem[];
    const uint32_t sb = (uint32_t)__cvta_generic_to_shared(smem);
    const int n0 = blockIdx.x * 128;

    const __half* Ap = g_hq + ((size_t)e * BT_ + m0) * I_;
    const __half* Bp = g_dq + ((size_t)e * D_ + n0) * I_;

    const int tid = threadIdx.x, lane = tid & 31, warp = tid >> 5;
    const int wm = warp & 1, wn = warp >> 1;
    const int g = lane >> 2, tg = lane & 3;
    const int rbase = tid >> 3;
    const uint32_t qo = (uint32_t)(tid & 7) * 16;
    const int qh = (tid & 7) * 8;

    const uint32_t aoffL = (uint32_t)((lane & 7) + ((lane >> 3) & 1) * 8) * ROWB + (lane >> 4) * 16;
    const uint32_t boffL = (uint32_t)((lane & 7) + (lane >> 4) * 8) * ROWB + ((lane >> 3) & 1) * 16;
    const uint32_t aro = (uint32_t)(wm * 32) * ROWB;
    const uint32_t bro = ATB64 + (uint32_t)(wn * 32) * ROWB;

    float acc[2][4][4];
#pragma unroll
    for (int mt = 0; mt < 2; mt++)
#pragma unroll
        for (int nt = 0; nt < 4; nt++)
#pragma unroll
            for (int i = 0; i < 4; i++) acc[mt][nt][i] = 0.0f;

#define ISSUE_D(buf, k0) do {                                                   \
        uint32_t st_ = sb + (uint32_t)(buf) * STGB64;                           \
        _Pragma("unroll")                                                       \
        for (int j = 0; j < 2; j++) {                                           \
            int r_ = rbase + 32 * j;                                            \
            cp16(st_ + (uint32_t)r_ * ROWB + qo, Ap + (size_t)r_ * 1024 + (k0) + qh); \
        }                                                                       \
        _Pragma("unroll")                                                       \
        for (int j = 0; j < 4; j++) {                                           \
            int r_ = rbase + 32 * j;                                            \
            cp16(st_ + ATB64 + (uint32_t)r_ * ROWB + qo, Bp + (size_t)r_ * 1024 + (k0) + qh); \
        }                                                                       \
        cpcommit();                                                             \
    } while (0)

    const int NS = I_ / KT;   // 16
    ISSUE_D(0, 0);
    ISSUE_D(1, KT);

#pragma unroll 1
    for (int st = 0; st < NS; st++) {
        cpwait1();
        __syncthreads();
        if (st + 2 < NS) ISSUE_D((st + 2) % 3, (st + 2) * KT);
        else cpcommit();

        const uint32_t stb = sb + (uint32_t)(st % 3) * STGB64;
#pragma unroll
        for (int ks = 0; ks < 4; ks++) {
            const uint32_t kb = (uint32_t)ks * 32u;
            uint32_t af[2][4];
#pragma unroll
            for (int mt = 0; mt < 2; mt++)
                ldsm4(af[mt], stb + aro + (uint32_t)(mt * 16) * ROWB + aoffL + kb);
            uint32_t bf[2][4];
#pragma unroll
            for (int p = 0; p < 2; p++)
                ldsm4(bf[p], stb + bro + (uint32_t)(p * 16) * ROWB + boffL + kb);
#pragma unroll
            for (int mt = 0; mt < 2; mt++)
#pragma unroll
                for (int p = 0; p < 2; p++)
#pragma unroll
                    for (int q = 0; q < 2; q++)
                        hmma16(acc[mt][2 * p + q], af[mt], &bf[p][2 * q]);
        }
    }
#undef ISSUE_D

    // scatter fp16 partials to token rows (masked by slot < cnt)
#pragma unroll
    for (int mt = 0; mt < 2; mt++) {
        int s0 = m0 + wm * 32 + mt * 16 + g;
        int s1 = s0 + 8;
        if (s0 < cnt) {
            int t0 = __ldg(&g_tok[e * BT_ + s0]);
            __half* P = g_part + ((size_t)e * BT_ + t0) * D_;
#pragma unroll
            for (int nt = 0; nt < 4; nt++) {
                int c0 = n0 + wn * 32 + nt * 8 + tg * 2;
                *(__half2*)(P + c0) = __floats2half2_rn(acc[mt][nt][0], acc[mt][nt][1]);
            }
        }
        if (s1 < cnt) {
            int t1 = __ldg(&g_tok[e * BT_ + s1]);
            __half* P = g_part + ((size_t)e * BT_ + t1) * D_;
#pragma unroll
            for (int nt = 0; nt < 4; nt++) {
                int c0 = n0 + wn * 32 + nt * 8 + tg * 2;
                *(__half2*)(P + c0) = __floats2half2_rn(acc[mt][nt][2], acc[mt][nt][3]);
            }
        }
    }
}

// ---------------------------------------------------------------------------
// reduce: out[t] = sum over active experts (fixed order) of part[e][t]
// grid 8192 blocks (one per token) x 256 threads (4 elems each)
// ---------------------------------------------------------------------------
__global__ __launch_bounds__(256) void reduce_kernel(float* __restrict__ out)
{
    __shared__ float ws[E_];
    int t = blockIdx.x, tid = threadIdx.x;
    if (tid < E_) ws[tid] = g_w[t * E_ + tid];
    __syncthreads();

    int d = tid * 4;
    float4 acc = make_float4(0.0f, 0.0f, 0.0f, 0.0f);
#pragma unroll
    for (int e = 0; e < E_; e++) {
        if (ws[e] != 0.0f) {
            const __half2* P = (const __half2*)(g_part + ((size_t)e * BT_ + t) * D_ + d);
            __half2 v0 = P[0], v1 = P[1];
            float2 f0 = __half22float2(v0), f1 = __half22float2(v1);
            acc.x += f0.x; acc.y += f0.y; acc.z += f1.x; acc.w += f1.y;
        }
    }
    *(float4*)(out + (size_t)t * D_ + d) = acc;
}

// ---------------------------------------------------------------------------
// launch — gemm_gu is the 6th launch so ncu (-s 5 -c 1) may land on it
// ---------------------------------------------------------------------------
extern "C" void kernel_launch(void* const* d_in, const int* in_sizes, int n_in,
                              void* d_out, int out_size)
{
    const float* x    = (const float*)d_in[0];
    const float* Wg   = (const float*)d_in[1];
    const float* Wu   = (const float*)d_in[2];
    const float* Wd   = (const float*)d_in[3];
    const float* Wr   = (const float*)d_in[4];
    const float* temp = (const float*)d_in[5];
    float* out = (float*)d_out;

    cudaFuncSetAttribute(gemm_gu_kernel, cudaFuncAttributeMaxDynamicSharedMemorySize, NSTG * STGB);
    cudaFuncSetAttribute(gemm_d_kernel,  cudaFuncAttributeMaxDynamicSharedMemorySize, NSTG * STGB64);

    __half *gq, *uq, *dq;
    cudaGetSymbolAddress((void**)&gq, g_gq);
    cudaGetSymbolAddress((void**)&uq, g_uq);
    cudaGetSymbolAddress((void**)&dq, g_dq);

    dim3 gt(32, 32, E_), bt(32, 8);

    routing_kernel<<<BT_ / 8, 256>>>(x, Wr, temp);      // 1 (also converts x->fp16)
    compact_kernel<<<E_, 256>>>();                      // 2
    convT_kernel<<<gt, bt>>>(Wg, gq);                   // 3
    convT_kernel<<<gt, bt>>>(Wu, uq);                   // 4
    convT_kernel<<<gt, bt>>>(Wd, dq);                   // 5

    dim3 gGU(I_ / 128, BT_ / 128, E_);
    gemm_gu_kernel<<<gGU, 256, NSTG * STGB>>>();        // 6 <- ncu target

    dim3 gD(D_ / 128, BT_ / 64, E_);
    gemm_d_kernel<<<gD, 256, NSTG * STGB64>>>();        // 7

    reduce_kernel<<<BT_, 256>>>(out);                   // 8
}

// round 15
// speedup vs baseline: 21.3358x; 1.0143x over previous
#include <cuda_runtime.h>
#include <cuda_fp16.h>
#include <cstdint>
#include <cstddef>

// Problem dims: B=4, T=2048 -> BT=8192 tokens, D=1024, E=8, I=1024
#define BT_ 8192
#define D_  1024
#define E_  8
#define I_  1024

#define GOLDEN_CENTER 0.36787944117144233f
#define GOLDEN_LOWER  0.21231792754821915f
#define GOLDEN_UPPER  0.5f

// ---------------------------------------------------------------------------
// Device scratch (static; no runtime allocation)
// ---------------------------------------------------------------------------
__device__ __half g_xq[BT_ * D_];                      // x fp16 [t][d]
__device__ __half g_gq[E_ * D_ * I_];                  // Wg^T fp16 [e][i][d]
__device__ __half g_uq[E_ * D_ * I_];                  // Wu^T fp16 [e][i][d]
__device__ __half g_dq[E_ * D_ * I_];                  // Wd^T fp16 [e][d][i]
__device__ __half g_hq[(size_t)E_ * BT_ * I_];         // h' compacted fp16 [e][slot][i]
__device__ float  g_w[BT_ * E_];                       // routing weights [t][e]
__device__ int    g_tok[E_ * BT_];                     // compacted token ids per expert
__device__ int    g_cnt[E_];                           // active token count per expert
__device__ __half g_part[(size_t)E_ * BT_ * D_];       // per-expert partial out fp16 [e][t][d]

// ---------------------------------------------------------------------------
// helpers
// ---------------------------------------------------------------------------
__device__ __forceinline__ void hmma16(float c[4], const uint32_t a[4], const uint32_t b[2]) {
    asm volatile(
        "mma.sync.aligned.m16n8k16.row.col.f32.f16.f16.f32 "
        "{%0,%1,%2,%3},{%4,%5,%6,%7},{%8,%9},{%0,%1,%2,%3};\n"
        : "+f"(c[0]), "+f"(c[1]), "+f"(c[2]), "+f"(c[3])
        : "r"(a[0]), "r"(a[1]), "r"(a[2]), "r"(a[3]), "r"(b[0]), "r"(b[1]));
}
__device__ __forceinline__ void ldsm4(uint32_t r[4], uint32_t addr) {
    asm volatile("ldmatrix.sync.aligned.m8n8.x4.shared.b16 {%0,%1,%2,%3}, [%4];"
        : "=r"(r[0]), "=r"(r[1]), "=r"(r[2]), "=r"(r[3]) : "r"(addr));
}
__device__ __forceinline__ void cp16(uint32_t dst, const void* src) {
    asm volatile("cp.async.cg.shared.global [%0], [%1], 16;\n" :: "r"(dst), "l"(src) : "memory");
}
__device__ __forceinline__ void cpcommit() { asm volatile("cp.async.commit_group;\n" ::: "memory"); }
__device__ __forceinline__ void cpwait1()  { asm volatile("cp.async.wait_group 1;\n" ::: "memory"); }
__device__ __forceinline__ float siluf(float v) { return v / (1.0f + expf(-v)); }

// smem rows: 128 data bytes + 16 pad = 144B; conflict-free for ldmatrix
#define ROWB   144u
#define KT     64        // K halfs per stage (128 bytes)
// fused gemm_gu: CTA 128m x 128n, tiles A/G/U each 128 rows
#define TLB    18432u    // 128 rows * 144B
#define STGB   55296u    // 3 tiles per stage
#define NSTG   3u
// gemm_d: CTA 64m x 128n
#define ATB64  9216u     // A tile: 64 rows * 144B
#define STGB64 27648u

// ---------------------------------------------------------------------------
// Routing + x->fp16, 2 warps per token (each covers half of D).
// fp32 twoProd-FMA + Neumaier compensated accumulation; partials merged
// with the same compensated combine. Block = 8 warps = 4 tokens.
// ---------------------------------------------------------------------------
__global__ __launch_bounds__(256) void routing_kernel(
    const float* __restrict__ x, const float* __restrict__ Wr,
    const float* __restrict__ temp)
{
    __shared__ float s_s[4][2][E_], s_c[4][2][E_];
    int tid = threadIdx.x;
    int warp = tid >> 5, lane = tid & 31;
    int pair = warp >> 1, h = warp & 1;
    int t = blockIdx.x * 4 + pair;

    const float* xr = x + (size_t)t * D_;
    float s[E_], c[E_];
#pragma unroll
    for (int e = 0; e < E_; e++) { s[e] = 0.0f; c[e] = 0.0f; }

#pragma unroll 4
    for (int d0 = lane + 32 * h; d0 < D_; d0 += 64) {
        float xv = __ldg(xr + d0);
        float4 wa = *(const float4*)(Wr + d0 * E_);
        float4 wb = *(const float4*)(Wr + d0 * E_ + 4);
        float wv[E_] = {wa.x, wa.y, wa.z, wa.w, wb.x, wb.y, wb.z, wb.w};
#pragma unroll
        for (int e = 0; e < E_; e++) {
            float p   = xv * wv[e];
            float err = fmaf(xv, wv[e], -p);
            float tt  = s[e] + p;
            float e1  = (fabsf(s[e]) >= fabsf(p)) ? ((s[e] - tt) + p)
                                                  : ((p - tt) + s[e]);
            s[e] = tt;
            c[e] += e1 + err;
        }
    }
#pragma unroll
    for (int off = 16; off > 0; off >>= 1) {
#pragma unroll
        for (int e = 0; e < E_; e++) {
            float s2 = __shfl_down_sync(0xffffffffu, s[e], off);
            float c2 = __shfl_down_sync(0xffffffffu, c[e], off);
            float tt = s[e] + s2;
            float e1 = (fabsf(s[e]) >= fabsf(s2)) ? ((s[e] - tt) + s2)
                                                  : ((s2 - tt) + s[e]);
            s[e] = tt;
            c[e] += c2 + e1;
        }
    }
    if (lane == 0) {
#pragma unroll
        for (int e = 0; e < E_; e++) { s_s[pair][h][e] = s[e]; s_c[pair][h][e] = c[e]; }
    }

    // fused x -> fp16 conversion (both warps, coalesced, L1-hot re-read)
    __half* xo = g_xq + (size_t)t * D_;
#pragma unroll
    for (int j = 0; j < 4; j++) {
        int d = (lane + 32 * h + 64 * j) * 4;
        float4 v = *(const float4*)(xr + d);
        *(__half2*)(xo + d)     = __floats2half2_rn(v.x, v.y);
        *(__half2*)(xo + d + 2) = __floats2half2_rn(v.z, v.w);
    }
    __syncthreads();

    if (h == 0 && lane == 0) {
        float T = temp[0];
        float dist[E_], wv[E_];
        float wsum = 0.0f;
#pragma unroll
        for (int e = 0; e < E_; e++) {
            float s0 = s_s[pair][0][e], s1 = s_s[pair][1][e];
            float tt = s0 + s1;
            float e1 = (fabsf(s0) >= fabsf(s1)) ? ((s0 - tt) + s1)
                                                : ((s1 - tt) + s0);
            float z = (tt + (s_c[pair][0][e] + s_c[pair][1][e] + e1)) / T;
            float inh = 1.0f / (1.0f + expf(-z));
            dist[e] = fabsf(inh - GOLDEN_CENTER);
            bool zone = (inh >= GOLDEN_LOWER) && (inh <= GOLDEN_UPPER);
            wv[e] = zone ? expf(-dist[e] / 0.1f) : 0.0f;
            wsum += wv[e];
        }
        if (wsum < 1e-8f) {
            float fb[E_];
#pragma unroll
            for (int e = 0; e < E_; e++) fb[e] = expf(-dist[e] / 0.3f);
            int i1 = 0;
#pragma unroll
            for (int e = 1; e < E_; e++) if (fb[e] > fb[i1]) i1 = e;
            int i2 = (i1 == 0) ? 1 : 0;
#pragma unroll
            for (int e = 0; e < E_; e++)
                if (e != i1 && fb[e] > fb[i2]) i2 = e;
            float sc = fmaxf(fb[i1] + fb[i2], 1e-8f);
#pragma unroll
            for (int e = 0; e < E_; e++)
                wv[e] = (e == i1 || e == i2) ? fb[e] / sc : 0.0f;
        }
        float s2 = 0.0f;
#pragma unroll
        for (int e = 0; e < E_; e++) s2 += wv[e];
        float inv = 1.0f / fmaxf(s2, 1e-8f);
#pragma unroll
        for (int e = 0; e < E_; e++) g_w[t * E_ + e] = wv[e] * inv;
    }
}

// ---------------------------------------------------------------------------
// Deterministic per-expert compaction (ordered by token id; no atomics).
// ---------------------------------------------------------------------------
__global__ __launch_bounds__(256) void compact_kernel()
{
    __shared__ int wsum[8];
    __shared__ int sbase;
    int e = blockIdx.x, tid = threadIdx.x, lane = tid & 31, wid = tid >> 5;
    if (tid == 0) sbase = 0;
    __syncthreads();

#pragma unroll 1
    for (int cch = 0; cch < BT_ / 256; cch++) {
        int t = cch * 256 + tid;
        int a = (g_w[t * E_ + e] != 0.0f) ? 1 : 0;
        unsigned m = __ballot_sync(0xffffffffu, a);
        int pos = __popc(m & ((1u << lane) - 1u));
        if (lane == 0) wsum[wid] = __popc(m);
        __syncthreads();
        int wbase = 0;
#pragma unroll
        for (int k = 0; k < 8; k++) if (k < wid) wbase += wsum[k];
        int tot = 0;
#pragma unroll
        for (int k = 0; k < 8; k++) tot += wsum[k];
        int base = sbase;
        __syncthreads();
        if (a) g_tok[e * BT_ + base + wbase + pos] = t;
        if (tid == 0) sbase = base + tot;
        __syncthreads();
    }

    int cnt = sbase;
    int pad = (cnt + 127) & ~127;
    for (int sidx = cnt + tid; sidx < pad; sidx += 256) g_tok[e * BT_ + sidx] = 0;
    if (tid == 0) g_cnt[e] = cnt;
}

// ---------------------------------------------------------------------------
// transpose + fp16, all 3 weight tensors in one launch (z = 24).
// Vectorized half2 stores (thread writes an r-pair).
// ---------------------------------------------------------------------------
__global__ void convT_kernel(
    const float* __restrict__ in0, const float* __restrict__ in1,
    const float* __restrict__ in2,
    __half* __restrict__ o0, __half* __restrict__ o1, __half* __restrict__ o2)
{
    __shared__ float t[32][33];
    int zz = blockIdx.z;
    int which = zz >> 3, e = zz & 7;
    const float* in = (which == 0) ? in0 : (which == 1) ? in1 : in2;
    __half* oq      = (which == 0) ? o0  : (which == 1) ? o1  : o2;

    const float* ip = in + ((size_t)e << 20);
    __half* op = oq + ((size_t)e << 20);
    int r0 = blockIdx.y * 32, c0 = blockIdx.x * 32;
    int tx = threadIdx.x, ty = threadIdx.y;

#pragma unroll
    for (int j = ty; j < 32; j += 8)
        t[j][tx] = ip[(size_t)(r0 + j) * 1024 + c0 + tx];
    __syncthreads();

    int rh = (tx & 15) * 2;
    int jh = tx >> 4;
#pragma unroll
    for (int k = ty; k < 16; k += 8) {
        int j = k * 2 + jh;
        __half2 v = __floats2half2_rn(t[rh][j], t[rh + 1][j]);
        *(__half2*)(op + (size_t)(c0 + j) * 1024 + r0 + rh) = v;
    }
}

// ---------------------------------------------------------------------------
// gemm_gu FUSED + COMPACT (unchanged): h'[e][slot] = w*silu(x@Wg^T)*(x@Wu^T)
// CTA 128slots x 128n, 8 warps (2m x 4n). grid (8, 64, 8), early-exit.
// ---------------------------------------------------------------------------
__global__ __launch_bounds__(256) void gemm_gu_kernel()
{
    const int e  = blockIdx.z;
    const int m0 = blockIdx.y * 128;
    const int cnt = __ldg(&g_cnt[e]);
    if (m0 >= cnt) return;

    extern __shared__ char smem[];
    const uint32_t sb = (uint32_t)__cvta_generic_to_shared(smem);
    const int n0 = blockIdx.x * 128;

    const __half* Gp = g_gq + ((size_t)e * I_ + n0) * D_;
    const __half* Up = g_uq + ((size_t)e * I_ + n0) * D_;

    const int tid = threadIdx.x, lane = tid & 31, warp = tid >> 5;
    const int wm = warp & 1, wn = warp >> 1;
    const int g = lane >> 2, tg = lane & 3;
    const int rbase = tid >> 3;
    const uint32_t qo = (uint32_t)(tid & 7) * 16;
    const int qh = (tid & 7) * 8;

    const __half* arow[4];
#pragma unroll
    for (int j = 0; j < 4; j++) {
        int tk = __ldg(&g_tok[e * BT_ + m0 + rbase + 32 * j]);
        arow[j] = g_xq + (size_t)tk * D_;
    }

    const uint32_t aoffL = (uint32_t)((lane & 7) + ((lane >> 3) & 1) * 8) * ROWB + (lane >> 4) * 16;
    const uint32_t boffL = (uint32_t)((lane & 7) + (lane >> 4) * 8) * ROWB + ((lane >> 3) & 1) * 16;
    const uint32_t aro  = (uint32_t)(wm * 64) * ROWB;
    const uint32_t broG = TLB  + (uint32_t)(wn * 32) * ROWB;
    const uint32_t broU = 2u * TLB + (uint32_t)(wn * 32) * ROWB;

    float accg[4][4][4], accu[4][4][4];
#pragma unroll
    for (int mt = 0; mt < 4; mt++)
#pragma unroll
        for (int nt = 0; nt < 4; nt++)
#pragma unroll
            for (int i = 0; i < 4; i++) { accg[mt][nt][i] = 0.0f; accu[mt][nt][i] = 0.0f; }

#define ISSUE_GU(buf, k0) do {                                                  \
        uint32_t st_ = sb + (uint32_t)(buf) * STGB;                             \
        _Pragma("unroll")                                                       \
        for (int j = 0; j < 4; j++) {                                           \
            int r_ = rbase + 32 * j;                                            \
            uint32_t o_ = (uint32_t)r_ * ROWB + qo;                             \
            size_t  ws_ = (size_t)r_ * 1024 + (k0) + qh;                        \
            cp16(st_ + o_,            arow[j] + (k0) + qh);                     \
            cp16(st_ + TLB + o_,      Gp + ws_);                                \
            cp16(st_ + 2u * TLB + o_, Up + ws_);                                \
        }                                                                       \
        cpcommit();                                                             \
    } while (0)

    const int NS = D_ / KT;   // 16
    ISSUE_GU(0, 0);
    ISSUE_GU(1, KT);

#pragma unroll 1
    for (int st = 0; st < NS; st++) {
        cpwait1();
        __syncthreads();
        if (st + 2 < NS) ISSUE_GU((st + 2) % 3, (st + 2) * KT);
        else cpcommit();

        const uint32_t stb = sb + (uint32_t)(st % 3) * STGB;
#pragma unroll
        for (int ks = 0; ks < 4; ks++) {
            const uint32_t kb = (uint32_t)ks * 32u;
            uint32_t af[4][4];
#pragma unroll
            for (int mt = 0; mt < 4; mt++)
                ldsm4(af[mt], stb + aro + (uint32_t)(mt * 16) * ROWB + aoffL + kb);
            uint32_t gf[2][4], uf[2][4];
#pragma unroll
            for (int p = 0; p < 2; p++) {
                ldsm4(gf[p], stb + broG + (uint32_t)(p * 16) * ROWB + boffL + kb);
                ldsm4(uf[p], stb + broU + (uint32_t)(p * 16) * ROWB + boffL + kb);
            }
#pragma unroll
            for (int mt = 0; mt < 4; mt++)
#pragma unroll
                for (int p = 0; p < 2; p++)
#pragma unroll
                    for (int q = 0; q < 2; q++) {
                        hmma16(accg[mt][2 * p + q], af[mt], &gf[p][2 * q]);
                        hmma16(accu[mt][2 * p + q], af[mt], &uf[p][2 * q]);
                    }
        }
    }
#undef ISSUE_GU

    __half* H = g_hq + (size_t)e * BT_ * I_;
#pragma unroll
    for (int mt = 0; mt < 4; mt++) {
        int r0 = m0 + wm * 64 + mt * 16 + g;
        int t0 = __ldg(&g_tok[e * BT_ + r0]);
        int t1 = __ldg(&g_tok[e * BT_ + r0 + 8]);
        float w0 = g_w[t0 * E_ + e];
        float w1 = g_w[t1 * E_ + e];
#pragma unroll
        for (int nt = 0; nt < 4; nt++) {
            int c0 = n0 + wn * 32 + nt * 8 + tg * 2;
            float h0 = w0 * siluf(accg[mt][nt][0]) * accu[mt][nt][0];
            float h1 = w0 * siluf(accg[mt][nt][1]) * accu[mt][nt][1];
            float h2 = w1 * siluf(accg[mt][nt][2]) * accu[mt][nt][2];
            float h3 = w1 * siluf(accg[mt][nt][3]) * accu[mt][nt][3];
            *(__half2*)(H + (size_t)r0 * I_ + c0)       = __floats2half2_rn(h0, h1);
            *(__half2*)(H + (size_t)(r0 + 8) * I_ + c0) = __floats2half2_rn(h2, h3);
        }
    }
}

// ---------------------------------------------------------------------------
// gemm_d COMPACT (unchanged): part[e][t] = h'[e][slot] @ Wd[e]^T, fp16 scatter
// ---------------------------------------------------------------------------
__global__ __launch_bounds__(256) void gemm_d_kernel()
{
    const int e  = blockIdx.z;
    const int m0 = blockIdx.y * 64;
    const int cnt = __ldg(&g_cnt[e]);
    if (m0 >= cnt) return;

    extern __shared__ char smem[];
    const uint32_t sb = (uint32_t)__cvta_generic_to_shared(smem);
    const int n0 = blockIdx.x * 128;

    const __half* Ap = g_hq + ((size_t)e * BT_ + m0) * I_;
    const __half* Bp = g_dq + ((size_t)e * D_ + n0) * I_;

    const int tid = threadIdx.x, lane = tid & 31, warp = tid >> 5;
    const int wm = warp & 1, wn = warp >> 1;
    const int g = lane >> 2, tg = lane & 3;
    const int rbase = tid >> 3;
    const uint32_t qo = (uint32_t)(tid & 7) * 16;
    const int qh = (tid & 7) * 8;

    const uint32_t aoffL = (uint32_t)((lane & 7) + ((lane >> 3) & 1) * 8) * ROWB + (lane >> 4) * 16;
    const uint32_t boffL = (uint32_t)((lane & 7) + (lane >> 4) * 8) * ROWB + ((lane >> 3) & 1) * 16;
    const uint32_t aro = (uint32_t)(wm * 32) * ROWB;
    const uint32_t bro = ATB64 + (uint32_t)(wn * 32) * ROWB;

    float acc[2][4][4];
#pragma unroll
    for (int mt = 0; mt < 2; mt++)
#pragma unroll
        for (int nt = 0; nt < 4; nt++)
#pragma unroll
            for (int i = 0; i < 4; i++) acc[mt][nt][i] = 0.0f;

#define ISSUE_D(buf, k0) do {                                                   \
        uint32_t st_ = sb + (uint32_t)(buf) * STGB64;                           \
        _Pragma("unroll")                                                       \
        for (int j = 0; j < 2; j++) {                                           \
            int r_ = rbase + 32 * j;                                            \
            cp16(st_ + (uint32_t)r_ * ROWB + qo, Ap + (size_t)r_ * 1024 + (k0) + qh); \
        }                                                                       \
        _Pragma("unroll")                                                       \
        for (int j = 0; j < 4; j++) {                                           \
            int r_ = rbase + 32 * j;                                            \
            cp16(st_ + ATB64 + (uint32_t)r_ * ROWB + qo, Bp + (size_t)r_ * 1024 + (k0) + qh); \
        }                                                                       \
        cpcommit();                                                             \
    } while (0)

    const int NS = I_ / KT;   // 16
    ISSUE_D(0, 0);
    ISSUE_D(1, KT);

#pragma unroll 1
    for (int st = 0; st < NS; st++) {
        cpwait1();
        __syncthreads();
        if (st + 2 < NS) ISSUE_D((st + 2) % 3, (st + 2) * KT);
        else cpcommit();

        const uint32_t stb = sb + (uint32_t)(st % 3) * STGB64;
#pragma unroll
        for (int ks = 0; ks < 4; ks++) {
            const uint32_t kb = (uint32_t)ks * 32u;
            uint32_t af[2][4];
#pragma unroll
            for (int mt = 0; mt < 2; mt++)
                ldsm4(af[mt], stb + aro + (uint32_t)(mt * 16) * ROWB + aoffL + kb);
            uint32_t bf[2][4];
#pragma unroll
            for (int p = 0; p < 2; p++)
                ldsm4(bf[p], stb + bro + (uint32_t)(p * 16) * ROWB + boffL + kb);
#pragma unroll
            for (int mt = 0; mt < 2; mt++)
#pragma unroll
                for (int p = 0; p < 2; p++)
#pragma unroll
                    for (int q = 0; q < 2; q++)
                        hmma16(acc[mt][2 * p + q], af[mt], &bf[p][2 * q]);
        }
    }
#undef ISSUE_D

#pragma unroll
    for (int mt = 0; mt < 2; mt++) {
        int s0 = m0 + wm * 32 + mt * 16 + g;
        int s1 = s0 + 8;
        if (s0 < cnt) {
            int t0 = __ldg(&g_tok[e * BT_ + s0]);
            __half* P = g_part + ((size_t)e * BT_ + t0) * D_;
#pragma unroll
            for (int nt = 0; nt < 4; nt++) {
                int c0 = n0 + wn * 32 + nt * 8 + tg * 2;
                *(__half2*)(P + c0) = __floats2half2_rn(acc[mt][nt][0], acc[mt][nt][1]);
            }
        }
        if (s1 < cnt) {
            int t1 = __ldg(&g_tok[e * BT_ + s1]);
            __half* P = g_part + ((size_t)e * BT_ + t1) * D_;
#pragma unroll
            for (int nt = 0; nt < 4; nt++) {
                int c0 = n0 + wn * 32 + nt * 8 + tg * 2;
                *(__half2*)(P + c0) = __floats2half2_rn(acc[mt][nt][2], acc[mt][nt][3]);
            }
        }
    }
}

// ---------------------------------------------------------------------------
// reduce (flat, no smem/sync): out[t][d] = sum_e active part[e][t][d]
// one float4 per thread; grid 8192 x 256
// ---------------------------------------------------------------------------
__global__ __launch_bounds__(256) void reduce_kernel(float* __restrict__ out)
{
    int gid = blockIdx.x * 256 + threadIdx.x;   // [0, 2M)
    int t = gid >> 8;
    int d = (gid & 255) * 4;

    const float* wr = g_w + t * E_;
    float4 acc = make_float4(0.0f, 0.0f, 0.0f, 0.0f);
#pragma unroll
    for (int e = 0; e < E_; e++) {
        float w = __ldg(wr + e);
        if (w != 0.0f) {
            const __half2* P = (const __half2*)(g_part + ((size_t)e * BT_ + t) * D_ + d);
            float2 f0 = __half22float2(P[0]), f1 = __half22float2(P[1]);
            acc.x += f0.x; acc.y += f0.y; acc.z += f1.x; acc.w += f1.y;
        }
    }
    *(float4*)(out + (size_t)t * D_ + d) = acc;
}

// ---------------------------------------------------------------------------
// launch
// ---------------------------------------------------------------------------
extern "C" void kernel_launch(void* const* d_in, const int* in_sizes, int n_in,
                              void* d_out, int out_size)
{
    const float* x    = (const float*)d_in[0];
    const float* Wg   = (const float*)d_in[1];
    const float* Wu   = (const float*)d_in[2];
    const float* Wd   = (const float*)d_in[3];
    const float* Wr   = (const float*)d_in[4];
    const float* temp = (const float*)d_in[5];
    float* out = (float*)d_out;

    cudaFuncSetAttribute(gemm_gu_kernel, cudaFuncAttributeMaxDynamicSharedMemorySize, NSTG * STGB);
    cudaFuncSetAttribute(gemm_d_kernel,  cudaFuncAttributeMaxDynamicSharedMemorySize, NSTG * STGB64);

    __half *gq, *uq, *dq;
    cudaGetSymbolAddress((void**)&gq, g_gq);
    cudaGetSymbolAddress((void**)&uq, g_uq);
    cudaGetSymbolAddress((void**)&dq, g_dq);

    routing_kernel<<<BT_ / 4, 256>>>(x, Wr, temp);      // 1 (+ x->fp16)
    compact_kernel<<<E_, 256>>>();                      // 2

    dim3 gt(32, 32, 3 * E_), bt(32, 8);
    convT_kernel<<<gt, bt>>>(Wg, Wu, Wd, gq, uq, dq);   // 3 (all weights)

    dim3 gGU(I_ / 128, BT_ / 128, E_);
    gemm_gu_kernel<<<gGU, 256, NSTG * STGB>>>();        // 4

    dim3 gD(D_ / 128, BT_ / 64, E_);
    gemm_d_kernel<<<gD, 256, NSTG * STGB64>>>();        // 5

    reduce_kernel<<<BT_, 256>>>(out);                   // 6
}

// round 16
// speedup vs baseline: 23.5311x; 1.1029x over previous
#include <cuda_runtime.h>
#include <cuda_fp16.h>
#include <cstdint>
#include <cstddef>

// Problem dims: B=4, T=2048 -> BT=8192 tokens, D=1024, E=8, I=1024
#define BT_ 8192
#define D_  1024
#define E_  8
#define I_  1024

#define GOLDEN_CENTER 0.36787944117144233f
#define GOLDEN_LOWER  0.21231792754821915f
#define GOLDEN_UPPER  0.5f

// ---------------------------------------------------------------------------
// Device scratch (static; no runtime allocation)
// ---------------------------------------------------------------------------
__device__ __half g_xq[BT_ * D_];                      // x fp16 [t][d]
__device__ __half g_gq[E_ * D_ * I_];                  // Wg^T fp16 [e][i][d]
__device__ __half g_uq[E_ * D_ * I_];                  // Wu^T fp16 [e][i][d]
__device__ __half g_dq[E_ * D_ * I_];                  // Wd^T fp16 [e][d][i]
__device__ __half g_hq[(size_t)E_ * BT_ * I_];         // h' compacted fp16 [e][slot][i]
__device__ float  g_w[BT_ * E_];                       // routing weights [t][e]
__device__ int    g_tok[E_ * BT_];                     // compacted token ids per expert
__device__ int    g_cnt[E_];                           // active token count per expert
__device__ __half g_part[(size_t)E_ * BT_ * D_];       // per-expert partial out fp16 [e][t][d]

// ---------------------------------------------------------------------------
// helpers
// ---------------------------------------------------------------------------
__device__ __forceinline__ void hmma16(float c[4], const uint32_t a[4], const uint32_t b[2]) {
    asm volatile(
        "mma.sync.aligned.m16n8k16.row.col.f32.f16.f16.f32 "
        "{%0,%1,%2,%3},{%4,%5,%6,%7},{%8,%9},{%0,%1,%2,%3};\n"
        : "+f"(c[0]), "+f"(c[1]), "+f"(c[2]), "+f"(c[3])
        : "r"(a[0]), "r"(a[1]), "r"(a[2]), "r"(a[3]), "r"(b[0]), "r"(b[1]));
}
__device__ __forceinline__ void ldsm4(uint32_t r[4], uint32_t addr) {
    asm volatile("ldmatrix.sync.aligned.m8n8.x4.shared.b16 {%0,%1,%2,%3}, [%4];"
        : "=r"(r[0]), "=r"(r[1]), "=r"(r[2]), "=r"(r[3]) : "r"(addr));
}
__device__ __forceinline__ void cp16(uint32_t dst, const void* src) {
    asm volatile("cp.async.cg.shared.global [%0], [%1], 16;\n" :: "r"(dst), "l"(src) : "memory");
}
__device__ __forceinline__ void cpcommit() { asm volatile("cp.async.commit_group;\n" ::: "memory"); }
__device__ __forceinline__ void cpwait1()  { asm volatile("cp.async.wait_group 1;\n" ::: "memory"); }
__device__ __forceinline__ float siluf(float v) { return v / (1.0f + expf(-v)); }

// smem rows: 128 data bytes + 16 pad = 144B; conflict-free for ldmatrix
#define ROWB   144u
#define KT     64        // K halfs per stage (128 bytes)
// gemm_gu: CTA 128slots x 64n; tiles A(128) + G(64) + U(64) rows
#define TLA2   18432u    // 128 rows * 144B
#define TLB2   9216u     // 64 rows * 144B
#define STG2   36864u    // stage bytes
#define NSTG   3u
// gemm_d: CTA 64m x 128n
#define ATB64  9216u     // A tile: 64 rows * 144B
#define STGB64 27648u

// ---------------------------------------------------------------------------
// Routing + x->fp16, 2 warps per token; compensated fp32 accumulation.
// ---------------------------------------------------------------------------
__global__ __launch_bounds__(256) void routing_kernel(
    const float* __restrict__ x, const float* __restrict__ Wr,
    const float* __restrict__ temp)
{
    __shared__ float s_s[4][2][E_], s_c[4][2][E_];
    int tid = threadIdx.x;
    int warp = tid >> 5, lane = tid & 31;
    int pair = warp >> 1, h = warp & 1;
    int t = blockIdx.x * 4 + pair;

    const float* xr = x + (size_t)t * D_;
    float s[E_], c[E_];
#pragma unroll
    for (int e = 0; e < E_; e++) { s[e] = 0.0f; c[e] = 0.0f; }

#pragma unroll 4
    for (int d0 = lane + 32 * h; d0 < D_; d0 += 64) {
        float xv = __ldg(xr + d0);
        float4 wa = *(const float4*)(Wr + d0 * E_);
        float4 wb = *(const float4*)(Wr + d0 * E_ + 4);
        float wv[E_] = {wa.x, wa.y, wa.z, wa.w, wb.x, wb.y, wb.z, wb.w};
#pragma unroll
        for (int e = 0; e < E_; e++) {
            float p   = xv * wv[e];
            float err = fmaf(xv, wv[e], -p);
            float tt  = s[e] + p;
            float e1  = (fabsf(s[e]) >= fabsf(p)) ? ((s[e] - tt) + p)
                                                  : ((p - tt) + s[e]);
            s[e] = tt;
            c[e] += e1 + err;
        }
    }
#pragma unroll
    for (int off = 16; off > 0; off >>= 1) {
#pragma unroll
        for (int e = 0; e < E_; e++) {
            float s2 = __shfl_down_sync(0xffffffffu, s[e], off);
            float c2 = __shfl_down_sync(0xffffffffu, c[e], off);
            float tt = s[e] + s2;
            float e1 = (fabsf(s[e]) >= fabsf(s2)) ? ((s[e] - tt) + s2)
                                                  : ((s2 - tt) + s[e]);
            s[e] = tt;
            c[e] += c2 + e1;
        }
    }
    if (lane == 0) {
#pragma unroll
        for (int e = 0; e < E_; e++) { s_s[pair][h][e] = s[e]; s_c[pair][h][e] = c[e]; }
    }

    __half* xo = g_xq + (size_t)t * D_;
#pragma unroll
    for (int j = 0; j < 4; j++) {
        int d = (lane + 32 * h + 64 * j) * 4;
        float4 v = *(const float4*)(xr + d);
        *(__half2*)(xo + d)     = __floats2half2_rn(v.x, v.y);
        *(__half2*)(xo + d + 2) = __floats2half2_rn(v.z, v.w);
    }
    __syncthreads();

    if (h == 0 && lane == 0) {
        float T = temp[0];
        float dist[E_], wv[E_];
        float wsum = 0.0f;
#pragma unroll
        for (int e = 0; e < E_; e++) {
            float s0 = s_s[pair][0][e], s1 = s_s[pair][1][e];
            float tt = s0 + s1;
            float e1 = (fabsf(s0) >= fabsf(s1)) ? ((s0 - tt) + s1)
                                                : ((s1 - tt) + s0);
            float z = (tt + (s_c[pair][0][e] + s_c[pair][1][e] + e1)) / T;
            float inh = 1.0f / (1.0f + expf(-z));
            dist[e] = fabsf(inh - GOLDEN_CENTER);
            bool zone = (inh >= GOLDEN_LOWER) && (inh <= GOLDEN_UPPER);
            wv[e] = zone ? expf(-dist[e] / 0.1f) : 0.0f;
            wsum += wv[e];
        }
        if (wsum < 1e-8f) {
            float fb[E_];
#pragma unroll
            for (int e = 0; e < E_; e++) fb[e] = expf(-dist[e] / 0.3f);
            int i1 = 0;
#pragma unroll
            for (int e = 1; e < E_; e++) if (fb[e] > fb[i1]) i1 = e;
            int i2 = (i1 == 0) ? 1 : 0;
#pragma unroll
            for (int e = 0; e < E_; e++)
                if (e != i1 && fb[e] > fb[i2]) i2 = e;
            float sc = fmaxf(fb[i1] + fb[i2], 1e-8f);
#pragma unroll
            for (int e = 0; e < E_; e++)
                wv[e] = (e == i1 || e == i2) ? fb[e] / sc : 0.0f;
        }
        float s2 = 0.0f;
#pragma unroll
        for (int e = 0; e < E_; e++) s2 += wv[e];
        float inv = 1.0f / fmaxf(s2, 1e-8f);
#pragma unroll
        for (int e = 0; e < E_; e++) g_w[t * E_ + e] = wv[e] * inv;
    }
}

// ---------------------------------------------------------------------------
// Deterministic per-expert compaction (ordered by token id; no atomics).
// ---------------------------------------------------------------------------
__global__ __launch_bounds__(256) void compact_kernel()
{
    __shared__ int wsum[8];
    __shared__ int sbase;
    int e = blockIdx.x, tid = threadIdx.x, lane = tid & 31, wid = tid >> 5;
    if (tid == 0) sbase = 0;
    __syncthreads();

#pragma unroll 1
    for (int cch = 0; cch < BT_ / 256; cch++) {
        int t = cch * 256 + tid;
        int a = (g_w[t * E_ + e] != 0.0f) ? 1 : 0;
        unsigned m = __ballot_sync(0xffffffffu, a);
        int pos = __popc(m & ((1u << lane) - 1u));
        if (lane == 0) wsum[wid] = __popc(m);
        __syncthreads();
        int wbase = 0;
#pragma unroll
        for (int k = 0; k < 8; k++) if (k < wid) wbase += wsum[k];
        int tot = 0;
#pragma unroll
        for (int k = 0; k < 8; k++) tot += wsum[k];
        int base = sbase;
        __syncthreads();
        if (a) g_tok[e * BT_ + base + wbase + pos] = t;
        if (tid == 0) sbase = base + tot;
        __syncthreads();
    }

    int cnt = sbase;
    int pad = (cnt + 127) & ~127;
    for (int sidx = cnt + tid; sidx < pad; sidx += 256) g_tok[e * BT_ + sidx] = 0;
    if (tid == 0) g_cnt[e] = cnt;
}

// ---------------------------------------------------------------------------
// transpose + fp16, all 3 weight tensors in one launch (z = 24)
// ---------------------------------------------------------------------------
__global__ void convT_kernel(
    const float* __restrict__ in0, const float* __restrict__ in1,
    const float* __restrict__ in2,
    __half* __restrict__ o0, __half* __restrict__ o1, __half* __restrict__ o2)
{
    __shared__ float t[32][33];
    int zz = blockIdx.z;
    int which = zz >> 3, e = zz & 7;
    const float* in = (which == 0) ? in0 : (which == 1) ? in1 : in2;
    __half* oq      = (which == 0) ? o0  : (which == 1) ? o1  : o2;

    const float* ip = in + ((size_t)e << 20);
    __half* op = oq + ((size_t)e << 20);
    int r0 = blockIdx.y * 32, c0 = blockIdx.x * 32;
    int tx = threadIdx.x, ty = threadIdx.y;

#pragma unroll
    for (int j = ty; j < 32; j += 8)
        t[j][tx] = ip[(size_t)(r0 + j) * 1024 + c0 + tx];
    __syncthreads();

    int rh = (tx & 15) * 2;
    int jh = tx >> 4;
#pragma unroll
    for (int k = ty; k < 16; k += 8) {
        int j = k * 2 + jh;
        __half2 v = __floats2half2_rn(t[rh][j], t[rh + 1][j]);
        *(__half2*)(op + (size_t)(c0 + j) * 1024 + r0 + rh) = v;
    }
}

// ---------------------------------------------------------------------------
// gemm_gu FUSED + COMPACT, 2 CTAs/SM: CTA 128slots x 64n, 8 warps (4m x 2n),
// warp 32x32 dual acc (gate/up). 3-stage ring, smem 108KB, <=128 regs.
// grid (I/64=16, BT/128=64, E=8), early-exit.
// ---------------------------------------------------------------------------
__global__ __launch_bounds__(256, 2) void gemm_gu_kernel()
{
    const int e  = blockIdx.z;
    const int m0 = blockIdx.y * 128;
    const int cnt = __ldg(&g_cnt[e]);
    if (m0 >= cnt) return;

    extern __shared__ char smem[];
    const uint32_t sb = (uint32_t)__cvta_generic_to_shared(smem);
    const int n0 = blockIdx.x * 64;

    const __half* Gp = g_gq + ((size_t)e * I_ + n0) * D_;
    const __half* Up = g_uq + ((size_t)e * I_ + n0) * D_;

    const int tid = threadIdx.x, lane = tid & 31, warp = tid >> 5;
    const int wm = warp & 3, wn = warp >> 2;
    const int g = lane >> 2, tg = lane & 3;
    const int rbase = tid >> 3;
    const uint32_t qo = (uint32_t)(tid & 7) * 16;
    const int qh = (tid & 7) * 8;

    const __half* arow[4];
#pragma unroll
    for (int j = 0; j < 4; j++) {
        int tk = __ldg(&g_tok[e * BT_ + m0 + rbase + 32 * j]);
        arow[j] = g_xq + (size_t)tk * D_;
    }

    const uint32_t aoffL = (uint32_t)((lane & 7) + ((lane >> 3) & 1) * 8) * ROWB + (lane >> 4) * 16;
    const uint32_t boffL = (uint32_t)((lane & 7) + (lane >> 4) * 8) * ROWB + ((lane >> 3) & 1) * 16;
    const uint32_t aro  = (uint32_t)(wm * 32) * ROWB;
    const uint32_t broG = TLA2 + (uint32_t)(wn * 32) * ROWB;
    const uint32_t broU = TLA2 + TLB2 + (uint32_t)(wn * 32) * ROWB;

    float accg[2][4][4], accu[2][4][4];
#pragma unroll
    for (int mt = 0; mt < 2; mt++)
#pragma unroll
        for (int nt = 0; nt < 4; nt++)
#pragma unroll
            for (int i = 0; i < 4; i++) { accg[mt][nt][i] = 0.0f; accu[mt][nt][i] = 0.0f; }

#define ISSUE_GU(buf, k0) do {                                                  \
        uint32_t st_ = sb + (uint32_t)(buf) * STG2;                             \
        _Pragma("unroll")                                                       \
        for (int j = 0; j < 4; j++) {                                           \
            int r_ = rbase + 32 * j;                                            \
            cp16(st_ + (uint32_t)r_ * ROWB + qo, arow[j] + (k0) + qh);          \
        }                                                                       \
        _Pragma("unroll")                                                       \
        for (int j = 0; j < 2; j++) {                                           \
            int r_ = rbase + 32 * j;                                            \
            size_t ws_ = (size_t)r_ * 1024 + (k0) + qh;                         \
            uint32_t o_ = (uint32_t)r_ * ROWB + qo;                             \
            cp16(st_ + TLA2 + o_,        Gp + ws_);                             \
            cp16(st_ + TLA2 + TLB2 + o_, Up + ws_);                             \
        }                                                                       \
        cpcommit();                                                             \
    } while (0)

    const int NS = D_ / KT;   // 16
    ISSUE_GU(0, 0);
    ISSUE_GU(1, KT);

#pragma unroll 1
    for (int st = 0; st < NS; st++) {
        cpwait1();
        __syncthreads();
        if (st + 2 < NS) ISSUE_GU((st + 2) % 3, (st + 2) * KT);
        else cpcommit();

        const uint32_t stb = sb + (uint32_t)(st % 3) * STG2;
#pragma unroll
        for (int ks = 0; ks < 4; ks++) {
            const uint32_t kb = (uint32_t)ks * 32u;
            uint32_t af[2][4];
#pragma unroll
            for (int mt = 0; mt < 2; mt++)
                ldsm4(af[mt], stb + aro + (uint32_t)(mt * 16) * ROWB + aoffL + kb);
            uint32_t gf[2][4], uf[2][4];
#pragma unroll
            for (int p = 0; p < 2; p++) {
                ldsm4(gf[p], stb + broG + (uint32_t)(p * 16) * ROWB + boffL + kb);
                ldsm4(uf[p], stb + broU + (uint32_t)(p * 16) * ROWB + boffL + kb);
            }
#pragma unroll
            for (int mt = 0; mt < 2; mt++)
#pragma unroll
                for (int p = 0; p < 2; p++)
#pragma unroll
                    for (int q = 0; q < 2; q++) {
                        hmma16(accg[mt][2 * p + q], af[mt], &gf[p][2 * q]);
                        hmma16(accu[mt][2 * p + q], af[mt], &uf[p][2 * q]);
                    }
        }
    }
#undef ISSUE_GU

    __half* H = g_hq + (size_t)e * BT_ * I_;
#pragma unroll
    for (int mt = 0; mt < 2; mt++) {
        int r0 = m0 + wm * 32 + mt * 16 + g;
        int t0 = __ldg(&g_tok[e * BT_ + r0]);
        int t1 = __ldg(&g_tok[e * BT_ + r0 + 8]);
        float w0 = g_w[t0 * E_ + e];
        float w1 = g_w[t1 * E_ + e];
#pragma unroll
        for (int nt = 0; nt < 4; nt++) {
            int c0 = n0 + wn * 32 + nt * 8 + tg * 2;
            float h0 = w0 * siluf(accg[mt][nt][0]) * accu[mt][nt][0];
            float h1 = w0 * siluf(accg[mt][nt][1]) * accu[mt][nt][1];
            float h2 = w1 * siluf(accg[mt][nt][2]) * accu[mt][nt][2];
            float h3 = w1 * siluf(accg[mt][nt][3]) * accu[mt][nt][3];
            *(__half2*)(H + (size_t)r0 * I_ + c0)       = __floats2half2_rn(h0, h1);
            *(__half2*)(H + (size_t)(r0 + 8) * I_ + c0) = __floats2half2_rn(h2, h3);
        }
    }
}

// ---------------------------------------------------------------------------
// gemm_d COMPACT (2 CTAs/SM): part[e][t] = h'[e][slot] @ Wd[e]^T, fp16 scatter
// CTA 64slots x 128n, 8 warps (2m x 4n). grid (8, 128, 8), early-exit.
// ---------------------------------------------------------------------------
__global__ __launch_bounds__(256, 2) void gemm_d_kernel()
{
    const int e  = blockIdx.z;
    const int m0 = blockIdx.y * 64;
    const int cnt = __ldg(&g_cnt[e]);
    if (m0 >= cnt) return;

    extern __shared__ char smem[];
    const uint32_t sb = (uint32_t)__cvta_generic_to_shared(smem);
    const int n0 = blockIdx.x * 128;

    const __half* Ap = g_hq + ((size_t)e * BT_ + m0) * I_;
    const __half* Bp = g_dq + ((size_t)e * D_ + n0) * I_;

    const int tid = threadIdx.x, lane = tid & 31, warp = tid >> 5;
    const int wm = warp & 1, wn = warp >> 1;
    const int g = lane >> 2, tg = lane & 3;
    const int rbase = tid >> 3;
    const uint32_t qo = (uint32_t)(tid & 7) * 16;
    const int qh = (tid & 7) * 8;

    const uint32_t aoffL = (uint32_t)((lane & 7) + ((lane >> 3) & 1) * 8) * ROWB + (lane >> 4) * 16;
    const uint32_t boffL = (uint32_t)((lane & 7) + (lane >> 4) * 8) * ROWB + ((lane >> 3) & 1) * 16;
    const uint32_t aro = (uint32_t)(wm * 32) * ROWB;
    const uint32_t bro = ATB64 + (uint32_t)(wn * 32) * ROWB;

    float acc[2][4][4];
#pragma unroll
    for (int mt = 0; mt < 2; mt++)
#pragma unroll
        for (int nt = 0; nt < 4; nt++)
#pragma unroll
            for (int i = 0; i < 4; i++) acc[mt][nt][i] = 0.0f;

#define ISSUE_D(buf, k0) do {                                                   \
        uint32_t st_ = sb + (uint32_t)(buf) * STGB64;                           \
        _Pragma("unroll")                                                       \
        for (int j = 0; j < 2; j++) {                                           \
            int r_ = rbase + 32 * j;                                            \
            cp16(st_ + (uint32_t)r_ * ROWB + qo, Ap + (size_t)r_ * 1024 + (k0) + qh); \
        }                                                                       \
        _Pragma("unroll")                                                       \
        for (int j = 0; j < 4; j++) {                                           \
            int r_ = rbase + 32 * j;                                            \
            cp16(st_ + ATB64 + (uint32_t)r_ * ROWB + qo, Bp + (size_t)r_ * 1024 + (k0) + qh); \
        }                                                                       \
        cpcommit();                                                             \
    } while (0)

    const int NS = I_ / KT;   // 16
    ISSUE_D(0, 0);
    ISSUE_D(1, KT);

#pragma unroll 1
    for (int st = 0; st < NS; st++) {
        cpwait1();
        __syncthreads();
        if (st + 2 < NS) ISSUE_D((st + 2) % 3, (st + 2) * KT);
        else cpcommit();

        const uint32_t stb = sb + (uint32_t)(st % 3) * STGB64;
#pragma unroll
        for (int ks = 0; ks < 4; ks++) {
            const uint32_t kb = (uint32_t)ks * 32u;
            uint32_t af[2][4];
#pragma unroll
            for (int mt = 0; mt < 2; mt++)
                ldsm4(af[mt], stb + aro + (uint32_t)(mt * 16) * ROWB + aoffL + kb);
            uint32_t bf[2][4];
#pragma unroll
            for (int p = 0; p < 2; p++)
                ldsm4(bf[p], stb + bro + (uint32_t)(p * 16) * ROWB + boffL + kb);
#pragma unroll
            for (int mt = 0; mt < 2; mt++)
#pragma unroll
                for (int p = 0; p < 2; p++)
#pragma unroll
                    for (int q = 0; q < 2; q++)
                        hmma16(acc[mt][2 * p + q], af[mt], &bf[p][2 * q]);
        }
    }
#undef ISSUE_D

#pragma unroll
    for (int mt = 0; mt < 2; mt++) {
        int s0 = m0 + wm * 32 + mt * 16 + g;
        int s1 = s0 + 8;
        if (s0 < cnt) {
            int t0 = __ldg(&g_tok[e * BT_ + s0]);
            __half* P = g_part + ((size_t)e * BT_ + t0) * D_;
#pragma unroll
            for (int nt = 0; nt < 4; nt++) {
                int c0 = n0 + wn * 32 + nt * 8 + tg * 2;
                *(__half2*)(P + c0) = __floats2half2_rn(acc[mt][nt][0], acc[mt][nt][1]);
            }
        }
        if (s1 < cnt) {
            int t1 = __ldg(&g_tok[e * BT_ + s1]);
            __half* P = g_part + ((size_t)e * BT_ + t1) * D_;
#pragma unroll
            for (int nt = 0; nt < 4; nt++) {
                int c0 = n0 + wn * 32 + nt * 8 + tg * 2;
                *(__half2*)(P + c0) = __floats2half2_rn(acc[mt][nt][2], acc[mt][nt][3]);
            }
        }
    }
}

// ---------------------------------------------------------------------------
// reduce (flat, no smem/sync): out[t][d] = sum_e active part[e][t][d]
// ---------------------------------------------------------------------------
__global__ __launch_bounds__(256) void reduce_kernel(float* __restrict__ out)
{
    int gid = blockIdx.x * 256 + threadIdx.x;   // [0, 2M)
    int t = gid >> 8;
    int d = (gid & 255) * 4;

    const float* wr = g_w + t * E_;
    float4 acc = make_float4(0.0f, 0.0f, 0.0f, 0.0f);
#pragma unroll
    for (int e = 0; e < E_; e++) {
        float w = __ldg(wr + e);
        if (w != 0.0f) {
            const __half2* P = (const __half2*)(g_part + ((size_t)e * BT_ + t) * D_ + d);
            float2 f0 = __half22float2(P[0]), f1 = __half22float2(P[1]);
            acc.x += f0.x; acc.y += f0.y; acc.z += f1.x; acc.w += f1.y;
        }
    }
    *(float4*)(out + (size_t)t * D_ + d) = acc;
}

// ---------------------------------------------------------------------------
// launch
// ---------------------------------------------------------------------------
extern "C" void kernel_launch(void* const* d_in, const int* in_sizes, int n_in,
                              void* d_out, int out_size)
{
    const float* x    = (const float*)d_in[0];
    const float* Wg   = (const float*)d_in[1];
    const float* Wu   = (const float*)d_in[2];
    const float* Wd   = (const float*)d_in[3];
    const float* Wr   = (const float*)d_in[4];
    const float* temp = (const float*)d_in[5];
    float* out = (float*)d_out;

    cudaFuncSetAttribute(gemm_gu_kernel, cudaFuncAttributeMaxDynamicSharedMemorySize, NSTG * STG2);
    cudaFuncSetAttribute(gemm_d_kernel,  cudaFuncAttributeMaxDynamicSharedMemorySize, NSTG * STGB64);

    __half *gq, *uq, *dq;
    cudaGetSymbolAddress((void**)&gq, g_gq);
    cudaGetSymbolAddress((void**)&uq, g_uq);
    cudaGetSymbolAddress((void**)&dq, g_dq);

    routing_kernel<<<BT_ / 4, 256>>>(x, Wr, temp);      // 1 (+ x->fp16)
    compact_kernel<<<E_, 256>>>();                      // 2

    dim3 gt(32, 32, 3 * E_), bt(32, 8);
    convT_kernel<<<gt, bt>>>(Wg, Wu, Wd, gq, uq, dq);   // 3

    dim3 gGU(I_ / 64, BT_ / 128, E_);
    gemm_gu_kernel<<<gGU, 256, NSTG * STG2>>>();        // 4

    dim3 gD(D_ / 128, BT_ / 64, E_);
    gemm_d_kernel<<<gD, 256, NSTG * STGB64>>>();        // 5

    reduce_kernel<<<BT_, 256>>>(out);                   // 6
}